// round 1
// baseline (speedup 1.0000x reference)
#include <cuda_runtime.h>
#include <math.h>

#define BB 2
#define HH 16
#define SS 2048
#define DD 1024
#define HD 64
#define MM (BB*SS)          // 4096 rows
#define QT 16               // q rows per attention block

// Scratch (device globals: allocation-free per harness rules)
__device__ float g_q[BB*HH*SS*HD];   // [B,H,S,hd]
__device__ float g_k[BB*HH*SS*HD];
__device__ float g_v[BB*HH*SS*HD];
__device__ float g_ao[MM*DD];        // merged-head attention output [B*S, D]

// ---------------------------------------------------------------------------
// QKV GEMM: [4096,1024] @ [1024,3072] + bias, scatter into q/k/v head layout
// 128x128 block tile, 8x8 per thread, K-tile 8.
// ---------------------------------------------------------------------------
__global__ __launch_bounds__(256) void qkv_gemm(const float* __restrict__ X,
                                                const float* __restrict__ W,
                                                const float* __restrict__ bias)
{
    __shared__ float As[8][128];
    __shared__ float Bs[8][128];
    const int tid = threadIdx.x;
    const int bm = blockIdx.y * 128;
    const int bn = blockIdx.x * 128;
    const int tx = tid & 15;
    const int ty = tid >> 4;

    float acc[8][8];
#pragma unroll
    for (int i = 0; i < 8; i++)
#pragma unroll
        for (int j = 0; j < 8; j++) acc[i][j] = 0.f;

    for (int k0 = 0; k0 < 1024; k0 += 8) {
#pragma unroll
        for (int i = 0; i < 4; i++) {
            int e = tid + i * 256;
            int m = e >> 3, kk = e & 7;
            As[kk][m] = X[(size_t)(bm + m) * 1024 + k0 + kk];
        }
#pragma unroll
        for (int i = 0; i < 4; i++) {
            int e = tid + i * 256;
            int kk = e >> 7, n = e & 127;
            Bs[kk][n] = W[(size_t)(k0 + kk) * 3072 + bn + n];
        }
        __syncthreads();
#pragma unroll
        for (int kk = 0; kk < 8; kk++) {
            float a[8], b[8];
#pragma unroll
            for (int i = 0; i < 8; i++) a[i] = As[kk][ty * 8 + i];
#pragma unroll
            for (int j = 0; j < 8; j++) b[j] = Bs[kk][tx * 8 + j];
#pragma unroll
            for (int i = 0; i < 8; i++)
#pragma unroll
                for (int j = 0; j < 8; j++) acc[i][j] += a[i] * b[j];
        }
        __syncthreads();
    }

    // Epilogue: add bias, scatter to q/k/v [B,H,S,hd]
#pragma unroll
    for (int i = 0; i < 8; i++) {
        const int m = bm + ty * 8 + i;
        const int b = m >> 11;          // /2048
        const int s = m & 2047;
#pragma unroll
        for (int j = 0; j < 8; j++) {
            const int n = bn + tx * 8 + j;
            const float v = acc[i][j] + bias[n];
            const int which = n >> 10;  // 0=q 1=k 2=v
            const int jj = n & 1023;
            const int h = jj >> 6;
            const int d = jj & 63;
            float* dst = (which == 0) ? g_q : (which == 1) ? g_k : g_v;
            dst[(size_t)((b * HH + h) * SS + s) * HD + d] = v;
        }
    }
}

// ---------------------------------------------------------------------------
// Attention: one block per (b, h, 16-row q tile). Full score rows in smem,
// single-pass softmax, causal zeros written exactly, AV from smem weights.
// ---------------------------------------------------------------------------
#define SMEM_FLOATS (QT*SS + QT*HD + 64*65)

__global__ __launch_bounds__(256) void attn_kernel(float* __restrict__ out_base)
{
    extern __shared__ float sm[];
    float* wrow = sm;                 // [QT][SS]
    float* Qs   = sm + QT * SS;       // [QT][HD]
    float* Ks   = Qs + QT * HD;       // [64][65] padded
    __shared__ float s_inv[QT];

    const int tid = threadIdx.x;
    const int b  = blockIdx.z;
    const int h  = blockIdx.y;
    const int q0 = blockIdx.x * QT;

    const float* Qbh = g_q + (size_t)((b * HH + h) * SS) * HD;
    const float* Kbh = g_k + (size_t)((b * HH + h) * SS) * HD;
    const float* Vbh = g_v + (size_t)((b * HH + h) * SS) * HD;

    // Load Q tile (QT*HD = 1024 floats)
#pragma unroll
    for (int i = 0; i < 4; i++) {
        int e = tid + i * 256;
        Qs[e] = Qbh[(size_t)q0 * HD + e];
    }
    __syncthreads();

    const int kmax = q0 + QT - 1;
    const int nkt  = (kmax >> 6) + 1;   // number of 64-wide k tiles (causal-bounded)
    const int kl   = nkt * 64;

    const int qr = tid >> 4;            // 0..15
    const int kg = tid & 15;            // 0..15 -> k cols kg*4..kg*4+3

    for (int kt = 0; kt < nkt; kt++) {
        const int kbase = kt * 64;
#pragma unroll
        for (int i = 0; i < 16; i++) {
            int e = tid + i * 256;
            int kr = e >> 6, dd = e & 63;
            Ks[kr * 65 + dd] = Kbh[(size_t)(kbase + kr) * HD + dd];
        }
        __syncthreads();

        float a0 = 0.f, a1 = 0.f, a2 = 0.f, a3 = 0.f;
        const float* qp = Qs + qr * HD;
        const float* kp = Ks + kg * 4 * 65;
#pragma unroll
        for (int dd = 0; dd < 64; dd++) {
            const float qv = qp[dd];
            a0 += qv * kp[dd];
            a1 += qv * kp[65 + dd];
            a2 += qv * kp[130 + dd];
            a3 += qv * kp[195 + dd];
        }
        const int q  = q0 + qr;
        const int kk = kbase + kg * 4;
        float* wr = wrow + qr * SS + kk;
        wr[0] = (kk + 0 <= q) ? a0 * 0.125f : -1e30f;
        wr[1] = (kk + 1 <= q) ? a1 * 0.125f : -1e30f;
        wr[2] = (kk + 2 <= q) ? a2 * 0.125f : -1e30f;
        wr[3] = (kk + 3 <= q) ? a3 * 0.125f : -1e30f;
        __syncthreads();
    }

    // Softmax (max + exp + sum), one warp handles 2 rows
    {
        const int w = tid >> 5, lane = tid & 31;
        for (int r = w * 2; r <= w * 2 + 1; r++) {
            float* src = wrow + r * SS;
            float mx = -1e30f;
            for (int k = lane; k < kl; k += 32) mx = fmaxf(mx, src[k]);
#pragma unroll
            for (int off = 16; off > 0; off >>= 1)
                mx = fmaxf(mx, __shfl_xor_sync(0xffffffffu, mx, off));
            float sum = 0.f;
            for (int k = lane; k < kl; k += 32) {
                float e = __expf(src[k] - mx);
                src[k] = e;
                sum += e;
            }
#pragma unroll
            for (int off = 16; off > 0; off >>= 1)
                sum += __shfl_xor_sync(0xffffffffu, sum, off);
            if (lane == 0) s_inv[r] = 1.0f / sum;
        }
    }
    __syncthreads();

    // Normalize in smem + write attn_weights to d_out (zeros past causal bound)
    float* attn = out_base + (size_t)MM * DD;   // attn region follows `out`
    for (int r = 0; r < QT; r++) {
        const float inv = s_inv[r];
        float* dst = attn + ((size_t)((b * HH + h) * SS) + q0 + r) * SS;
        float* src = wrow + r * SS;
        for (int k = tid; k < kl; k += 256) {
            float v = src[k] * inv;
            src[k] = v;
            dst[k] = v;
        }
        for (int k = kl + tid; k < SS; k += 256) dst[k] = 0.f;
    }
    __syncthreads();

    // AV: thread owns (d, 4 q-rows). Weights broadcast from smem, V coalesced.
    {
        const int d = tid & 63;
        const int g = tid >> 6;   // 0..3 -> rows g*4..g*4+3
        float a0 = 0.f, a1 = 0.f, a2 = 0.f, a3 = 0.f;
        const float* w0 = wrow + (g * 4 + 0) * SS;
        const float* w1 = wrow + (g * 4 + 1) * SS;
        const float* w2 = wrow + (g * 4 + 2) * SS;
        const float* w3 = wrow + (g * 4 + 3) * SS;
#pragma unroll 4
        for (int k = 0; k < kl; k++) {
            const float vv = Vbh[(size_t)k * HD + d];
            a0 += w0[k] * vv;
            a1 += w1[k] * vv;
            a2 += w2[k] * vv;
            a3 += w3[k] * vv;
        }
        const int srow = b * SS + q0;
        const int col  = h * HD + d;
        g_ao[(size_t)(srow + g * 4 + 0) * DD + col] = a0;
        g_ao[(size_t)(srow + g * 4 + 1) * DD + col] = a1;
        g_ao[(size_t)(srow + g * 4 + 2) * DD + col] = a2;
        g_ao[(size_t)(srow + g * 4 + 3) * DD + col] = a3;
    }
}

// ---------------------------------------------------------------------------
// Projection GEMM: [4096,1024] @ [1024,1024] + bias -> d_out[0 : 4096*1024)
// ---------------------------------------------------------------------------
__global__ __launch_bounds__(256) void proj_gemm(const float* __restrict__ W,
                                                 const float* __restrict__ bias,
                                                 float* __restrict__ out)
{
    __shared__ float As[8][128];
    __shared__ float Bs[8][128];
    const int tid = threadIdx.x;
    const int bm = blockIdx.y * 128;
    const int bn = blockIdx.x * 128;
    const int tx = tid & 15;
    const int ty = tid >> 4;

    float acc[8][8];
#pragma unroll
    for (int i = 0; i < 8; i++)
#pragma unroll
        for (int j = 0; j < 8; j++) acc[i][j] = 0.f;

    for (int k0 = 0; k0 < 1024; k0 += 8) {
#pragma unroll
        for (int i = 0; i < 4; i++) {
            int e = tid + i * 256;
            int m = e >> 3, kk = e & 7;
            As[kk][m] = g_ao[(size_t)(bm + m) * 1024 + k0 + kk];
        }
#pragma unroll
        for (int i = 0; i < 4; i++) {
            int e = tid + i * 256;
            int kk = e >> 7, n = e & 127;
            Bs[kk][n] = W[(size_t)(k0 + kk) * 1024 + bn + n];
        }
        __syncthreads();
#pragma unroll
        for (int kk = 0; kk < 8; kk++) {
            float a[8], b[8];
#pragma unroll
            for (int i = 0; i < 8; i++) a[i] = As[kk][ty * 8 + i];
#pragma unroll
            for (int j = 0; j < 8; j++) b[j] = Bs[kk][tx * 8 + j];
#pragma unroll
            for (int i = 0; i < 8; i++)
#pragma unroll
                for (int j = 0; j < 8; j++) acc[i][j] += a[i] * b[j];
        }
        __syncthreads();
    }

#pragma unroll
    for (int i = 0; i < 8; i++) {
        const int m = bm + ty * 8 + i;
#pragma unroll
        for (int j = 0; j < 8; j++) {
            const int n = bn + tx * 8 + j;
            out[(size_t)m * DD + n] = acc[i][j] + bias[n];
        }
    }
}

// ---------------------------------------------------------------------------
extern "C" void kernel_launch(void* const* d_in, const int* in_sizes, int n_in,
                              void* d_out, int out_size)
{
    const float* x      = (const float*)d_in[0];
    const float* W_attn = (const float*)d_in[1];
    const float* b_attn = (const float*)d_in[2];
    const float* W_proj = (const float*)d_in[3];
    const float* b_proj = (const float*)d_in[4];
    float* out = (float*)d_out;

    // Opt into >48KB dynamic smem (idempotent, deterministic, capture-safe)
    cudaFuncSetAttribute(attn_kernel,
                         cudaFuncAttributeMaxDynamicSharedMemorySize,
                         SMEM_FLOATS * (int)sizeof(float));

    qkv_gemm<<<dim3(24, 32), 256>>>(x, W_attn, b_attn);
    attn_kernel<<<dim3(SS / QT, HH, BB), 256, SMEM_FLOATS * sizeof(float)>>>(out);
    proj_gemm<<<dim3(8, 32), 256>>>(W_proj, b_proj, out);
}

// round 2
// speedup vs baseline: 2.5916x; 2.5916x over previous
#include <cuda_runtime.h>
#include <math.h>

#define BB 2
#define HH 16
#define SS 2048
#define DD 1024
#define HD 64
#define MM (BB*SS)          // 4096 rows
#define QT 16               // q rows per attention block

#define WS 2052             // wrow smem stride (pad: 2052%32==4 -> conflict-free frags)
#define KLD 68              // K/V/Q tile smem stride (68%32==4)

// Scratch (device globals: allocation-free per harness rules)
__device__ float g_q[BB*HH*SS*HD];   // [B,H,S,hd]
__device__ float g_k[BB*HH*SS*HD];
__device__ float g_v[BB*HH*SS*HD];
__device__ float g_ao[MM*DD];        // merged-head attention output [B*S, D]

// ---------------------------------------------------------------------------
// tf32 mma helpers
// ---------------------------------------------------------------------------
__device__ __forceinline__ unsigned f2tf(float f) {
    unsigned u;
    asm("cvt.rna.tf32.f32 %0, %1;" : "=r"(u) : "f"(f));
    return u;
}

__device__ __forceinline__ void mma8(float* c,
                                     unsigned a0, unsigned a1, unsigned a2, unsigned a3,
                                     unsigned b0, unsigned b1) {
    asm volatile(
        "mma.sync.aligned.m16n8k8.row.col.f32.tf32.tf32.f32 "
        "{%0,%1,%2,%3},{%4,%5,%6,%7},{%8,%9},{%0,%1,%2,%3};"
        : "+f"(c[0]), "+f"(c[1]), "+f"(c[2]), "+f"(c[3])
        : "r"(a0), "r"(a1), "r"(a2), "r"(a3), "r"(b0), "r"(b1));
}

// ---------------------------------------------------------------------------
// QKV GEMM (tf32 mma): [4096,1024] @ [1024,3072] + bias -> scatter q/k/v
// Block tile 128x128, warp tile 64x32, K-tile 32.
// ---------------------------------------------------------------------------
#define ALD 36
#define BLD 136

__global__ __launch_bounds__(256) void qkv_gemm(const float* __restrict__ X,
                                                const float* __restrict__ W,
                                                const float* __restrict__ bias)
{
    __shared__ float As[128 * ALD];
    __shared__ float Bs[32 * BLD];

    const int tid  = threadIdx.x;
    const int lane = tid & 31;
    const int wid  = tid >> 5;
    const int g    = lane >> 2;
    const int tg   = lane & 3;
    const int wm   = (wid >> 2) * 64;   // warp row offset in block
    const int wn   = (wid & 3) * 32;    // warp col offset in block
    const int bm   = blockIdx.y * 128;
    const int bn   = blockIdx.x * 128;

    float acc[4][4][4];
#pragma unroll
    for (int mi = 0; mi < 4; mi++)
#pragma unroll
        for (int nj = 0; nj < 4; nj++)
#pragma unroll
            for (int t = 0; t < 4; t++) acc[mi][nj][t] = 0.f;

    for (int k0 = 0; k0 < 1024; k0 += 32) {
        // Stage A: 128x32 (f4)
#pragma unroll
        for (int i = 0; i < 4; i++) {
            int idx = tid + i * 256;              // 1024 float4
            int row = idx >> 3, c4 = idx & 7;
            *(float4*)&As[row * ALD + c4 * 4] =
                *(const float4*)&X[(size_t)(bm + row) * 1024 + k0 + c4 * 4];
        }
        // Stage B: 32x128 (f4)
#pragma unroll
        for (int i = 0; i < 4; i++) {
            int idx = tid + i * 256;
            int row = idx >> 5, c4 = idx & 31;
            *(float4*)&Bs[row * BLD + c4 * 4] =
                *(const float4*)&W[(size_t)(k0 + row) * 3072 + bn + c4 * 4];
        }
        __syncthreads();

#pragma unroll
        for (int kc = 0; kc < 4; kc++) {
            const int k = kc * 8;
            unsigned af[4][4], bf[4][2];
#pragma unroll
            for (int mi = 0; mi < 4; mi++) {
                const int rb = wm + mi * 16;
                af[mi][0] = f2tf(As[(rb + g    ) * ALD + k + tg    ]);
                af[mi][1] = f2tf(As[(rb + g + 8) * ALD + k + tg    ]);
                af[mi][2] = f2tf(As[(rb + g    ) * ALD + k + tg + 4]);
                af[mi][3] = f2tf(As[(rb + g + 8) * ALD + k + tg + 4]);
            }
#pragma unroll
            for (int nj = 0; nj < 4; nj++) {
                const int cb = wn + nj * 8;
                bf[nj][0] = f2tf(Bs[(k + tg    ) * BLD + cb + g]);
                bf[nj][1] = f2tf(Bs[(k + tg + 4) * BLD + cb + g]);
            }
#pragma unroll
            for (int mi = 0; mi < 4; mi++)
#pragma unroll
                for (int nj = 0; nj < 4; nj++)
                    mma8(acc[mi][nj], af[mi][0], af[mi][1], af[mi][2], af[mi][3],
                         bf[nj][0], bf[nj][1]);
        }
        __syncthreads();
    }

    // Epilogue: bias + scatter to q/k/v [B,H,S,hd]
#pragma unroll
    for (int mi = 0; mi < 4; mi++) {
#pragma unroll
        for (int nj = 0; nj < 4; nj++) {
#pragma unroll
            for (int t = 0; t < 4; t++) {
                const int m = bm + wm + mi * 16 + g + ((t >= 2) ? 8 : 0);
                const int n = bn + wn + nj * 8 + 2 * tg + (t & 1);
                const float v = acc[mi][nj][t] + bias[n];
                const int bidx = m >> 11;
                const int s = m & 2047;
                const int which = n >> 10;
                const int jj = n & 1023;
                const int h = jj >> 6;
                const int d = jj & 63;
                float* dst = (which == 0) ? g_q : (which == 1) ? g_k : g_v;
                dst[(size_t)((bidx * HH + h) * SS + s) * HD + d] = v;
            }
        }
    }
}

// ---------------------------------------------------------------------------
// Attention (tf32 mma): one block per (b, h, 16-row q tile).
// Scores via mma (Q frags register-resident), exact softmax over full row in
// smem, weights -> d_out, AV via mma from smem weights + V tiles.
// ---------------------------------------------------------------------------
#define ATT_SMEM_FLOATS (QT*WS + QT*KLD + 64*KLD)

__global__ __launch_bounds__(256) void attn_kernel(float* __restrict__ out_base)
{
    extern __shared__ float sm[];
    float* wrow = sm;                     // [16][WS]
    float* Qs   = sm + QT * WS;           // [16][KLD]
    float* KVs  = Qs + QT * KLD;          // [64][KLD]
    __shared__ float s_inv[QT];

    const int tid  = threadIdx.x;
    const int lane = tid & 31;
    const int wid  = tid >> 5;
    const int g    = lane >> 2;
    const int tg   = lane & 3;
    const int n0   = wid * 8;

    const int b  = blockIdx.z;
    const int h  = blockIdx.y;
    const int q0 = blockIdx.x * QT;

    const float* Qbh = g_q + (size_t)((b * HH + h) * SS) * HD;
    const float* Kbh = g_k + (size_t)((b * HH + h) * SS) * HD;
    const float* Vbh = g_v + (size_t)((b * HH + h) * SS) * HD;

    // Load Q tile 16x64 into smem
#pragma unroll
    for (int i = 0; i < 4; i++) {
        int e = tid + i * 256;
        int r = e >> 6, d = e & 63;
        Qs[r * KLD + d] = Qbh[(size_t)(q0 + r) * HD + d];
    }
    __syncthreads();

    // Preload Q fragments for all 8 k-chunks (register-resident for all tiles)
    unsigned qa[8][4];
#pragma unroll
    for (int kc = 0; kc < 8; kc++) {
        const int k = kc * 8;
        qa[kc][0] = f2tf(Qs[(g    ) * KLD + k + tg    ]);
        qa[kc][1] = f2tf(Qs[(g + 8) * KLD + k + tg    ]);
        qa[kc][2] = f2tf(Qs[(g    ) * KLD + k + tg + 4]);
        qa[kc][3] = f2tf(Qs[(g + 8) * KLD + k + tg + 4]);
    }

    const int kmax = q0 + QT - 1;
    const int nkt  = (kmax >> 6) + 1;     // 64-wide k tiles (causal-bounded)
    const int kl   = nkt * 64;

    // ---- Score phase ----
    for (int kt = 0; kt < nkt; kt++) {
        const int kbase = kt * 64;
        // Stage K tile 64x64
#pragma unroll
        for (int i = 0; i < 4; i++) {
            int idx = tid + i * 256;          // 1024 float4
            int kr = idx >> 4, c4 = idx & 15;
            *(float4*)&KVs[kr * KLD + c4 * 4] =
                *(const float4*)&Kbh[(size_t)(kbase + kr) * HD + c4 * 4];
        }
        __syncthreads();

        float c[4] = {0.f, 0.f, 0.f, 0.f};
#pragma unroll
        for (int kc = 0; kc < 8; kc++) {
            const unsigned b0 = f2tf(KVs[(n0 + g) * KLD + kc * 8 + tg    ]);
            const unsigned b1 = f2tf(KVs[(n0 + g) * KLD + kc * 8 + tg + 4]);
            mma8(c, qa[kc][0], qa[kc][1], qa[kc][2], qa[kc][3], b0, b1);
        }

        const int col = kbase + n0 + 2 * tg;
        const int r0 = g, r1 = g + 8;
        wrow[r0 * WS + col    ] = (col     <= q0 + r0) ? c[0] * 0.125f : -1e30f;
        wrow[r0 * WS + col + 1] = (col + 1 <= q0 + r0) ? c[1] * 0.125f : -1e30f;
        wrow[r1 * WS + col    ] = (col     <= q0 + r1) ? c[2] * 0.125f : -1e30f;
        wrow[r1 * WS + col + 1] = (col + 1 <= q0 + r1) ? c[3] * 0.125f : -1e30f;
        __syncthreads();
    }

    // ---- Softmax: one warp per 2 rows ----
    {
        for (int r = wid * 2; r <= wid * 2 + 1; r++) {
            float* src = wrow + r * WS;
            float mx = -1e30f;
            for (int k = lane; k < kl; k += 32) mx = fmaxf(mx, src[k]);
#pragma unroll
            for (int off = 16; off > 0; off >>= 1)
                mx = fmaxf(mx, __shfl_xor_sync(0xffffffffu, mx, off));
            float sum = 0.f;
            for (int k = lane; k < kl; k += 32) {
                float e = __expf(src[k] - mx);
                src[k] = e;
                sum += e;
            }
#pragma unroll
            for (int off = 16; off > 0; off >>= 1)
                sum += __shfl_xor_sync(0xffffffffu, sum, off);
            if (lane == 0) s_inv[r] = 1.0f / sum;
        }
    }
    __syncthreads();

    // ---- Normalize + write attn_weights (float4) ----
    float* attn = out_base + (size_t)MM * DD;
    for (int r = 0; r < QT; r++) {
        const float inv = s_inv[r];
        float4* d4 = (float4*)(attn + ((size_t)((b * HH + h) * SS) + q0 + r) * SS);
        float4* s4 = (float4*)(wrow + r * WS);
        const int kl4 = kl >> 2;
        for (int k = tid; k < kl4; k += 256) {
            float4 v = s4[k];
            v.x *= inv; v.y *= inv; v.z *= inv; v.w *= inv;
            s4[k] = v;
            d4[k] = v;
        }
        const float4 z4 = make_float4(0.f, 0.f, 0.f, 0.f);
        for (int k = kl4 + tid; k < (SS >> 2); k += 256) d4[k] = z4;
    }
    __syncthreads();

    // ---- AV phase: output 16x64, warp owns 8 d-cols ----
    float av[4] = {0.f, 0.f, 0.f, 0.f};
    for (int kt = 0; kt < nkt; kt++) {
        const int kbase = kt * 64;
        // Stage V tile 64x64
#pragma unroll
        for (int i = 0; i < 4; i++) {
            int idx = tid + i * 256;
            int kr = idx >> 4, c4 = idx & 15;
            *(float4*)&KVs[kr * KLD + c4 * 4] =
                *(const float4*)&Vbh[(size_t)(kbase + kr) * HD + c4 * 4];
        }
        __syncthreads();

#pragma unroll
        for (int kc = 0; kc < 8; kc++) {
            const int kk = kbase + kc * 8;
            const unsigned a0 = f2tf(wrow[(g    ) * WS + kk + tg    ]);
            const unsigned a1 = f2tf(wrow[(g + 8) * WS + kk + tg    ]);
            const unsigned a2 = f2tf(wrow[(g    ) * WS + kk + tg + 4]);
            const unsigned a3 = f2tf(wrow[(g + 8) * WS + kk + tg + 4]);
            const unsigned b0 = f2tf(KVs[(kc * 8 + tg    ) * KLD + n0 + g]);
            const unsigned b1 = f2tf(KVs[(kc * 8 + tg + 4) * KLD + n0 + g]);
            mma8(av, a0, a1, a2, a3, b0, b1);
        }
        __syncthreads();
    }

    // Write AV result to merged-head layout g_ao [B*S, D]
    {
        const int col  = h * HD + n0 + 2 * tg;
        const int row0 = b * SS + q0 + g;
        g_ao[(size_t)(row0    ) * DD + col    ] = av[0];
        g_ao[(size_t)(row0    ) * DD + col + 1] = av[1];
        g_ao[(size_t)(row0 + 8) * DD + col    ] = av[2];
        g_ao[(size_t)(row0 + 8) * DD + col + 1] = av[3];
    }
}

// ---------------------------------------------------------------------------
// Projection GEMM (tf32 mma): [4096,1024] @ [1024,1024] + bias -> out
// ---------------------------------------------------------------------------
__global__ __launch_bounds__(256) void proj_gemm(const float* __restrict__ W,
                                                 const float* __restrict__ bias,
                                                 float* __restrict__ out)
{
    __shared__ float As[128 * ALD];
    __shared__ float Bs[32 * BLD];

    const int tid  = threadIdx.x;
    const int lane = tid & 31;
    const int wid  = tid >> 5;
    const int g    = lane >> 2;
    const int tg   = lane & 3;
    const int wm   = (wid >> 2) * 64;
    const int wn   = (wid & 3) * 32;
    const int bm   = blockIdx.y * 128;
    const int bn   = blockIdx.x * 128;

    float acc[4][4][4];
#pragma unroll
    for (int mi = 0; mi < 4; mi++)
#pragma unroll
        for (int nj = 0; nj < 4; nj++)
#pragma unroll
            for (int t = 0; t < 4; t++) acc[mi][nj][t] = 0.f;

    for (int k0 = 0; k0 < 1024; k0 += 32) {
#pragma unroll
        for (int i = 0; i < 4; i++) {
            int idx = tid + i * 256;
            int row = idx >> 3, c4 = idx & 7;
            *(float4*)&As[row * ALD + c4 * 4] =
                *(const float4*)&g_ao[(size_t)(bm + row) * 1024 + k0 + c4 * 4];
        }
#pragma unroll
        for (int i = 0; i < 4; i++) {
            int idx = tid + i * 256;
            int row = idx >> 5, c4 = idx & 31;
            *(float4*)&Bs[row * BLD + c4 * 4] =
                *(const float4*)&W[(size_t)(k0 + row) * 1024 + bn + c4 * 4];
        }
        __syncthreads();

#pragma unroll
        for (int kc = 0; kc < 4; kc++) {
            const int k = kc * 8;
            unsigned af[4][4], bf[4][2];
#pragma unroll
            for (int mi = 0; mi < 4; mi++) {
                const int rb = wm + mi * 16;
                af[mi][0] = f2tf(As[(rb + g    ) * ALD + k + tg    ]);
                af[mi][1] = f2tf(As[(rb + g + 8) * ALD + k + tg    ]);
                af[mi][2] = f2tf(As[(rb + g    ) * ALD + k + tg + 4]);
                af[mi][3] = f2tf(As[(rb + g + 8) * ALD + k + tg + 4]);
            }
#pragma unroll
            for (int nj = 0; nj < 4; nj++) {
                const int cb = wn + nj * 8;
                bf[nj][0] = f2tf(Bs[(k + tg    ) * BLD + cb + g]);
                bf[nj][1] = f2tf(Bs[(k + tg + 4) * BLD + cb + g]);
            }
#pragma unroll
            for (int mi = 0; mi < 4; mi++)
#pragma unroll
                for (int nj = 0; nj < 4; nj++)
                    mma8(acc[mi][nj], af[mi][0], af[mi][1], af[mi][2], af[mi][3],
                         bf[nj][0], bf[nj][1]);
        }
        __syncthreads();
    }

#pragma unroll
    for (int mi = 0; mi < 4; mi++) {
#pragma unroll
        for (int nj = 0; nj < 4; nj++) {
#pragma unroll
            for (int t = 0; t < 4; t++) {
                const int m = bm + wm + mi * 16 + g + ((t >= 2) ? 8 : 0);
                const int n = bn + wn + nj * 8 + 2 * tg + (t & 1);
                out[(size_t)m * DD + n] = acc[mi][nj][t] + bias[n];
            }
        }
    }
}

// ---------------------------------------------------------------------------
extern "C" void kernel_launch(void* const* d_in, const int* in_sizes, int n_in,
                              void* d_out, int out_size)
{
    const float* x      = (const float*)d_in[0];
    const float* W_attn = (const float*)d_in[1];
    const float* b_attn = (const float*)d_in[2];
    const float* W_proj = (const float*)d_in[3];
    const float* b_proj = (const float*)d_in[4];
    float* out = (float*)d_out;

    cudaFuncSetAttribute(attn_kernel,
                         cudaFuncAttributeMaxDynamicSharedMemorySize,
                         ATT_SMEM_FLOATS * (int)sizeof(float));

    qkv_gemm<<<dim3(24, 32), 256>>>(x, W_attn, b_attn);
    attn_kernel<<<dim3(SS / QT, HH, BB), 256, ATT_SMEM_FLOATS * sizeof(float)>>>(out);
    proj_gemm<<<dim3(8, 32), 256>>>(W_proj, b_proj, out);
}

// round 4
// speedup vs baseline: 4.7581x; 1.8360x over previous
#include <cuda_runtime.h>
#include <math.h>

#define BB 2
#define HH 16
#define SS 2048
#define DD 1024
#define HD 64
#define MM (BB*SS)          // 4096 rows

// Scratch (device globals: allocation-free per harness rules)
__device__ float g_q[BB*HH*SS*HD];   // [B,H,S,hd]
__device__ float g_k[BB*HH*SS*HD];
__device__ float g_v[BB*HH*SS*HD];
__device__ float g_ao[MM*DD];        // merged-head attention output [B*S, D]

// ---------------------------------------------------------------------------
// tf32 helpers
// ---------------------------------------------------------------------------
__device__ __forceinline__ unsigned f2tf(float f) {
    unsigned u;
    asm("cvt.rna.tf32.f32 %0, %1;" : "=r"(u) : "f"(f));
    return u;
}
__device__ __forceinline__ float4 tf4(float4 v) {
    v.x = __uint_as_float(f2tf(v.x));
    v.y = __uint_as_float(f2tf(v.y));
    v.z = __uint_as_float(f2tf(v.z));
    v.w = __uint_as_float(f2tf(v.w));
    return v;
}
__device__ __forceinline__ void mma8(float* c,
                                     unsigned a0, unsigned a1, unsigned a2, unsigned a3,
                                     unsigned b0, unsigned b1) {
    asm volatile(
        "mma.sync.aligned.m16n8k8.row.col.f32.tf32.tf32.f32 "
        "{%0,%1,%2,%3},{%4,%5,%6,%7},{%8,%9},{%0,%1,%2,%3};"
        : "+f"(c[0]), "+f"(c[1]), "+f"(c[2]), "+f"(c[3])
        : "r"(a0), "r"(a1), "r"(a2), "r"(a3), "r"(b0), "r"(b1));
}

// ---------------------------------------------------------------------------
// QKV GEMM (tf32 mma, cvt at staging): [4096,1024]@[1024,3072]+bias -> q/k/v
// ---------------------------------------------------------------------------
#define ALD 36
#define BLD 136

__global__ __launch_bounds__(256) void qkv_gemm(const float* __restrict__ X,
                                                const float* __restrict__ W,
                                                const float* __restrict__ bias)
{
    __shared__ float As[128 * ALD];
    __shared__ float Bs[32 * BLD];

    const int tid  = threadIdx.x;
    const int lane = tid & 31;
    const int wid  = tid >> 5;
    const int g    = lane >> 2;
    const int tg   = lane & 3;
    const int wm   = (wid >> 2) * 64;
    const int wn   = (wid & 3) * 32;
    const int bm   = blockIdx.y * 128;
    const int bn   = blockIdx.x * 128;

    float acc[4][4][4];
#pragma unroll
    for (int mi = 0; mi < 4; mi++)
#pragma unroll
        for (int nj = 0; nj < 4; nj++)
#pragma unroll
            for (int t = 0; t < 4; t++) acc[mi][nj][t] = 0.f;

    for (int k0 = 0; k0 < 1024; k0 += 32) {
#pragma unroll
        for (int i = 0; i < 4; i++) {
            int idx = tid + i * 256;
            int row = idx >> 3, c4 = idx & 7;
            *(float4*)&As[row * ALD + c4 * 4] =
                tf4(*(const float4*)&X[(size_t)(bm + row) * 1024 + k0 + c4 * 4]);
        }
#pragma unroll
        for (int i = 0; i < 4; i++) {
            int idx = tid + i * 256;
            int row = idx >> 5, c4 = idx & 31;
            *(float4*)&Bs[row * BLD + c4 * 4] =
                tf4(*(const float4*)&W[(size_t)(k0 + row) * 3072 + bn + c4 * 4]);
        }
        __syncthreads();

#pragma unroll
        for (int kc = 0; kc < 4; kc++) {
            const int k = kc * 8;
            unsigned af[4][4], bf[4][2];
#pragma unroll
            for (int mi = 0; mi < 4; mi++) {
                const int rb = wm + mi * 16;
                af[mi][0] = __float_as_uint(As[(rb + g    ) * ALD + k + tg    ]);
                af[mi][1] = __float_as_uint(As[(rb + g + 8) * ALD + k + tg    ]);
                af[mi][2] = __float_as_uint(As[(rb + g    ) * ALD + k + tg + 4]);
                af[mi][3] = __float_as_uint(As[(rb + g + 8) * ALD + k + tg + 4]);
            }
#pragma unroll
            for (int nj = 0; nj < 4; nj++) {
                const int cb = wn + nj * 8;
                bf[nj][0] = __float_as_uint(Bs[(k + tg    ) * BLD + cb + g]);
                bf[nj][1] = __float_as_uint(Bs[(k + tg + 4) * BLD + cb + g]);
            }
#pragma unroll
            for (int mi = 0; mi < 4; mi++)
#pragma unroll
                for (int nj = 0; nj < 4; nj++)
                    mma8(acc[mi][nj], af[mi][0], af[mi][1], af[mi][2], af[mi][3],
                         bf[nj][0], bf[nj][1]);
        }
        __syncthreads();
    }

#pragma unroll
    for (int mi = 0; mi < 4; mi++) {
#pragma unroll
        for (int nj = 0; nj < 4; nj++) {
#pragma unroll
            for (int t = 0; t < 4; t++) {
                const int m = bm + wm + mi * 16 + g + ((t >= 2) ? 8 : 0);
                const int n = bn + wn + nj * 8 + 2 * tg + (t & 1);
                const float v = acc[mi][nj][t] + bias[n];
                const int bidx = m >> 11;
                const int s = m & 2047;
                const int which = n >> 10;
                const int jj = n & 1023;
                const int h = jj >> 6;
                const int d = jj & 63;
                float* dst = (which == 0) ? g_q : (which == 1) ? g_k : g_v;
                dst[(size_t)((bidx * HH + h) * SS + s) * HD + d] = v;
            }
        }
    }
}

// ---------------------------------------------------------------------------
// Flash-style attention: 128 q-rows per block, online softmax, second pass
// recomputes scores to emit exact normalized attn_weights.
// ---------------------------------------------------------------------------
#define PS_LD 132
#define KV_LD 68
#define ATT_SMEM_FLOATS (128*PS_LD + 128*KV_LD + 128*KV_LD)

__global__ __launch_bounds__(256) void attn_kernel(float* __restrict__ out_base)
{
    extern __shared__ float sm[];
    float* Ps = sm;                       // [128][PS_LD]
    float* Ks = sm + 128 * PS_LD;         // [128][KV_LD]
    float* Vs = Ks + 128 * KV_LD;         // [128][KV_LD]

    const int tid  = threadIdx.x;
    const int lane = tid & 31;
    const int wid  = tid >> 5;
    const int g    = lane >> 2;
    const int tg   = lane & 3;
    const int qw   = wid * 16;            // warp's q-row offset in block tile

    const int b  = blockIdx.z;
    const int h  = blockIdx.y;
    const int qt = blockIdx.x;
    const int q0 = qt * 128;

    const float* Qbh = g_q + (size_t)((b * HH + h) * SS) * HD;
    const float* Kbh = g_k + (size_t)((b * HH + h) * SS) * HD;
    const float* Vbh = g_v + (size_t)((b * HH + h) * SS) * HD;

    // Stage Q (tf32) into Ks temporarily, preload Q fragments into registers
#pragma unroll
    for (int i = 0; i < 8; i++) {
        int idx = tid + i * 256;          // 2048 float4
        int row = idx >> 4, c4 = idx & 15;
        *(float4*)&Ks[row * KV_LD + c4 * 4] =
            tf4(*(const float4*)&Qbh[(size_t)(q0 + row) * HD + c4 * 4]);
    }
    __syncthreads();

    unsigned qa[8][4];
#pragma unroll
    for (int kc = 0; kc < 8; kc++) {
        const int k = kc * 8;
        qa[kc][0] = __float_as_uint(Ks[(qw + g    ) * KV_LD + k + tg    ]);
        qa[kc][1] = __float_as_uint(Ks[(qw + g + 8) * KV_LD + k + tg    ]);
        qa[kc][2] = __float_as_uint(Ks[(qw + g    ) * KV_LD + k + tg + 4]);
        qa[kc][3] = __float_as_uint(Ks[(qw + g + 8) * KV_LD + k + tg + 4]);
    }

    float m0 = -1e30f, m1 = -1e30f, l0 = 0.f, l1 = 0.f;
    float o[8][4];
#pragma unroll
    for (int nf = 0; nf < 8; nf++)
#pragma unroll
        for (int t = 0; t < 4; t++) o[nf][t] = 0.f;

    const int nkt  = qt + 1;
    const int row0 = q0 + qw + g;
    const int row1 = row0 + 8;

    // ======================= Pass 1: online softmax + AV ===================
    for (int kt = 0; kt < nkt; kt++) {
        const int kbase = kt * 128;
        __syncthreads();
#pragma unroll
        for (int i = 0; i < 8; i++) {
            int idx = tid + i * 256;
            int row = idx >> 4, c4 = idx & 15;
            *(float4*)&Ks[row * KV_LD + c4 * 4] =
                tf4(*(const float4*)&Kbh[(size_t)(kbase + row) * HD + c4 * 4]);
        }
#pragma unroll
        for (int i = 0; i < 8; i++) {
            int idx = tid + i * 256;
            int row = idx >> 4, c4 = idx & 15;
            *(float4*)&Vs[row * KV_LD + c4 * 4] =
                tf4(*(const float4*)&Vbh[(size_t)(kbase + row) * HD + c4 * 4]);
        }
        __syncthreads();

        // S = Q K^T : 16 n-frags x 8 kc
        float s[16][4];
#pragma unroll
        for (int nf = 0; nf < 16; nf++)
#pragma unroll
            for (int t = 0; t < 4; t++) s[nf][t] = 0.f;
#pragma unroll
        for (int kc = 0; kc < 8; kc++) {
            const int k = kc * 8;
#pragma unroll
            for (int nf = 0; nf < 16; nf++) {
                const unsigned b0 = __float_as_uint(Ks[(nf * 8 + g) * KV_LD + k + tg    ]);
                const unsigned b1 = __float_as_uint(Ks[(nf * 8 + g) * KV_LD + k + tg + 4]);
                mma8(s[nf], qa[kc][0], qa[kc][1], qa[kc][2], qa[kc][3], b0, b1);
            }
        }

        // scale + causal mask (diag tile only) + tile row max
        const bool diag = (kt == qt);
        float mx0 = -1e30f, mx1 = -1e30f;
#pragma unroll
        for (int nf = 0; nf < 16; nf++) {
            const int col = kbase + nf * 8 + 2 * tg;
            float v0 = s[nf][0] * 0.125f;
            float v1 = s[nf][1] * 0.125f;
            float v2 = s[nf][2] * 0.125f;
            float v3 = s[nf][3] * 0.125f;
            if (diag) {
                if (col     > row0) v0 = -1e30f;
                if (col + 1 > row0) v1 = -1e30f;
                if (col     > row1) v2 = -1e30f;
                if (col + 1 > row1) v3 = -1e30f;
            }
            s[nf][0] = v0; s[nf][1] = v1; s[nf][2] = v2; s[nf][3] = v3;
            mx0 = fmaxf(mx0, fmaxf(v0, v1));
            mx1 = fmaxf(mx1, fmaxf(v2, v3));
        }
        mx0 = fmaxf(mx0, __shfl_xor_sync(0xffffffffu, mx0, 1));
        mx0 = fmaxf(mx0, __shfl_xor_sync(0xffffffffu, mx0, 2));
        mx1 = fmaxf(mx1, __shfl_xor_sync(0xffffffffu, mx1, 1));
        mx1 = fmaxf(mx1, __shfl_xor_sync(0xffffffffu, mx1, 2));

        const float mn0 = fmaxf(m0, mx0);
        const float mn1 = fmaxf(m1, mx1);
        const float al0 = __expf(m0 - mn0);
        const float al1 = __expf(m1 - mn1);

        float rs0 = 0.f, rs1 = 0.f;
#pragma unroll
        for (int nf = 0; nf < 16; nf++) {
            const float p0 = __expf(s[nf][0] - mn0);
            const float p1 = __expf(s[nf][1] - mn0);
            const float p2 = __expf(s[nf][2] - mn1);
            const float p3 = __expf(s[nf][3] - mn1);
            rs0 += p0 + p1;
            rs1 += p2 + p3;
            float2 t0, t1;
            t0.x = __uint_as_float(f2tf(p0)); t0.y = __uint_as_float(f2tf(p1));
            t1.x = __uint_as_float(f2tf(p2)); t1.y = __uint_as_float(f2tf(p3));
            *(float2*)&Ps[(qw + g    ) * PS_LD + nf * 8 + 2 * tg] = t0;
            *(float2*)&Ps[(qw + g + 8) * PS_LD + nf * 8 + 2 * tg] = t1;
        }
        rs0 += __shfl_xor_sync(0xffffffffu, rs0, 1);
        rs0 += __shfl_xor_sync(0xffffffffu, rs0, 2);
        rs1 += __shfl_xor_sync(0xffffffffu, rs1, 1);
        rs1 += __shfl_xor_sync(0xffffffffu, rs1, 2);

        m0 = mn0; m1 = mn1;
        l0 = l0 * al0 + rs0;
        l1 = l1 * al1 + rs1;
#pragma unroll
        for (int nf = 0; nf < 8; nf++) {
            o[nf][0] *= al0; o[nf][1] *= al0;
            o[nf][2] *= al1; o[nf][3] *= al1;
        }

        // O += P V  (A from Ps — warp-private rows, no sync needed)
#pragma unroll
        for (int kc = 0; kc < 16; kc++) {
            const int k = kc * 8;
            const unsigned a0 = __float_as_uint(Ps[(qw + g    ) * PS_LD + k + tg    ]);
            const unsigned a1 = __float_as_uint(Ps[(qw + g + 8) * PS_LD + k + tg    ]);
            const unsigned a2 = __float_as_uint(Ps[(qw + g    ) * PS_LD + k + tg + 4]);
            const unsigned a3 = __float_as_uint(Ps[(qw + g + 8) * PS_LD + k + tg + 4]);
#pragma unroll
            for (int nf = 0; nf < 8; nf++) {
                const unsigned b0 = __float_as_uint(Vs[(k + tg    ) * KV_LD + nf * 8 + g]);
                const unsigned b1 = __float_as_uint(Vs[(k + tg + 4) * KV_LD + nf * 8 + g]);
                mma8(o[nf], a0, a1, a2, a3, b0, b1);
            }
        }
    }

    // Write O / l to merged-head layout
    const float il0 = 1.0f / l0;
    const float il1 = 1.0f / l1;
    {
        const int orow = b * SS + q0 + qw + g;
#pragma unroll
        for (int nf = 0; nf < 8; nf++) {
            const int col = h * HD + nf * 8 + 2 * tg;
            float2 r0, r1;
            r0.x = o[nf][0] * il0; r0.y = o[nf][1] * il0;
            r1.x = o[nf][2] * il1; r1.y = o[nf][3] * il1;
            *(float2*)&g_ao[(size_t)orow * DD + col] = r0;
            *(float2*)&g_ao[(size_t)(orow + 8) * DD + col] = r1;
        }
    }

    // =============== Pass 2: recompute scores, emit weights ================
    float* attn = out_base + (size_t)MM * DD;
    const size_t arow = (size_t)(b * HH + h) * SS + q0;

    for (int kt = 0; kt < nkt; kt++) {
        const int kbase = kt * 128;
        __syncthreads();
#pragma unroll
        for (int i = 0; i < 8; i++) {
            int idx = tid + i * 256;
            int row = idx >> 4, c4 = idx & 15;
            *(float4*)&Ks[row * KV_LD + c4 * 4] =
                tf4(*(const float4*)&Kbh[(size_t)(kbase + row) * HD + c4 * 4]);
        }
        __syncthreads();

        float s[16][4];
#pragma unroll
        for (int nf = 0; nf < 16; nf++)
#pragma unroll
            for (int t = 0; t < 4; t++) s[nf][t] = 0.f;
#pragma unroll
        for (int kc = 0; kc < 8; kc++) {
            const int k = kc * 8;
#pragma unroll
            for (int nf = 0; nf < 16; nf++) {
                const unsigned b0 = __float_as_uint(Ks[(nf * 8 + g) * KV_LD + k + tg    ]);
                const unsigned b1 = __float_as_uint(Ks[(nf * 8 + g) * KV_LD + k + tg + 4]);
                mma8(s[nf], qa[kc][0], qa[kc][1], qa[kc][2], qa[kc][3], b0, b1);
            }
        }

        const bool diag = (kt == qt);
#pragma unroll
        for (int nf = 0; nf < 16; nf++) {
            const int col = kbase + nf * 8 + 2 * tg;
            float w0 = __expf(s[nf][0] * 0.125f - m0) * il0;
            float w1 = __expf(s[nf][1] * 0.125f - m0) * il0;
            float w2 = __expf(s[nf][2] * 0.125f - m1) * il1;
            float w3 = __expf(s[nf][3] * 0.125f - m1) * il1;
            if (diag) {
                if (col     > row0) w0 = 0.f;
                if (col + 1 > row0) w1 = 0.f;
                if (col     > row1) w2 = 0.f;
                if (col + 1 > row1) w3 = 0.f;
            }
            float2 t0, t1;
            t0.x = w0; t0.y = w1;
            t1.x = w2; t1.y = w3;
            *(float2*)&Ps[(qw + g    ) * PS_LD + nf * 8 + 2 * tg] = t0;
            *(float2*)&Ps[(qw + g + 8) * PS_LD + nf * 8 + 2 * tg] = t1;
        }
        __syncthreads();

        // block-wide coalesced copy Ps -> attn (128 rows x 32 float4 = 4096)
#pragma unroll
        for (int i = 0; i < 16; i++) {
            int idx = tid + i * 256;      // 4096 float4
            int row = idx >> 5, c4 = idx & 31;
            float4 v = *(float4*)&Ps[row * PS_LD + c4 * 4];
            *(float4*)&attn[(arow + row) * SS + kbase + c4 * 4] = v;
        }
    }

    // zero-fill strictly-upper region
    const int kl = nkt * 128;
    if (kl < SS) {
        const float4 z = make_float4(0.f, 0.f, 0.f, 0.f);
        const int w4 = (SS - kl) >> 2;
        for (int row = 0; row < 128; row++) {
            float4* dst = (float4*)&attn[(arow + row) * SS + kl];
            for (int c = tid; c < w4; c += 256) dst[c] = z;
        }
    }
}

// ---------------------------------------------------------------------------
// Projection GEMM (tf32 mma, cvt at staging)
// ---------------------------------------------------------------------------
__global__ __launch_bounds__(256) void proj_gemm(const float* __restrict__ W,
                                                 const float* __restrict__ bias,
                                                 float* __restrict__ out)
{
    __shared__ float As[128 * ALD];
    __shared__ float Bs[32 * BLD];

    const int tid  = threadIdx.x;
    const int lane = tid & 31;
    const int wid  = tid >> 5;
    const int g    = lane >> 2;
    const int tg   = lane & 3;
    const int wm   = (wid >> 2) * 64;
    const int wn   = (wid & 3) * 32;
    const int bm   = blockIdx.y * 128;
    const int bn   = blockIdx.x * 128;

    float acc[4][4][4];
#pragma unroll
    for (int mi = 0; mi < 4; mi++)
#pragma unroll
        for (int nj = 0; nj < 4; nj++)
#pragma unroll
            for (int t = 0; t < 4; t++) acc[mi][nj][t] = 0.f;

    for (int k0 = 0; k0 < 1024; k0 += 32) {
#pragma unroll
        for (int i = 0; i < 4; i++) {
            int idx = tid + i * 256;
            int row = idx >> 3, c4 = idx & 7;
            *(float4*)&As[row * ALD + c4 * 4] =
                tf4(*(const float4*)&g_ao[(size_t)(bm + row) * 1024 + k0 + c4 * 4]);
        }
#pragma unroll
        for (int i = 0; i < 4; i++) {
            int idx = tid + i * 256;
            int row = idx >> 5, c4 = idx & 31;
            *(float4*)&Bs[row * BLD + c4 * 4] =
                tf4(*(const float4*)&W[(size_t)(k0 + row) * 1024 + bn + c4 * 4]);
        }
        __syncthreads();

#pragma unroll
        for (int kc = 0; kc < 4; kc++) {
            const int k = kc * 8;
            unsigned af[4][4], bf[4][2];
#pragma unroll
            for (int mi = 0; mi < 4; mi++) {
                const int rb = wm + mi * 16;
                af[mi][0] = __float_as_uint(As[(rb + g    ) * ALD + k + tg    ]);
                af[mi][1] = __float_as_uint(As[(rb + g + 8) * ALD + k + tg    ]);
                af[mi][2] = __float_as_uint(As[(rb + g    ) * ALD + k + tg + 4]);
                af[mi][3] = __float_as_uint(As[(rb + g + 8) * ALD + k + tg + 4]);
            }
#pragma unroll
            for (int nj = 0; nj < 4; nj++) {
                const int cb = wn + nj * 8;
                bf[nj][0] = __float_as_uint(Bs[(k + tg    ) * BLD + cb + g]);
                bf[nj][1] = __float_as_uint(Bs[(k + tg + 4) * BLD + cb + g]);
            }
#pragma unroll
            for (int mi = 0; mi < 4; mi++)
#pragma unroll
                for (int nj = 0; nj < 4; nj++)
                    mma8(acc[mi][nj], af[mi][0], af[mi][1], af[mi][2], af[mi][3],
                         bf[nj][0], bf[nj][1]);
        }
        __syncthreads();
    }

#pragma unroll
    for (int mi = 0; mi < 4; mi++) {
#pragma unroll
        for (int nj = 0; nj < 4; nj++) {
#pragma unroll
            for (int t = 0; t < 4; t++) {
                const int m = bm + wm + mi * 16 + g + ((t >= 2) ? 8 : 0);
                const int n = bn + wn + nj * 8 + 2 * tg + (t & 1);
                out[(size_t)m * DD + n] = acc[mi][nj][t] + bias[n];
            }
        }
    }
}

// ---------------------------------------------------------------------------
extern "C" void kernel_launch(void* const* d_in, const int* in_sizes, int n_in,
                              void* d_out, int out_size)
{
    const float* x      = (const float*)d_in[0];
    const float* W_attn = (const float*)d_in[1];
    const float* b_attn = (const float*)d_in[2];
    const float* W_proj = (const float*)d_in[3];
    const float* b_proj = (const float*)d_in[4];
    float* out = (float*)d_out;

    cudaFuncSetAttribute(attn_kernel,
                         cudaFuncAttributeMaxDynamicSharedMemorySize,
                         ATT_SMEM_FLOATS * (int)sizeof(float));

    qkv_gemm<<<dim3(24, 32), 256>>>(x, W_attn, b_attn);
    attn_kernel<<<dim3(SS / 128, HH, BB), 256, ATT_SMEM_FLOATS * sizeof(float)>>>(out);
    proj_gemm<<<dim3(8, 32), 256>>>(W_proj, b_proj, out);
}

// round 5
// speedup vs baseline: 5.1179x; 1.0756x over previous
#include <cuda_runtime.h>
#include <math.h>

#define BB 2
#define HH 16
#define SS 2048
#define DD 1024
#define HD 64
#define MM (BB*SS)          // 4096 rows

// Scratch (device globals: allocation-free per harness rules)
__device__ float g_q[BB*HH*SS*HD];   // [B,H,S,hd]
__device__ float g_k[BB*HH*SS*HD];
__device__ float g_v[BB*HH*SS*HD];
__device__ float g_ao[MM*DD];        // merged-head attention output [B*S, D]

// ---------------------------------------------------------------------------
// tf32 helpers
// ---------------------------------------------------------------------------
__device__ __forceinline__ unsigned f2tf(float f) {
    unsigned u;
    asm("cvt.rna.tf32.f32 %0, %1;" : "=r"(u) : "f"(f));
    return u;
}
__device__ __forceinline__ float4 tf4(float4 v) {
    v.x = __uint_as_float(f2tf(v.x));
    v.y = __uint_as_float(f2tf(v.y));
    v.z = __uint_as_float(f2tf(v.z));
    v.w = __uint_as_float(f2tf(v.w));
    return v;
}
__device__ __forceinline__ void mma8(float* c,
                                     unsigned a0, unsigned a1, unsigned a2, unsigned a3,
                                     unsigned b0, unsigned b1) {
    asm volatile(
        "mma.sync.aligned.m16n8k8.row.col.f32.tf32.tf32.f32 "
        "{%0,%1,%2,%3},{%4,%5,%6,%7},{%8,%9},{%0,%1,%2,%3};"
        : "+f"(c[0]), "+f"(c[1]), "+f"(c[2]), "+f"(c[3])
        : "r"(a0), "r"(a1), "r"(a2), "r"(a3), "r"(b0), "r"(b1));
}

// ---------------------------------------------------------------------------
// QKV GEMM: double-buffered, software-pipelined tf32 mma
// ---------------------------------------------------------------------------
#define ALD 36
#define BLD 136
#define ASZ (128*ALD)
#define BSZ (32*BLD)
#define GEMM_SMEM_FLOATS (2*ASZ + 2*BSZ)

__global__ __launch_bounds__(256) void qkv_gemm(const float* __restrict__ X,
                                                const float* __restrict__ W,
                                                const float* __restrict__ bias)
{
    extern __shared__ float smq[];
    float* As = smq;              // [2][ASZ]
    float* Bs = smq + 2 * ASZ;    // [2][BSZ]

    const int tid  = threadIdx.x;
    const int lane = tid & 31;
    const int wid  = tid >> 5;
    const int g    = lane >> 2;
    const int tg   = lane & 3;
    const int wm   = (wid >> 2) * 64;
    const int wn   = (wid & 3) * 32;
    const int bm   = blockIdx.y * 128;
    const int bn   = blockIdx.x * 128;

    float acc[4][4][4];
#pragma unroll
    for (int mi = 0; mi < 4; mi++)
#pragma unroll
        for (int nj = 0; nj < 4; nj++)
#pragma unroll
            for (int t = 0; t < 4; t++) acc[mi][nj][t] = 0.f;

    // per-thread staging coordinates
    const int arow = tid >> 3, ac4 = tid & 7;        // + i*32 rows
    const int brow = tid >> 5, bc4 = tid & 31;       // + i*8 rows

    float4 pa[4], pb[4];
    const int NK = 32;     // 1024/32 k-tiles

    // prologue: load + store tile 0
#pragma unroll
    for (int i = 0; i < 4; i++)
        pa[i] = *(const float4*)&X[(size_t)(bm + arow + i * 32) * 1024 + ac4 * 4];
#pragma unroll
    for (int i = 0; i < 4; i++)
        pb[i] = *(const float4*)&W[(size_t)(brow + i * 8) * 3072 + bn + bc4 * 4];
#pragma unroll
    for (int i = 0; i < 4; i++)
        *(float4*)&As[(arow + i * 32) * ALD + ac4 * 4] = tf4(pa[i]);
#pragma unroll
    for (int i = 0; i < 4; i++)
        *(float4*)&Bs[(brow + i * 8) * BLD + bc4 * 4] = tf4(pb[i]);
    __syncthreads();

    for (int kt = 0; kt < NK; kt++) {
        const float* Ab = As + (kt & 1) * ASZ;
        const float* Bb = Bs + (kt & 1) * BSZ;
        const bool more = (kt + 1 < NK);

        if (more) {
            const int k0 = (kt + 1) * 32;
#pragma unroll
            for (int i = 0; i < 4; i++)
                pa[i] = *(const float4*)&X[(size_t)(bm + arow + i * 32) * 1024 + k0 + ac4 * 4];
#pragma unroll
            for (int i = 0; i < 4; i++)
                pb[i] = *(const float4*)&W[(size_t)(k0 + brow + i * 8) * 3072 + bn + bc4 * 4];
        }

#pragma unroll
        for (int kc = 0; kc < 4; kc++) {
            const int k = kc * 8;
            unsigned af[4][4], bf[4][2];
#pragma unroll
            for (int mi = 0; mi < 4; mi++) {
                const int rb = wm + mi * 16;
                af[mi][0] = __float_as_uint(Ab[(rb + g    ) * ALD + k + tg    ]);
                af[mi][1] = __float_as_uint(Ab[(rb + g + 8) * ALD + k + tg    ]);
                af[mi][2] = __float_as_uint(Ab[(rb + g    ) * ALD + k + tg + 4]);
                af[mi][3] = __float_as_uint(Ab[(rb + g + 8) * ALD + k + tg + 4]);
            }
#pragma unroll
            for (int nj = 0; nj < 4; nj++) {
                const int cb = wn + nj * 8;
                bf[nj][0] = __float_as_uint(Bb[(k + tg    ) * BLD + cb + g]);
                bf[nj][1] = __float_as_uint(Bb[(k + tg + 4) * BLD + cb + g]);
            }
#pragma unroll
            for (int mi = 0; mi < 4; mi++)
#pragma unroll
                for (int nj = 0; nj < 4; nj++)
                    mma8(acc[mi][nj], af[mi][0], af[mi][1], af[mi][2], af[mi][3],
                         bf[nj][0], bf[nj][1]);
        }

        if (more) {
            float* An = As + ((kt + 1) & 1) * ASZ;
            float* Bn = Bs + ((kt + 1) & 1) * BSZ;
#pragma unroll
            for (int i = 0; i < 4; i++)
                *(float4*)&An[(arow + i * 32) * ALD + ac4 * 4] = tf4(pa[i]);
#pragma unroll
            for (int i = 0; i < 4; i++)
                *(float4*)&Bn[(brow + i * 8) * BLD + bc4 * 4] = tf4(pb[i]);
        }
        __syncthreads();
    }

#pragma unroll
    for (int mi = 0; mi < 4; mi++) {
#pragma unroll
        for (int nj = 0; nj < 4; nj++) {
#pragma unroll
            for (int t = 0; t < 4; t++) {
                const int m = bm + wm + mi * 16 + g + ((t >= 2) ? 8 : 0);
                const int n = bn + wn + nj * 8 + 2 * tg + (t & 1);
                const float v = acc[mi][nj][t] + bias[n];
                const int bidx = m >> 11;
                const int s = m & 2047;
                const int which = n >> 10;
                const int jj = n & 1023;
                const int h = jj >> 6;
                const int d = jj & 63;
                float* dst = (which == 0) ? g_q : (which == 1) ? g_k : g_v;
                dst[(size_t)((bidx * HH + h) * SS + s) * HD + d] = v;
            }
        }
    }
}

// ---------------------------------------------------------------------------
// Flash-style attention, double-buffered K/V, pipelined; pass 2 writes
// weights direct from registers.
// ---------------------------------------------------------------------------
#define PS_LD 132
#define KV_LD 68
#define KVSZ (128*KV_LD)
#define ATT_SMEM_FLOATS (128*PS_LD + 4*KVSZ)

__global__ __launch_bounds__(256) void attn_kernel(float* __restrict__ out_base)
{
    extern __shared__ float sm[];
    float* Ps = sm;                       // [128][PS_LD]
    float* Ks = sm + 128 * PS_LD;         // [2][KVSZ]
    float* Vs = Ks + 2 * KVSZ;            // [2][KVSZ]

    const int tid  = threadIdx.x;
    const int lane = tid & 31;
    const int wid  = tid >> 5;
    const int g    = lane >> 2;
    const int tg   = lane & 3;
    const int qw   = wid * 16;

    const int b  = blockIdx.z;
    const int h  = blockIdx.y;
    const int qt = blockIdx.x;
    const int q0 = qt * 128;

    const float* Qbh = g_q + (size_t)((b * HH + h) * SS) * HD;
    const float* Kbh = g_k + (size_t)((b * HH + h) * SS) * HD;
    const float* Vbh = g_v + (size_t)((b * HH + h) * SS) * HD;

    // per-thread staging coords (8 float4 per 128x64 tile)
    const int srow = tid >> 4, sc4 = tid & 15;    // +i*16 rows

    // Stage Q into Ks[0], preload fragments
#pragma unroll
    for (int i = 0; i < 8; i++)
        *(float4*)&Ks[(srow + i * 16) * KV_LD + sc4 * 4] =
            tf4(*(const float4*)&Qbh[(size_t)(q0 + srow + i * 16) * HD + sc4 * 4]);
    __syncthreads();

    unsigned qa[8][4];
#pragma unroll
    for (int kc = 0; kc < 8; kc++) {
        const int k = kc * 8;
        qa[kc][0] = __float_as_uint(Ks[(qw + g    ) * KV_LD + k + tg    ]);
        qa[kc][1] = __float_as_uint(Ks[(qw + g + 8) * KV_LD + k + tg    ]);
        qa[kc][2] = __float_as_uint(Ks[(qw + g    ) * KV_LD + k + tg + 4]);
        qa[kc][3] = __float_as_uint(Ks[(qw + g + 8) * KV_LD + k + tg + 4]);
    }
    __syncthreads();

    float m0 = -1e30f, m1 = -1e30f, l0 = 0.f, l1 = 0.f;
    float o[8][4];
#pragma unroll
    for (int nf = 0; nf < 8; nf++)
#pragma unroll
        for (int t = 0; t < 4; t++) o[nf][t] = 0.f;

    const int nkt  = qt + 1;
    const int row0 = q0 + qw + g;
    const int row1 = row0 + 8;

    float4 pk[8], pv[8];

    // prologue: stage K0, V0
#pragma unroll
    for (int i = 0; i < 8; i++)
        pk[i] = *(const float4*)&Kbh[(size_t)(srow + i * 16) * HD + sc4 * 4];
#pragma unroll
    for (int i = 0; i < 8; i++)
        pv[i] = *(const float4*)&Vbh[(size_t)(srow + i * 16) * HD + sc4 * 4];
#pragma unroll
    for (int i = 0; i < 8; i++)
        *(float4*)&Ks[(srow + i * 16) * KV_LD + sc4 * 4] = tf4(pk[i]);
#pragma unroll
    for (int i = 0; i < 8; i++)
        *(float4*)&Vs[(srow + i * 16) * KV_LD + sc4 * 4] = tf4(pv[i]);
    __syncthreads();

    // ======================= Pass 1: online softmax + AV ===================
    for (int kt = 0; kt < nkt; kt++) {
        const float* Kb = Ks + (kt & 1) * KVSZ;
        const float* Vb = Vs + (kt & 1) * KVSZ;
        const bool more = (kt + 1 < nkt);
        const int kbase = kt * 128;

        // S = Q K^T
        float s[16][4];
#pragma unroll
        for (int nf = 0; nf < 16; nf++)
#pragma unroll
            for (int t = 0; t < 4; t++) s[nf][t] = 0.f;
#pragma unroll
        for (int kc = 0; kc < 8; kc++) {
            const int k = kc * 8;
#pragma unroll
            for (int nf = 0; nf < 16; nf++) {
                const unsigned b0 = __float_as_uint(Kb[(nf * 8 + g) * KV_LD + k + tg    ]);
                const unsigned b1 = __float_as_uint(Kb[(nf * 8 + g) * KV_LD + k + tg + 4]);
                mma8(s[nf], qa[kc][0], qa[kc][1], qa[kc][2], qa[kc][3], b0, b1);
            }
        }

        // prefetch next K (overlaps softmax + PV)
        if (more) {
            const int nb = (kt + 1) * 128;
#pragma unroll
            for (int i = 0; i < 8; i++)
                pk[i] = *(const float4*)&Kbh[(size_t)(nb + srow + i * 16) * HD + sc4 * 4];
        }

        // scale + causal mask + tile row max
        const bool diag = (kt == qt);
        float mx0 = -1e30f, mx1 = -1e30f;
#pragma unroll
        for (int nf = 0; nf < 16; nf++) {
            const int col = kbase + nf * 8 + 2 * tg;
            float v0 = s[nf][0] * 0.125f;
            float v1 = s[nf][1] * 0.125f;
            float v2 = s[nf][2] * 0.125f;
            float v3 = s[nf][3] * 0.125f;
            if (diag) {
                if (col     > row0) v0 = -1e30f;
                if (col + 1 > row0) v1 = -1e30f;
                if (col     > row1) v2 = -1e30f;
                if (col + 1 > row1) v3 = -1e30f;
            }
            s[nf][0] = v0; s[nf][1] = v1; s[nf][2] = v2; s[nf][3] = v3;
            mx0 = fmaxf(mx0, fmaxf(v0, v1));
            mx1 = fmaxf(mx1, fmaxf(v2, v3));
        }
        mx0 = fmaxf(mx0, __shfl_xor_sync(0xffffffffu, mx0, 1));
        mx0 = fmaxf(mx0, __shfl_xor_sync(0xffffffffu, mx0, 2));
        mx1 = fmaxf(mx1, __shfl_xor_sync(0xffffffffu, mx1, 1));
        mx1 = fmaxf(mx1, __shfl_xor_sync(0xffffffffu, mx1, 2));

        const float mn0 = fmaxf(m0, mx0);
        const float mn1 = fmaxf(m1, mx1);
        const float al0 = __expf(m0 - mn0);
        const float al1 = __expf(m1 - mn1);

        float rs0 = 0.f, rs1 = 0.f;
#pragma unroll
        for (int nf = 0; nf < 16; nf++) {
            const float p0 = __expf(s[nf][0] - mn0);
            const float p1 = __expf(s[nf][1] - mn0);
            const float p2 = __expf(s[nf][2] - mn1);
            const float p3 = __expf(s[nf][3] - mn1);
            rs0 += p0 + p1;
            rs1 += p2 + p3;
            float2 t0, t1;
            t0.x = __uint_as_float(f2tf(p0)); t0.y = __uint_as_float(f2tf(p1));
            t1.x = __uint_as_float(f2tf(p2)); t1.y = __uint_as_float(f2tf(p3));
            *(float2*)&Ps[(qw + g    ) * PS_LD + nf * 8 + 2 * tg] = t0;
            *(float2*)&Ps[(qw + g + 8) * PS_LD + nf * 8 + 2 * tg] = t1;
        }
        rs0 += __shfl_xor_sync(0xffffffffu, rs0, 1);
        rs0 += __shfl_xor_sync(0xffffffffu, rs0, 2);
        rs1 += __shfl_xor_sync(0xffffffffu, rs1, 1);
        rs1 += __shfl_xor_sync(0xffffffffu, rs1, 2);

        m0 = mn0; m1 = mn1;
        l0 = l0 * al0 + rs0;
        l1 = l1 * al1 + rs1;
#pragma unroll
        for (int nf = 0; nf < 8; nf++) {
            o[nf][0] *= al0; o[nf][1] *= al0;
            o[nf][2] *= al1; o[nf][3] *= al1;
        }

        // prefetch next V (overlaps PV)
        if (more) {
            const int nb = (kt + 1) * 128;
#pragma unroll
            for (int i = 0; i < 8; i++)
                pv[i] = *(const float4*)&Vbh[(size_t)(nb + srow + i * 16) * HD + sc4 * 4];
        }

        // O += P V (Ps rows are warp-private)
#pragma unroll
        for (int kc = 0; kc < 16; kc++) {
            const int k = kc * 8;
            const unsigned a0 = __float_as_uint(Ps[(qw + g    ) * PS_LD + k + tg    ]);
            const unsigned a1 = __float_as_uint(Ps[(qw + g + 8) * PS_LD + k + tg    ]);
            const unsigned a2 = __float_as_uint(Ps[(qw + g    ) * PS_LD + k + tg + 4]);
            const unsigned a3 = __float_as_uint(Ps[(qw + g + 8) * PS_LD + k + tg + 4]);
#pragma unroll
            for (int nf = 0; nf < 8; nf++) {
                const unsigned b0 = __float_as_uint(Vb[(k + tg    ) * KV_LD + nf * 8 + g]);
                const unsigned b1 = __float_as_uint(Vb[(k + tg + 4) * KV_LD + nf * 8 + g]);
                mma8(o[nf], a0, a1, a2, a3, b0, b1);
            }
        }

        if (more) {
            float* Kn = Ks + ((kt + 1) & 1) * KVSZ;
            float* Vn = Vs + ((kt + 1) & 1) * KVSZ;
#pragma unroll
            for (int i = 0; i < 8; i++)
                *(float4*)&Kn[(srow + i * 16) * KV_LD + sc4 * 4] = tf4(pk[i]);
#pragma unroll
            for (int i = 0; i < 8; i++)
                *(float4*)&Vn[(srow + i * 16) * KV_LD + sc4 * 4] = tf4(pv[i]);
        }
        __syncthreads();
    }

    // Write O / l to merged-head layout
    const float il0 = 1.0f / l0;
    const float il1 = 1.0f / l1;
    {
        const int orow = b * SS + q0 + qw + g;
#pragma unroll
        for (int nf = 0; nf < 8; nf++) {
            const int col = h * HD + nf * 8 + 2 * tg;
            float2 r0, r1;
            r0.x = o[nf][0] * il0; r0.y = o[nf][1] * il0;
            r1.x = o[nf][2] * il1; r1.y = o[nf][3] * il1;
            *(float2*)&g_ao[(size_t)orow * DD + col] = r0;
            *(float2*)&g_ao[(size_t)(orow + 8) * DD + col] = r1;
        }
    }

    // =============== Pass 2: recompute scores, write weights direct ========
    float* attn = out_base + (size_t)MM * DD;
    const size_t abase = (size_t)(b * HH + h) * SS + q0;
    float* w0p = attn + (abase + qw + g) * SS;
    float* w1p = attn + (abase + qw + g + 8) * SS;

    // prologue: stage K0 (Ks buffers free after pass-1 final sync)
#pragma unroll
    for (int i = 0; i < 8; i++)
        pk[i] = *(const float4*)&Kbh[(size_t)(srow + i * 16) * HD + sc4 * 4];
#pragma unroll
    for (int i = 0; i < 8; i++)
        *(float4*)&Ks[(srow + i * 16) * KV_LD + sc4 * 4] = tf4(pk[i]);
    __syncthreads();

    for (int kt = 0; kt < nkt; kt++) {
        const float* Kb = Ks + (kt & 1) * KVSZ;
        const bool more = (kt + 1 < nkt);
        const int kbase = kt * 128;

        float s[16][4];
#pragma unroll
        for (int nf = 0; nf < 16; nf++)
#pragma unroll
            for (int t = 0; t < 4; t++) s[nf][t] = 0.f;
#pragma unroll
        for (int kc = 0; kc < 8; kc++) {
            const int k = kc * 8;
#pragma unroll
            for (int nf = 0; nf < 16; nf++) {
                const unsigned b0 = __float_as_uint(Kb[(nf * 8 + g) * KV_LD + k + tg    ]);
                const unsigned b1 = __float_as_uint(Kb[(nf * 8 + g) * KV_LD + k + tg + 4]);
                mma8(s[nf], qa[kc][0], qa[kc][1], qa[kc][2], qa[kc][3], b0, b1);
            }
        }

        if (more) {
            const int nb = (kt + 1) * 128;
#pragma unroll
            for (int i = 0; i < 8; i++)
                pk[i] = *(const float4*)&Kbh[(size_t)(nb + srow + i * 16) * HD + sc4 * 4];
        }

        const bool diag = (kt == qt);
#pragma unroll
        for (int nf = 0; nf < 16; nf++) {
            const int col = kbase + nf * 8 + 2 * tg;
            float w0 = __expf(s[nf][0] * 0.125f - m0) * il0;
            float w1 = __expf(s[nf][1] * 0.125f - m0) * il0;
            float w2 = __expf(s[nf][2] * 0.125f - m1) * il1;
            float w3 = __expf(s[nf][3] * 0.125f - m1) * il1;
            if (diag) {
                if (col     > row0) w0 = 0.f;
                if (col + 1 > row0) w1 = 0.f;
                if (col     > row1) w2 = 0.f;
                if (col + 1 > row1) w3 = 0.f;
            }
            float2 t0, t1;
            t0.x = w0; t0.y = w1;
            t1.x = w2; t1.y = w3;
            *(float2*)&w0p[col] = t0;
            *(float2*)&w1p[col] = t1;
        }

        if (more) {
            float* Kn = Ks + ((kt + 1) & 1) * KVSZ;
#pragma unroll
            for (int i = 0; i < 8; i++)
                *(float4*)&Kn[(srow + i * 16) * KV_LD + sc4 * 4] = tf4(pk[i]);
        }
        __syncthreads();
    }

    // zero-fill strictly-upper region
    const int kl = nkt * 128;
    if (kl < SS) {
        const float4 z = make_float4(0.f, 0.f, 0.f, 0.f);
        const int w4 = (SS - kl) >> 2;
        for (int row = 0; row < 128; row++) {
            float4* dst = (float4*)&attn[(abase + row) * SS + kl];
            for (int c = tid; c < w4; c += 256) dst[c] = z;
        }
    }
}

// ---------------------------------------------------------------------------
// Projection GEMM: double-buffered, pipelined tf32 mma
// ---------------------------------------------------------------------------
__global__ __launch_bounds__(256) void proj_gemm(const float* __restrict__ W,
                                                 const float* __restrict__ bias,
                                                 float* __restrict__ out)
{
    extern __shared__ float smq[];
    float* As = smq;
    float* Bs = smq + 2 * ASZ;

    const int tid  = threadIdx.x;
    const int lane = tid & 31;
    const int wid  = tid >> 5;
    const int g    = lane >> 2;
    const int tg   = lane & 3;
    const int wm   = (wid >> 2) * 64;
    const int wn   = (wid & 3) * 32;
    const int bm   = blockIdx.y * 128;
    const int bn   = blockIdx.x * 128;

    float acc[4][4][4];
#pragma unroll
    for (int mi = 0; mi < 4; mi++)
#pragma unroll
        for (int nj = 0; nj < 4; nj++)
#pragma unroll
            for (int t = 0; t < 4; t++) acc[mi][nj][t] = 0.f;

    const int arow = tid >> 3, ac4 = tid & 7;
    const int brow = tid >> 5, bc4 = tid & 31;

    float4 pa[4], pb[4];
    const int NK = 32;

#pragma unroll
    for (int i = 0; i < 4; i++)
        pa[i] = *(const float4*)&g_ao[(size_t)(bm + arow + i * 32) * 1024 + ac4 * 4];
#pragma unroll
    for (int i = 0; i < 4; i++)
        pb[i] = *(const float4*)&W[(size_t)(brow + i * 8) * 1024 + bn + bc4 * 4];
#pragma unroll
    for (int i = 0; i < 4; i++)
        *(float4*)&As[(arow + i * 32) * ALD + ac4 * 4] = tf4(pa[i]);
#pragma unroll
    for (int i = 0; i < 4; i++)
        *(float4*)&Bs[(brow + i * 8) * BLD + bc4 * 4] = tf4(pb[i]);
    __syncthreads();

    for (int kt = 0; kt < NK; kt++) {
        const float* Ab = As + (kt & 1) * ASZ;
        const float* Bb = Bs + (kt & 1) * BSZ;
        const bool more = (kt + 1 < NK);

        if (more) {
            const int k0 = (kt + 1) * 32;
#pragma unroll
            for (int i = 0; i < 4; i++)
                pa[i] = *(const float4*)&g_ao[(size_t)(bm + arow + i * 32) * 1024 + k0 + ac4 * 4];
#pragma unroll
            for (int i = 0; i < 4; i++)
                pb[i] = *(const float4*)&W[(size_t)(k0 + brow + i * 8) * 1024 + bn + bc4 * 4];
        }

#pragma unroll
        for (int kc = 0; kc < 4; kc++) {
            const int k = kc * 8;
            unsigned af[4][4], bf[4][2];
#pragma unroll
            for (int mi = 0; mi < 4; mi++) {
                const int rb = wm + mi * 16;
                af[mi][0] = __float_as_uint(Ab[(rb + g    ) * ALD + k + tg    ]);
                af[mi][1] = __float_as_uint(Ab[(rb + g + 8) * ALD + k + tg    ]);
                af[mi][2] = __float_as_uint(Ab[(rb + g    ) * ALD + k + tg + 4]);
                af[mi][3] = __float_as_uint(Ab[(rb + g + 8) * ALD + k + tg + 4]);
            }
#pragma unroll
            for (int nj = 0; nj < 4; nj++) {
                const int cb = wn + nj * 8;
                bf[nj][0] = __float_as_uint(Bb[(k + tg    ) * BLD + cb + g]);
                bf[nj][1] = __float_as_uint(Bb[(k + tg + 4) * BLD + cb + g]);
            }
#pragma unroll
            for (int mi = 0; mi < 4; mi++)
#pragma unroll
                for (int nj = 0; nj < 4; nj++)
                    mma8(acc[mi][nj], af[mi][0], af[mi][1], af[mi][2], af[mi][3],
                         bf[nj][0], bf[nj][1]);
        }

        if (more) {
            float* An = As + ((kt + 1) & 1) * ASZ;
            float* Bn = Bs + ((kt + 1) & 1) * BSZ;
#pragma unroll
            for (int i = 0; i < 4; i++)
                *(float4*)&An[(arow + i * 32) * ALD + ac4 * 4] = tf4(pa[i]);
#pragma unroll
            for (int i = 0; i < 4; i++)
                *(float4*)&Bn[(brow + i * 8) * BLD + bc4 * 4] = tf4(pb[i]);
        }
        __syncthreads();
    }

#pragma unroll
    for (int mi = 0; mi < 4; mi++) {
#pragma unroll
        for (int nj = 0; nj < 4; nj++) {
#pragma unroll
            for (int t = 0; t < 4; t++) {
                const int m = bm + wm + mi * 16 + g + ((t >= 2) ? 8 : 0);
                const int n = bn + wn + nj * 8 + 2 * tg + (t & 1);
                out[(size_t)m * DD + n] = acc[mi][nj][t] + bias[n];
            }
        }
    }
}

// ---------------------------------------------------------------------------
extern "C" void kernel_launch(void* const* d_in, const int* in_sizes, int n_in,
                              void* d_out, int out_size)
{
    const float* x      = (const float*)d_in[0];
    const float* W_attn = (const float*)d_in[1];
    const float* b_attn = (const float*)d_in[2];
    const float* W_proj = (const float*)d_in[3];
    const float* b_proj = (const float*)d_in[4];
    float* out = (float*)d_out;

    cudaFuncSetAttribute(qkv_gemm,
                         cudaFuncAttributeMaxDynamicSharedMemorySize,
                         GEMM_SMEM_FLOATS * (int)sizeof(float));
    cudaFuncSetAttribute(proj_gemm,
                         cudaFuncAttributeMaxDynamicSharedMemorySize,
                         GEMM_SMEM_FLOATS * (int)sizeof(float));
    cudaFuncSetAttribute(attn_kernel,
                         cudaFuncAttributeMaxDynamicSharedMemorySize,
                         ATT_SMEM_FLOATS * (int)sizeof(float));

    qkv_gemm<<<dim3(24, 32), 256, GEMM_SMEM_FLOATS * sizeof(float)>>>(x, W_attn, b_attn);
    attn_kernel<<<dim3(SS / 128, HH, BB), 256, ATT_SMEM_FLOATS * sizeof(float)>>>(out);
    proj_gemm<<<dim3(8, 32), 256, GEMM_SMEM_FLOATS * sizeof(float)>>>(W_proj, b_proj, out);
}

// round 6
// speedup vs baseline: 5.8271x; 1.1386x over previous
#include <cuda_runtime.h>
#include <math.h>

#define BB 2
#define HH 16
#define SS 2048
#define DD 1024
#define HD 64
#define MM (BB*SS)          // 4096 rows

// Scratch (device globals: allocation-free per harness rules)
__device__ float g_q[BB*HH*SS*HD];   // [B,H,S,hd]  (tf32-rounded)
__device__ float g_k[BB*HH*SS*HD];
__device__ float g_v[BB*HH*SS*HD];
__device__ float g_ao[MM*DD];        // attention output, tf32-rounded
__device__ float g_x[MM*DD];         // tf32-rounded X
__device__ float g_wa[DD*3*DD];      // tf32-rounded W_attn
__device__ float g_wp[DD*DD];        // tf32-rounded W_proj

// ---------------------------------------------------------------------------
// helpers
// ---------------------------------------------------------------------------
__device__ __forceinline__ unsigned f2tf(float f) {
    unsigned u;
    asm("cvt.rna.tf32.f32 %0, %1;" : "=r"(u) : "f"(f));
    return u;
}
__device__ __forceinline__ float4 tf4(float4 v) {
    v.x = __uint_as_float(f2tf(v.x));
    v.y = __uint_as_float(f2tf(v.y));
    v.z = __uint_as_float(f2tf(v.z));
    v.w = __uint_as_float(f2tf(v.w));
    return v;
}
__device__ __forceinline__ void mma8(float* c,
                                     unsigned a0, unsigned a1, unsigned a2, unsigned a3,
                                     unsigned b0, unsigned b1) {
    asm volatile(
        "mma.sync.aligned.m16n8k8.row.col.f32.tf32.tf32.f32 "
        "{%0,%1,%2,%3},{%4,%5,%6,%7},{%8,%9},{%0,%1,%2,%3};"
        : "+f"(c[0]), "+f"(c[1]), "+f"(c[2]), "+f"(c[3])
        : "r"(a0), "r"(a1), "r"(a2), "r"(a3), "r"(b0), "r"(b1));
}
__device__ __forceinline__ void cpa16(float* smem_dst, const float* gsrc) {
    unsigned s = (unsigned)__cvta_generic_to_shared(smem_dst);
    asm volatile("cp.async.cg.shared.global [%0], [%1], 16;" :: "r"(s), "l"(gsrc));
}
__device__ __forceinline__ void cpa_commit() {
    asm volatile("cp.async.commit_group;");
}
__device__ __forceinline__ void cpa_wait0() {
    asm volatile("cp.async.wait_group 0;");
}

// ---------------------------------------------------------------------------
// Input pre-round kernel: tf32-round X, W_attn, W_proj into scratch
// ---------------------------------------------------------------------------
__global__ __launch_bounds__(256) void cvt_inputs(const float* __restrict__ X,
                                                  const float* __restrict__ Wa,
                                                  const float* __restrict__ Wp)
{
    const int stride = gridDim.x * blockDim.x;
    int i = blockIdx.x * blockDim.x + threadIdx.x;
    for (int k = i; k < MM * DD / 4; k += stride)
        ((float4*)g_x)[k] = tf4(((const float4*)X)[k]);
    for (int k = i; k < DD * 3 * DD / 4; k += stride)
        ((float4*)g_wa)[k] = tf4(((const float4*)Wa)[k]);
    for (int k = i; k < DD * DD / 4; k += stride)
        ((float4*)g_wp)[k] = tf4(((const float4*)Wp)[k]);
}

// ---------------------------------------------------------------------------
// QKV GEMM: cp.async 2-stage pipeline, 2 CTAs/SM
// ---------------------------------------------------------------------------
#define ALD 36
#define BLD 136
#define ASZ (128*ALD)
#define BSZ (32*BLD)
#define GEMM_SMEM_FLOATS (2*ASZ + 2*BSZ)

__global__ __launch_bounds__(256, 2) void qkv_gemm(const float* __restrict__ bias)
{
    extern __shared__ float smq[];
    float* As = smq;              // [2][ASZ]
    float* Bs = smq + 2 * ASZ;    // [2][BSZ]

    const int tid  = threadIdx.x;
    const int lane = tid & 31;
    const int wid  = tid >> 5;
    const int g    = lane >> 2;
    const int tg   = lane & 3;
    const int wm   = (wid >> 2) * 64;
    const int wn   = (wid & 3) * 32;
    const int bm   = blockIdx.y * 128;
    const int bn   = blockIdx.x * 128;

    float acc[4][4][4];
#pragma unroll
    for (int mi = 0; mi < 4; mi++)
#pragma unroll
        for (int nj = 0; nj < 4; nj++)
#pragma unroll
            for (int t = 0; t < 4; t++) acc[mi][nj][t] = 0.f;

    const int arow = tid >> 3, ac4 = tid & 7;
    const int brow = tid >> 5, bc4 = tid & 31;
    const int NK = 32;

    // prologue: async-load tile 0
#pragma unroll
    for (int i = 0; i < 4; i++)
        cpa16(&As[(arow + i * 32) * ALD + ac4 * 4],
              &g_x[(size_t)(bm + arow + i * 32) * 1024 + ac4 * 4]);
#pragma unroll
    for (int i = 0; i < 4; i++)
        cpa16(&Bs[(brow + i * 8) * BLD + bc4 * 4],
              &g_wa[(size_t)(brow + i * 8) * 3072 + bn + bc4 * 4]);
    cpa_commit();

    for (int kt = 0; kt < NK; kt++) {
        cpa_wait0();
        __syncthreads();

        if (kt + 1 < NK) {
            const int k0 = (kt + 1) * 32;
            float* An = As + ((kt + 1) & 1) * ASZ;
            float* Bn = Bs + ((kt + 1) & 1) * BSZ;
#pragma unroll
            for (int i = 0; i < 4; i++)
                cpa16(&An[(arow + i * 32) * ALD + ac4 * 4],
                      &g_x[(size_t)(bm + arow + i * 32) * 1024 + k0 + ac4 * 4]);
#pragma unroll
            for (int i = 0; i < 4; i++)
                cpa16(&Bn[(brow + i * 8) * BLD + bc4 * 4],
                      &g_wa[(size_t)(k0 + brow + i * 8) * 3072 + bn + bc4 * 4]);
            cpa_commit();
        }

        const float* Ab = As + (kt & 1) * ASZ;
        const float* Bb = Bs + (kt & 1) * BSZ;
#pragma unroll
        for (int kc = 0; kc < 4; kc++) {
            const int k = kc * 8;
            unsigned af[4][4], bf[4][2];
#pragma unroll
            for (int mi = 0; mi < 4; mi++) {
                const int rb = wm + mi * 16;
                af[mi][0] = __float_as_uint(Ab[(rb + g    ) * ALD + k + tg    ]);
                af[mi][1] = __float_as_uint(Ab[(rb + g + 8) * ALD + k + tg    ]);
                af[mi][2] = __float_as_uint(Ab[(rb + g    ) * ALD + k + tg + 4]);
                af[mi][3] = __float_as_uint(Ab[(rb + g + 8) * ALD + k + tg + 4]);
            }
#pragma unroll
            for (int nj = 0; nj < 4; nj++) {
                const int cb = wn + nj * 8;
                bf[nj][0] = __float_as_uint(Bb[(k + tg    ) * BLD + cb + g]);
                bf[nj][1] = __float_as_uint(Bb[(k + tg + 4) * BLD + cb + g]);
            }
#pragma unroll
            for (int mi = 0; mi < 4; mi++)
#pragma unroll
                for (int nj = 0; nj < 4; nj++)
                    mma8(acc[mi][nj], af[mi][0], af[mi][1], af[mi][2], af[mi][3],
                         bf[nj][0], bf[nj][1]);
        }
    }

    // Epilogue: bias + tf32-round + scatter to q/k/v [B,H,S,hd]
#pragma unroll
    for (int mi = 0; mi < 4; mi++) {
#pragma unroll
        for (int nj = 0; nj < 4; nj++) {
#pragma unroll
            for (int t = 0; t < 4; t++) {
                const int m = bm + wm + mi * 16 + g + ((t >= 2) ? 8 : 0);
                const int n = bn + wn + nj * 8 + 2 * tg + (t & 1);
                const float v = __uint_as_float(f2tf(acc[mi][nj][t] + bias[n]));
                const int bidx = m >> 11;
                const int s = m & 2047;
                const int which = n >> 10;
                const int jj = n & 1023;
                const int h = jj >> 6;
                const int d = jj & 63;
                float* dst = (which == 0) ? g_q : (which == 1) ? g_k : g_v;
                dst[(size_t)((bidx * HH + h) * SS + s) * HD + d] = v;
            }
        }
    }
}

// ---------------------------------------------------------------------------
// Flash-style attention with cp.async-staged K/V (pre-rounded producers)
// ---------------------------------------------------------------------------
#define PS_LD 132
#define KV_LD 68
#define KVSZ (128*KV_LD)
#define ATT_SMEM_FLOATS (128*PS_LD + 4*KVSZ)

__global__ __launch_bounds__(256) void attn_kernel(float* __restrict__ out_base)
{
    extern __shared__ float sm[];
    float* Ps = sm;                       // [128][PS_LD]
    float* Ks = sm + 128 * PS_LD;         // [2][KVSZ]
    float* Vs = Ks + 2 * KVSZ;            // [2][KVSZ]

    const int tid  = threadIdx.x;
    const int lane = tid & 31;
    const int wid  = tid >> 5;
    const int g    = lane >> 2;
    const int tg   = lane & 3;
    const int qw   = wid * 16;

    const int b  = blockIdx.z;
    const int h  = blockIdx.y;
    const int qt = blockIdx.x;
    const int q0 = qt * 128;

    const float* Qbh = g_q + (size_t)((b * HH + h) * SS) * HD;
    const float* Kbh = g_k + (size_t)((b * HH + h) * SS) * HD;
    const float* Vbh = g_v + (size_t)((b * HH + h) * SS) * HD;

    const int srow = tid >> 4, sc4 = tid & 15;

    // prologue: async-load K0, V0
#pragma unroll
    for (int i = 0; i < 8; i++)
        cpa16(&Ks[(srow + i * 16) * KV_LD + sc4 * 4],
              &Kbh[(size_t)(srow + i * 16) * HD + sc4 * 4]);
#pragma unroll
    for (int i = 0; i < 8; i++)
        cpa16(&Vs[(srow + i * 16) * KV_LD + sc4 * 4],
              &Vbh[(size_t)(srow + i * 16) * HD + sc4 * 4]);
    cpa_commit();

    // Q fragments loaded directly from gmem (once; g_q is pre-rounded)
    unsigned qa[8][4];
    {
        const float* q0p = Qbh + (size_t)(q0 + qw + g) * HD;
        const float* q1p = Qbh + (size_t)(q0 + qw + g + 8) * HD;
#pragma unroll
        for (int kc = 0; kc < 8; kc++) {
            const int k = kc * 8;
            qa[kc][0] = __float_as_uint(q0p[k + tg    ]);
            qa[kc][1] = __float_as_uint(q1p[k + tg    ]);
            qa[kc][2] = __float_as_uint(q0p[k + tg + 4]);
            qa[kc][3] = __float_as_uint(q1p[k + tg + 4]);
        }
    }

    float m0 = -1e30f, m1 = -1e30f, l0 = 0.f, l1 = 0.f;
    float o[8][4];
#pragma unroll
    for (int nf = 0; nf < 8; nf++)
#pragma unroll
        for (int t = 0; t < 4; t++) o[nf][t] = 0.f;

    const int nkt  = qt + 1;
    const int row0 = q0 + qw + g;
    const int row1 = row0 + 8;

    // ======================= Pass 1: online softmax + AV ===================
    for (int kt = 0; kt < nkt; kt++) {
        cpa_wait0();
        __syncthreads();

        if (kt + 1 < nkt) {
            const int nb = (kt + 1) * 128;
            float* Kn = Ks + ((kt + 1) & 1) * KVSZ;
            float* Vn = Vs + ((kt + 1) & 1) * KVSZ;
#pragma unroll
            for (int i = 0; i < 8; i++)
                cpa16(&Kn[(srow + i * 16) * KV_LD + sc4 * 4],
                      &Kbh[(size_t)(nb + srow + i * 16) * HD + sc4 * 4]);
#pragma unroll
            for (int i = 0; i < 8; i++)
                cpa16(&Vn[(srow + i * 16) * KV_LD + sc4 * 4],
                      &Vbh[(size_t)(nb + srow + i * 16) * HD + sc4 * 4]);
            cpa_commit();
        }

        const float* Kb = Ks + (kt & 1) * KVSZ;
        const float* Vb = Vs + (kt & 1) * KVSZ;
        const int kbase = kt * 128;

        // S = Q K^T
        float s[16][4];
#pragma unroll
        for (int nf = 0; nf < 16; nf++)
#pragma unroll
            for (int t = 0; t < 4; t++) s[nf][t] = 0.f;
#pragma unroll
        for (int kc = 0; kc < 8; kc++) {
            const int k = kc * 8;
#pragma unroll
            for (int nf = 0; nf < 16; nf++) {
                const unsigned b0 = __float_as_uint(Kb[(nf * 8 + g) * KV_LD + k + tg    ]);
                const unsigned b1 = __float_as_uint(Kb[(nf * 8 + g) * KV_LD + k + tg + 4]);
                mma8(s[nf], qa[kc][0], qa[kc][1], qa[kc][2], qa[kc][3], b0, b1);
            }
        }

        // scale + causal mask + tile row max
        const bool diag = (kt == qt);
        float mx0 = -1e30f, mx1 = -1e30f;
#pragma unroll
        for (int nf = 0; nf < 16; nf++) {
            const int col = kbase + nf * 8 + 2 * tg;
            float v0 = s[nf][0] * 0.125f;
            float v1 = s[nf][1] * 0.125f;
            float v2 = s[nf][2] * 0.125f;
            float v3 = s[nf][3] * 0.125f;
            if (diag) {
                if (col     > row0) v0 = -1e30f;
                if (col + 1 > row0) v1 = -1e30f;
                if (col     > row1) v2 = -1e30f;
                if (col + 1 > row1) v3 = -1e30f;
            }
            s[nf][0] = v0; s[nf][1] = v1; s[nf][2] = v2; s[nf][3] = v3;
            mx0 = fmaxf(mx0, fmaxf(v0, v1));
            mx1 = fmaxf(mx1, fmaxf(v2, v3));
        }
        mx0 = fmaxf(mx0, __shfl_xor_sync(0xffffffffu, mx0, 1));
        mx0 = fmaxf(mx0, __shfl_xor_sync(0xffffffffu, mx0, 2));
        mx1 = fmaxf(mx1, __shfl_xor_sync(0xffffffffu, mx1, 1));
        mx1 = fmaxf(mx1, __shfl_xor_sync(0xffffffffu, mx1, 2));

        const float mn0 = fmaxf(m0, mx0);
        const float mn1 = fmaxf(m1, mx1);
        const float al0 = __expf(m0 - mn0);
        const float al1 = __expf(m1 - mn1);

        float rs0 = 0.f, rs1 = 0.f;
#pragma unroll
        for (int nf = 0; nf < 16; nf++) {
            const float p0 = __expf(s[nf][0] - mn0);
            const float p1 = __expf(s[nf][1] - mn0);
            const float p2 = __expf(s[nf][2] - mn1);
            const float p3 = __expf(s[nf][3] - mn1);
            rs0 += p0 + p1;
            rs1 += p2 + p3;
            float2 t0, t1;
            t0.x = __uint_as_float(f2tf(p0)); t0.y = __uint_as_float(f2tf(p1));
            t1.x = __uint_as_float(f2tf(p2)); t1.y = __uint_as_float(f2tf(p3));
            *(float2*)&Ps[(qw + g    ) * PS_LD + nf * 8 + 2 * tg] = t0;
            *(float2*)&Ps[(qw + g + 8) * PS_LD + nf * 8 + 2 * tg] = t1;
        }
        rs0 += __shfl_xor_sync(0xffffffffu, rs0, 1);
        rs0 += __shfl_xor_sync(0xffffffffu, rs0, 2);
        rs1 += __shfl_xor_sync(0xffffffffu, rs1, 1);
        rs1 += __shfl_xor_sync(0xffffffffu, rs1, 2);

        m0 = mn0; m1 = mn1;
        l0 = l0 * al0 + rs0;
        l1 = l1 * al1 + rs1;
#pragma unroll
        for (int nf = 0; nf < 8; nf++) {
            o[nf][0] *= al0; o[nf][1] *= al0;
            o[nf][2] *= al1; o[nf][3] *= al1;
        }

        // O += P V (Ps rows are warp-private)
#pragma unroll
        for (int kc = 0; kc < 16; kc++) {
            const int k = kc * 8;
            const unsigned a0 = __float_as_uint(Ps[(qw + g    ) * PS_LD + k + tg    ]);
            const unsigned a1 = __float_as_uint(Ps[(qw + g + 8) * PS_LD + k + tg    ]);
            const unsigned a2 = __float_as_uint(Ps[(qw + g    ) * PS_LD + k + tg + 4]);
            const unsigned a3 = __float_as_uint(Ps[(qw + g + 8) * PS_LD + k + tg + 4]);
#pragma unroll
            for (int nf = 0; nf < 8; nf++) {
                const unsigned b0 = __float_as_uint(Vb[(k + tg    ) * KV_LD + nf * 8 + g]);
                const unsigned b1 = __float_as_uint(Vb[(k + tg + 4) * KV_LD + nf * 8 + g]);
                mma8(o[nf], a0, a1, a2, a3, b0, b1);
            }
        }
    }

    // Write O / l (tf32-rounded; consumed only by proj mma)
    const float il0 = 1.0f / l0;
    const float il1 = 1.0f / l1;
    {
        const int orow = b * SS + q0 + qw + g;
#pragma unroll
        for (int nf = 0; nf < 8; nf++) {
            const int col = h * HD + nf * 8 + 2 * tg;
            float2 r0, r1;
            r0.x = __uint_as_float(f2tf(o[nf][0] * il0));
            r0.y = __uint_as_float(f2tf(o[nf][1] * il0));
            r1.x = __uint_as_float(f2tf(o[nf][2] * il1));
            r1.y = __uint_as_float(f2tf(o[nf][3] * il1));
            *(float2*)&g_ao[(size_t)orow * DD + col] = r0;
            *(float2*)&g_ao[(size_t)(orow + 8) * DD + col] = r1;
        }
    }
    __syncthreads();   // all warps done reading Ks/Vs before pass-2 overwrites

    // =============== Pass 2: recompute scores, write weights direct ========
    float* attn = out_base + (size_t)MM * DD;
    const size_t abase = (size_t)(b * HH + h) * SS + q0;
    float* w0p = attn + (abase + qw + g) * SS;
    float* w1p = attn + (abase + qw + g + 8) * SS;

#pragma unroll
    for (int i = 0; i < 8; i++)
        cpa16(&Ks[(srow + i * 16) * KV_LD + sc4 * 4],
              &Kbh[(size_t)(srow + i * 16) * HD + sc4 * 4]);
    cpa_commit();

    for (int kt = 0; kt < nkt; kt++) {
        cpa_wait0();
        __syncthreads();

        if (kt + 1 < nkt) {
            const int nb = (kt + 1) * 128;
            float* Kn = Ks + ((kt + 1) & 1) * KVSZ;
#pragma unroll
            for (int i = 0; i < 8; i++)
                cpa16(&Kn[(srow + i * 16) * KV_LD + sc4 * 4],
                      &Kbh[(size_t)(nb + srow + i * 16) * HD + sc4 * 4]);
            cpa_commit();
        }

        const float* Kb = Ks + (kt & 1) * KVSZ;
        const int kbase = kt * 128;

        float s[16][4];
#pragma unroll
        for (int nf = 0; nf < 16; nf++)
#pragma unroll
            for (int t = 0; t < 4; t++) s[nf][t] = 0.f;
#pragma unroll
        for (int kc = 0; kc < 8; kc++) {
            const int k = kc * 8;
#pragma unroll
            for (int nf = 0; nf < 16; nf++) {
                const unsigned b0 = __float_as_uint(Kb[(nf * 8 + g) * KV_LD + k + tg    ]);
                const unsigned b1 = __float_as_uint(Kb[(nf * 8 + g) * KV_LD + k + tg + 4]);
                mma8(s[nf], qa[kc][0], qa[kc][1], qa[kc][2], qa[kc][3], b0, b1);
            }
        }

        const bool diag = (kt == qt);
#pragma unroll
        for (int nf = 0; nf < 16; nf++) {
            const int col = kbase + nf * 8 + 2 * tg;
            float w0 = __expf(s[nf][0] * 0.125f - m0) * il0;
            float w1 = __expf(s[nf][1] * 0.125f - m0) * il0;
            float w2 = __expf(s[nf][2] * 0.125f - m1) * il1;
            float w3 = __expf(s[nf][3] * 0.125f - m1) * il1;
            if (diag) {
                if (col     > row0) w0 = 0.f;
                if (col + 1 > row0) w1 = 0.f;
                if (col     > row1) w2 = 0.f;
                if (col + 1 > row1) w3 = 0.f;
            }
            float2 t0, t1;
            t0.x = w0; t0.y = w1;
            t1.x = w2; t1.y = w3;
            *(float2*)&w0p[col] = t0;
            *(float2*)&w1p[col] = t1;
        }
    }

    // zero-fill strictly-upper region
    const int kl = nkt * 128;
    if (kl < SS) {
        const float4 z = make_float4(0.f, 0.f, 0.f, 0.f);
        const int w4 = (SS - kl) >> 2;
        for (int row = 0; row < 128; row++) {
            float4* dst = (float4*)&attn[(abase + row) * SS + kl];
            for (int c = tid; c < w4; c += 256) dst[c] = z;
        }
    }
}

// ---------------------------------------------------------------------------
// Projection GEMM: cp.async 2-stage pipeline, 2 CTAs/SM
// ---------------------------------------------------------------------------
__global__ __launch_bounds__(256, 2) void proj_gemm(const float* __restrict__ bias,
                                                    float* __restrict__ out)
{
    extern __shared__ float smq[];
    float* As = smq;
    float* Bs = smq + 2 * ASZ;

    const int tid  = threadIdx.x;
    const int lane = tid & 31;
    const int wid  = tid >> 5;
    const int g    = lane >> 2;
    const int tg   = lane & 3;
    const int wm   = (wid >> 2) * 64;
    const int wn   = (wid & 3) * 32;
    const int bm   = blockIdx.y * 128;
    const int bn   = blockIdx.x * 128;

    float acc[4][4][4];
#pragma unroll
    for (int mi = 0; mi < 4; mi++)
#pragma unroll
        for (int nj = 0; nj < 4; nj++)
#pragma unroll
            for (int t = 0; t < 4; t++) acc[mi][nj][t] = 0.f;

    const int arow = tid >> 3, ac4 = tid & 7;
    const int brow = tid >> 5, bc4 = tid & 31;
    const int NK = 32;

#pragma unroll
    for (int i = 0; i < 4; i++)
        cpa16(&As[(arow + i * 32) * ALD + ac4 * 4],
              &g_ao[(size_t)(bm + arow + i * 32) * 1024 + ac4 * 4]);
#pragma unroll
    for (int i = 0; i < 4; i++)
        cpa16(&Bs[(brow + i * 8) * BLD + bc4 * 4],
              &g_wp[(size_t)(brow + i * 8) * 1024 + bn + bc4 * 4]);
    cpa_commit();

    for (int kt = 0; kt < NK; kt++) {
        cpa_wait0();
        __syncthreads();

        if (kt + 1 < NK) {
            const int k0 = (kt + 1) * 32;
            float* An = As + ((kt + 1) & 1) * ASZ;
            float* Bn = Bs + ((kt + 1) & 1) * BSZ;
#pragma unroll
            for (int i = 0; i < 4; i++)
                cpa16(&An[(arow + i * 32) * ALD + ac4 * 4],
                      &g_ao[(size_t)(bm + arow + i * 32) * 1024 + k0 + ac4 * 4]);
#pragma unroll
            for (int i = 0; i < 4; i++)
                cpa16(&Bn[(brow + i * 8) * BLD + bc4 * 4],
                      &g_wp[(size_t)(k0 + brow + i * 8) * 1024 + bn + bc4 * 4]);
            cpa_commit();
        }

        const float* Ab = As + (kt & 1) * ASZ;
        const float* Bb = Bs + (kt & 1) * BSZ;
#pragma unroll
        for (int kc = 0; kc < 4; kc++) {
            const int k = kc * 8;
            unsigned af[4][4], bf[4][2];
#pragma unroll
            for (int mi = 0; mi < 4; mi++) {
                const int rb = wm + mi * 16;
                af[mi][0] = __float_as_uint(Ab[(rb + g    ) * ALD + k + tg    ]);
                af[mi][1] = __float_as_uint(Ab[(rb + g + 8) * ALD + k + tg    ]);
                af[mi][2] = __float_as_uint(Ab[(rb + g    ) * ALD + k + tg + 4]);
                af[mi][3] = __float_as_uint(Ab[(rb + g + 8) * ALD + k + tg + 4]);
            }
#pragma unroll
            for (int nj = 0; nj < 4; nj++) {
                const int cb = wn + nj * 8;
                bf[nj][0] = __float_as_uint(Bb[(k + tg    ) * BLD + cb + g]);
                bf[nj][1] = __float_as_uint(Bb[(k + tg + 4) * BLD + cb + g]);
            }
#pragma unroll
            for (int mi = 0; mi < 4; mi++)
#pragma unroll
                for (int nj = 0; nj < 4; nj++)
                    mma8(acc[mi][nj], af[mi][0], af[mi][1], af[mi][2], af[mi][3],
                         bf[nj][0], bf[nj][1]);
        }
    }

#pragma unroll
    for (int mi = 0; mi < 4; mi++) {
#pragma unroll
        for (int nj = 0; nj < 4; nj++) {
#pragma unroll
            for (int t = 0; t < 4; t++) {
                const int m = bm + wm + mi * 16 + g + ((t >= 2) ? 8 : 0);
                const int n = bn + wn + nj * 8 + 2 * tg + (t & 1);
                out[(size_t)m * DD + n] = acc[mi][nj][t] + bias[n];
            }
        }
    }
}

// ---------------------------------------------------------------------------
extern "C" void kernel_launch(void* const* d_in, const int* in_sizes, int n_in,
                              void* d_out, int out_size)
{
    const float* x      = (const float*)d_in[0];
    const float* W_attn = (const float*)d_in[1];
    const float* b_attn = (const float*)d_in[2];
    const float* W_proj = (const float*)d_in[3];
    const float* b_proj = (const float*)d_in[4];
    float* out = (float*)d_out;

    cudaFuncSetAttribute(qkv_gemm,
                         cudaFuncAttributeMaxDynamicSharedMemorySize,
                         GEMM_SMEM_FLOATS * (int)sizeof(float));
    cudaFuncSetAttribute(proj_gemm,
                         cudaFuncAttributeMaxDynamicSharedMemorySize,
                         GEMM_SMEM_FLOATS * (int)sizeof(float));
    cudaFuncSetAttribute(attn_kernel,
                         cudaFuncAttributeMaxDynamicSharedMemorySize,
                         ATT_SMEM_FLOATS * (int)sizeof(float));

    cvt_inputs<<<1024, 256>>>(x, W_attn, W_proj);
    qkv_gemm<<<dim3(24, 32), 256, GEMM_SMEM_FLOATS * sizeof(float)>>>(b_attn);
    attn_kernel<<<dim3(SS / 128, HH, BB), 256, ATT_SMEM_FLOATS * sizeof(float)>>>(out);
    proj_gemm<<<dim3(8, 32), 256, GEMM_SMEM_FLOATS * sizeof(float)>>>(b_proj, out);
}

// round 8
// speedup vs baseline: 7.2955x; 1.2520x over previous
#include <cuda_runtime.h>
#include <cuda_fp16.h>
#include <math.h>

#define BB 2
#define HH 16
#define SS 2048
#define DD 1024
#define HD 64
#define MM (BB*SS)          // 4096 rows

// Scratch (device globals)
__device__ __half g_q[BB*HH*SS*HD];   // [B,H,S,hd] fp16
__device__ __half g_k[BB*HH*SS*HD];
__device__ float  g_v[BB*HH*SS*HD];   // tf32-rounded float (PV stays tf32)
__device__ __half g_ao[MM*DD];        // attention output fp16
__device__ __half g_x[MM*DD];         // fp16 X
__device__ __half g_wa[3*DD*DD];      // W_attn^T  [n=3072][k=1024] fp16
__device__ __half g_wp[DD*DD];        // W_proj^T  [n=1024][k=1024] fp16

// ---------------------------------------------------------------------------
// helpers
// ---------------------------------------------------------------------------
__device__ __forceinline__ unsigned f2tf(float f) {
    unsigned u;
    asm("cvt.rna.tf32.f32 %0, %1;" : "=r"(u) : "f"(f));
    return u;
}
__device__ __forceinline__ void mma16(float* c,
                                      unsigned a0, unsigned a1, unsigned a2, unsigned a3,
                                      unsigned b0, unsigned b1) {
    asm volatile(
        "mma.sync.aligned.m16n8k16.row.col.f32.f16.f16.f32 "
        "{%0,%1,%2,%3},{%4,%5,%6,%7},{%8,%9},{%0,%1,%2,%3};"
        : "+f"(c[0]), "+f"(c[1]), "+f"(c[2]), "+f"(c[3])
        : "r"(a0), "r"(a1), "r"(a2), "r"(a3), "r"(b0), "r"(b1));
}
__device__ __forceinline__ void mma8(float* c,
                                     unsigned a0, unsigned a1, unsigned a2, unsigned a3,
                                     unsigned b0, unsigned b1) {
    asm volatile(
        "mma.sync.aligned.m16n8k8.row.col.f32.tf32.tf32.f32 "
        "{%0,%1,%2,%3},{%4,%5,%6,%7},{%8,%9},{%0,%1,%2,%3};"
        : "+f"(c[0]), "+f"(c[1]), "+f"(c[2]), "+f"(c[3])
        : "r"(a0), "r"(a1), "r"(a2), "r"(a3), "r"(b0), "r"(b1));
}
__device__ __forceinline__ void cpa16(const void* smem_dst, const void* gsrc) {
    unsigned s = (unsigned)__cvta_generic_to_shared(smem_dst);
    asm volatile("cp.async.cg.shared.global [%0], [%1], 16;" :: "r"(s), "l"(gsrc));
}
__device__ __forceinline__ void cpa_commit() {
    asm volatile("cp.async.commit_group;");
}
__device__ __forceinline__ void cpa_wait0() {
    asm volatile("cp.async.wait_group 0;");
}
__device__ __forceinline__ void cpa_wait1() {
    asm volatile("cp.async.wait_group 1;");
}

// ---------------------------------------------------------------------------
// Converters
// ---------------------------------------------------------------------------
__global__ __launch_bounds__(256) void cvt_x(const float* __restrict__ X)
{
    const int stride = gridDim.x * blockDim.x;
    for (int k = blockIdx.x * blockDim.x + threadIdx.x; k < MM * DD / 4; k += stride) {
        float4 v = ((const float4*)X)[k];
        __half2 h0 = __floats2half2_rn(v.x, v.y);
        __half2 h1 = __floats2half2_rn(v.z, v.w);
        ((__half2*)g_x)[k * 2    ] = h0;
        ((__half2*)g_x)[k * 2 + 1] = h1;
    }
}

// W [1024][N] float -> Wt [N][1024] half (tiled transpose)
__global__ __launch_bounds__(256) void transpose_wa(const float* __restrict__ W)
{
    __shared__ float ts[32][33];
    const int tx = threadIdx.x & 31, ty = threadIdx.x >> 5;
    const int nb = blockIdx.x * 32, kb = blockIdx.y * 32;
#pragma unroll
    for (int i = 0; i < 4; i++)
        ts[ty + i * 8][tx] = W[(size_t)(kb + ty + i * 8) * 3072 + nb + tx];
    __syncthreads();
#pragma unroll
    for (int i = 0; i < 4; i++)
        g_wa[(size_t)(nb + ty + i * 8) * 1024 + kb + tx] = __float2half_rn(ts[tx][ty + i * 8]);
}
__global__ __launch_bounds__(256) void transpose_wp(const float* __restrict__ W)
{
    __shared__ float ts[32][33];
    const int tx = threadIdx.x & 31, ty = threadIdx.x >> 5;
    const int nb = blockIdx.x * 32, kb = blockIdx.y * 32;
#pragma unroll
    for (int i = 0; i < 4; i++)
        ts[ty + i * 8][tx] = W[(size_t)(kb + ty + i * 8) * 1024 + nb + tx];
    __syncthreads();
#pragma unroll
    for (int i = 0; i < 4; i++)
        g_wp[(size_t)(nb + ty + i * 8) * 1024 + kb + tx] = __float2half_rn(ts[tx][ty + i * 8]);
}

// ---------------------------------------------------------------------------
// fp16 GEMM core: C[128x128] tile, A [m][k] half, B [n][k] half, 3-stage cp.async
// A/B tiles: 128 rows x 32 halves, row stride 40 halves (20 u32, conflict-free)
// ---------------------------------------------------------------------------
#define TH 40                 // halves per tile row
#define TH32 20
#define TSZ (128*TH)          // halves per tile buffer
#define GEMM_SMEM_BYTES (3 * 2 * TSZ * 2)

__device__ __forceinline__ void gemm128(const __half* __restrict__ Asrc, size_t a_stride,
                                        const __half* __restrict__ Bsrc, size_t b_stride,
                                        int bm, int bn, __half* sh, float acc[4][4][4])
{
    __half* Ah = sh;                 // [3][TSZ]
    __half* Bh = sh + 3 * TSZ;       // [3][TSZ]

    const int tid  = threadIdx.x;
    const int NK = 32;

    auto stage = [&](int t) {
        const int k0 = t * 32;
        __half* An = Ah + (t % 3) * TSZ;
        __half* Bn = Bh + (t % 3) * TSZ;
#pragma unroll
        for (int i = 0; i < 2; i++) {
            int c = tid + i * 256;               // 512 chunks
            int row = c >> 2, cc = c & 3;
            cpa16(&An[row * TH + cc * 8], &Asrc[(size_t)(bm + row) * a_stride + k0 + cc * 8]);
            cpa16(&Bn[row * TH + cc * 8], &Bsrc[(size_t)(bn + row) * b_stride + k0 + cc * 8]);
        }
    };

    stage(0); cpa_commit();
    stage(1); cpa_commit();

    const int lane = tid & 31;
    const int wid  = tid >> 5;
    const int g    = lane >> 2;
    const int tg   = lane & 3;
    const int wm   = (wid >> 2) * 64;
    const int wn   = (wid & 3) * 32;

    for (int kt = 0; kt < NK; kt++) {
        cpa_wait1();
        __syncthreads();
        if (kt + 2 < NK) stage(kt + 2);
        cpa_commit();

        const unsigned* A32 = (const unsigned*)(Ah + (kt % 3) * TSZ);
        const unsigned* B32 = (const unsigned*)(Bh + (kt % 3) * TSZ);
#pragma unroll
        for (int kc = 0; kc < 2; kc++) {
            const int kb = kc * 8;
            unsigned af[4][4], bf[4][2];
#pragma unroll
            for (int mi = 0; mi < 4; mi++) {
                const int rb = wm + mi * 16;
                af[mi][0] = A32[(rb + g    ) * TH32 + kb + tg    ];
                af[mi][1] = A32[(rb + g + 8) * TH32 + kb + tg    ];
                af[mi][2] = A32[(rb + g    ) * TH32 + kb + tg + 4];
                af[mi][3] = A32[(rb + g + 8) * TH32 + kb + tg + 4];
            }
#pragma unroll
            for (int nj = 0; nj < 4; nj++) {
                const int cb = wn + nj * 8;
                bf[nj][0] = B32[(cb + g) * TH32 + kb + tg    ];
                bf[nj][1] = B32[(cb + g) * TH32 + kb + tg + 4];
            }
#pragma unroll
            for (int mi = 0; mi < 4; mi++)
#pragma unroll
                for (int nj = 0; nj < 4; nj++)
                    mma16(acc[mi][nj], af[mi][0], af[mi][1], af[mi][2], af[mi][3],
                          bf[nj][0], bf[nj][1]);
        }
    }
}

// ---------------------------------------------------------------------------
// QKV GEMM: X[4096,1024]h @ Wa^T -> q/k (half) , v (float, tf32-rounded)
// ---------------------------------------------------------------------------
__global__ __launch_bounds__(256, 2) void qkv_gemm(const float* __restrict__ bias)
{
    extern __shared__ __half shq[];
    float acc[4][4][4];
#pragma unroll
    for (int mi = 0; mi < 4; mi++)
#pragma unroll
        for (int nj = 0; nj < 4; nj++)
#pragma unroll
            for (int t = 0; t < 4; t++) acc[mi][nj][t] = 0.f;

    const int bm = blockIdx.y * 128;
    const int bn = blockIdx.x * 128;
    gemm128(g_x, 1024, g_wa, 1024, bm, bn, shq, acc);

    const int lane = threadIdx.x & 31;
    const int wid  = threadIdx.x >> 5;
    const int g    = lane >> 2;
    const int tg   = lane & 3;
    const int wm   = (wid >> 2) * 64;
    const int wn   = (wid & 3) * 32;

#pragma unroll
    for (int mi = 0; mi < 4; mi++) {
#pragma unroll
        for (int nj = 0; nj < 4; nj++) {
#pragma unroll
            for (int t = 0; t < 4; t++) {
                const int m = bm + wm + mi * 16 + g + ((t >= 2) ? 8 : 0);
                const int n = bn + wn + nj * 8 + 2 * tg + (t & 1);
                const float v = acc[mi][nj][t] + bias[n];
                const int bidx = m >> 11;
                const int s = m & 2047;
                const int which = n >> 10;
                const int jj = n & 1023;
                const int h = jj >> 6;
                const int d = jj & 63;
                const size_t off = (size_t)((bidx * HH + h) * SS + s) * HD + d;
                if (which == 0)      g_q[off] = __float2half_rn(v);
                else if (which == 1) g_k[off] = __float2half_rn(v);
                else                 g_v[off] = __uint_as_float(f2tf(v));
            }
        }
    }
}

// ---------------------------------------------------------------------------
// Projection GEMM: g_ao[4096,1024]h @ Wp^T + bias -> out (float)
// ---------------------------------------------------------------------------
__global__ __launch_bounds__(256, 2) void proj_gemm(const float* __restrict__ bias,
                                                    float* __restrict__ out)
{
    extern __shared__ __half shq[];
    float acc[4][4][4];
#pragma unroll
    for (int mi = 0; mi < 4; mi++)
#pragma unroll
        for (int nj = 0; nj < 4; nj++)
#pragma unroll
            for (int t = 0; t < 4; t++) acc[mi][nj][t] = 0.f;

    const int bm = blockIdx.y * 128;
    const int bn = blockIdx.x * 128;
    gemm128(g_ao, 1024, g_wp, 1024, bm, bn, shq, acc);

    const int lane = threadIdx.x & 31;
    const int wid  = threadIdx.x >> 5;
    const int g    = lane >> 2;
    const int tg   = lane & 3;
    const int wm   = (wid >> 2) * 64;
    const int wn   = (wid & 3) * 32;

#pragma unroll
    for (int mi = 0; mi < 4; mi++) {
#pragma unroll
        for (int nj = 0; nj < 4; nj++) {
#pragma unroll
            for (int t = 0; t < 4; t++) {
                const int m = bm + wm + mi * 16 + g + ((t >= 2) ? 8 : 0);
                const int n = bn + wn + nj * 8 + 2 * tg + (t & 1);
                out[(size_t)m * DD + n] = acc[mi][nj][t] + bias[n];
            }
        }
    }
}

// ---------------------------------------------------------------------------
// Flash-style attention: QK^T in fp16 (both passes), PV in tf32.
// ---------------------------------------------------------------------------
#define PS_LD 132
#define KH 72                 // K tile row stride (halves); KH/2=36 u32, conflict-free
#define KSZH (128*KH)
#define KV_LD 68
#define KVSZ (128*KV_LD)
#define ATT_SMEM_BYTES (128*PS_LD*4 + 2*KSZH*2 + 2*KVSZ*4)

__global__ __launch_bounds__(256) void attn_kernel(float* __restrict__ out_base)
{
    extern __shared__ float sm[];
    float*  Ps = sm;                                  // [128][PS_LD] float
    __half* Kh = (__half*)(sm + 128 * PS_LD);         // [2][128][KH] half
    float*  Vs = (float*)(Kh + 2 * KSZH);             // [2][128][KV_LD] float

    const int tid  = threadIdx.x;
    const int lane = tid & 31;
    const int wid  = tid >> 5;
    const int g    = lane >> 2;
    const int tg   = lane & 3;
    const int qw   = wid * 16;

    const int b  = blockIdx.z;
    const int h  = blockIdx.y;
    const int qt = blockIdx.x;
    const int q0 = qt * 128;

    const __half* Qbh = g_q + (size_t)((b * HH + h) * SS) * HD;
    const __half* Kbh = g_k + (size_t)((b * HH + h) * SS) * HD;
    const float*  Vbh = g_v + (size_t)((b * HH + h) * SS) * HD;

    const int vrow = tid >> 4, vc4 = tid & 15;    // V staging: +i*16 rows

    // prologue: async-load K0 (half) + V0 (float)
#pragma unroll
    for (int i = 0; i < 4; i++) {
        int c = tid + i * 256;                    // 1024 chunks of 16B (K)
        int row = c >> 3, cc = c & 7;
        cpa16(&Kh[row * KH + cc * 8], &Kbh[(size_t)row * HD + cc * 8]);
    }
#pragma unroll
    for (int i = 0; i < 8; i++)
        cpa16(&Vs[(vrow + i * 16) * KV_LD + vc4 * 4],
              &Vbh[(size_t)(vrow + i * 16) * HD + vc4 * 4]);
    cpa_commit();

    // Q fragments (fp16, 4 kc steps of k16)
    unsigned qa[4][4];
    {
        const unsigned* q0p = (const unsigned*)(Qbh + (size_t)(q0 + qw + g) * HD);
        const unsigned* q1p = (const unsigned*)(Qbh + (size_t)(q0 + qw + g + 8) * HD);
#pragma unroll
        for (int kc = 0; kc < 4; kc++) {
            qa[kc][0] = q0p[kc * 8 + tg    ];
            qa[kc][1] = q1p[kc * 8 + tg    ];
            qa[kc][2] = q0p[kc * 8 + 4 + tg];
            qa[kc][3] = q1p[kc * 8 + 4 + tg];
        }
    }

    float m0 = -1e30f, m1 = -1e30f, l0 = 0.f, l1 = 0.f;
    float o[8][4];
#pragma unroll
    for (int nf = 0; nf < 8; nf++)
#pragma unroll
        for (int t = 0; t < 4; t++) o[nf][t] = 0.f;

    const int nkt  = qt + 1;
    const int row0 = q0 + qw + g;
    const int row1 = row0 + 8;

    // ======================= Pass 1 ===================
    for (int kt = 0; kt < nkt; kt++) {
        cpa_wait0();
        __syncthreads();

        if (kt + 1 < nkt) {
            const int nb = (kt + 1) * 128;
            __half* Kn = Kh + ((kt + 1) & 1) * KSZH;
            float*  Vn = Vs + ((kt + 1) & 1) * KVSZ;
#pragma unroll
            for (int i = 0; i < 4; i++) {
                int c = tid + i * 256;
                int row = c >> 3, cc = c & 7;
                cpa16(&Kn[row * KH + cc * 8], &Kbh[(size_t)(nb + row) * HD + cc * 8]);
            }
#pragma unroll
            for (int i = 0; i < 8; i++)
                cpa16(&Vn[(vrow + i * 16) * KV_LD + vc4 * 4],
                      &Vbh[(size_t)(nb + vrow + i * 16) * HD + vc4 * 4]);
            cpa_commit();
        }

        const unsigned* K32 = (const unsigned*)(Kh + (kt & 1) * KSZH);
        const float* Vb = Vs + (kt & 1) * KVSZ;
        const int kbase = kt * 128;

        // S = Q K^T (fp16 mma)
        float s[16][4];
#pragma unroll
        for (int nf = 0; nf < 16; nf++)
#pragma unroll
            for (int t = 0; t < 4; t++) s[nf][t] = 0.f;
#pragma unroll
        for (int kc = 0; kc < 4; kc++) {
#pragma unroll
            for (int nf = 0; nf < 16; nf++) {
                const unsigned b0 = K32[(nf * 8 + g) * (KH/2) + kc * 8 + tg    ];
                const unsigned b1 = K32[(nf * 8 + g) * (KH/2) + kc * 8 + tg + 4];
                mma16(s[nf], qa[kc][0], qa[kc][1], qa[kc][2], qa[kc][3], b0, b1);
            }
        }

        // scale + causal mask + tile row max
        const bool diag = (kt == qt);
        float mx0 = -1e30f, mx1 = -1e30f;
#pragma unroll
        for (int nf = 0; nf < 16; nf++) {
            const int col = kbase + nf * 8 + 2 * tg;
            float v0 = s[nf][0] * 0.125f;
            float v1 = s[nf][1] * 0.125f;
            float v2 = s[nf][2] * 0.125f;
            float v3 = s[nf][3] * 0.125f;
            if (diag) {
                if (col     > row0) v0 = -1e30f;
                if (col + 1 > row0) v1 = -1e30f;
                if (col     > row1) v2 = -1e30f;
                if (col + 1 > row1) v3 = -1e30f;
            }
            s[nf][0] = v0; s[nf][1] = v1; s[nf][2] = v2; s[nf][3] = v3;
            mx0 = fmaxf(mx0, fmaxf(v0, v1));
            mx1 = fmaxf(mx1, fmaxf(v2, v3));
        }
        mx0 = fmaxf(mx0, __shfl_xor_sync(0xffffffffu, mx0, 1));
        mx0 = fmaxf(mx0, __shfl_xor_sync(0xffffffffu, mx0, 2));
        mx1 = fmaxf(mx1, __shfl_xor_sync(0xffffffffu, mx1, 1));
        mx1 = fmaxf(mx1, __shfl_xor_sync(0xffffffffu, mx1, 2));

        const float mn0 = fmaxf(m0, mx0);
        const float mn1 = fmaxf(m1, mx1);
        const float al0 = __expf(m0 - mn0);
        const float al1 = __expf(m1 - mn1);

        float rs0 = 0.f, rs1 = 0.f;
#pragma unroll
        for (int nf = 0; nf < 16; nf++) {
            const float p0 = __expf(s[nf][0] - mn0);
            const float p1 = __expf(s[nf][1] - mn0);
            const float p2 = __expf(s[nf][2] - mn1);
            const float p3 = __expf(s[nf][3] - mn1);
            rs0 += p0 + p1;
            rs1 += p2 + p3;
            float2 t0, t1;
            t0.x = __uint_as_float(f2tf(p0)); t0.y = __uint_as_float(f2tf(p1));
            t1.x = __uint_as_float(f2tf(p2)); t1.y = __uint_as_float(f2tf(p3));
            *(float2*)&Ps[(qw + g    ) * PS_LD + nf * 8 + 2 * tg] = t0;
            *(float2*)&Ps[(qw + g + 8) * PS_LD + nf * 8 + 2 * tg] = t1;
        }
        rs0 += __shfl_xor_sync(0xffffffffu, rs0, 1);
        rs0 += __shfl_xor_sync(0xffffffffu, rs0, 2);
        rs1 += __shfl_xor_sync(0xffffffffu, rs1, 1);
        rs1 += __shfl_xor_sync(0xffffffffu, rs1, 2);

        m0 = mn0; m1 = mn1;
        l0 = l0 * al0 + rs0;
        l1 = l1 * al1 + rs1;
#pragma unroll
        for (int nf = 0; nf < 8; nf++) {
            o[nf][0] *= al0; o[nf][1] *= al0;
            o[nf][2] *= al1; o[nf][3] *= al1;
        }

        // O += P V (tf32; Ps rows warp-private)
#pragma unroll
        for (int kc = 0; kc < 16; kc++) {
            const int k = kc * 8;
            const unsigned a0 = __float_as_uint(Ps[(qw + g    ) * PS_LD + k + tg    ]);
            const unsigned a1 = __float_as_uint(Ps[(qw + g + 8) * PS_LD + k + tg    ]);
            const unsigned a2 = __float_as_uint(Ps[(qw + g    ) * PS_LD + k + tg + 4]);
            const unsigned a3 = __float_as_uint(Ps[(qw + g + 8) * PS_LD + k + tg + 4]);
#pragma unroll
            for (int nf = 0; nf < 8; nf++) {
                const unsigned b0 = __float_as_uint(Vb[(k + tg    ) * KV_LD + nf * 8 + g]);
                const unsigned b1 = __float_as_uint(Vb[(k + tg + 4) * KV_LD + nf * 8 + g]);
                mma8(o[nf], a0, a1, a2, a3, b0, b1);
            }
        }
    }

    // Write O / l (fp16 for proj)
    const float il0 = 1.0f / l0;
    const float il1 = 1.0f / l1;
    {
        const int orow = b * SS + q0 + qw + g;
#pragma unroll
        for (int nf = 0; nf < 8; nf++) {
            const int col = h * HD + nf * 8 + 2 * tg;
            __half2* d0 = (__half2*)&g_ao[(size_t)orow * DD + col];
            __half2* d1 = (__half2*)&g_ao[(size_t)(orow + 8) * DD + col];
            *d0 = __floats2half2_rn(o[nf][0] * il0, o[nf][1] * il0);
            *d1 = __floats2half2_rn(o[nf][2] * il1, o[nf][3] * il1);
        }
    }
    __syncthreads();   // all reads of Kh/Vs done before pass-2 overwrites

    // =============== Pass 2: recompute scores, write weights direct ========
    float* attn = out_base + (size_t)MM * DD;
    const size_t abase = (size_t)(b * HH + h) * SS + q0;
    float* w0p = attn + (abase + qw + g) * SS;
    float* w1p = attn + (abase + qw + g + 8) * SS;

#pragma unroll
    for (int i = 0; i < 4; i++) {
        int c = tid + i * 256;
        int row = c >> 3, cc = c & 7;
        cpa16(&Kh[row * KH + cc * 8], &Kbh[(size_t)row * HD + cc * 8]);
    }
    cpa_commit();

    for (int kt = 0; kt < nkt; kt++) {
        cpa_wait0();
        __syncthreads();

        if (kt + 1 < nkt) {
            const int nb = (kt + 1) * 128;
            __half* Kn = Kh + ((kt + 1) & 1) * KSZH;
#pragma unroll
            for (int i = 0; i < 4; i++) {
                int c = tid + i * 256;
                int row = c >> 3, cc = c & 7;
                cpa16(&Kn[row * KH + cc * 8], &Kbh[(size_t)(nb + row) * HD + cc * 8]);
            }
            cpa_commit();
        }

        const unsigned* K32 = (const unsigned*)(Kh + (kt & 1) * KSZH);
        const int kbase = kt * 128;

        float s[16][4];
#pragma unroll
        for (int nf = 0; nf < 16; nf++)
#pragma unroll
            for (int t = 0; t < 4; t++) s[nf][t] = 0.f;
#pragma unroll
        for (int kc = 0; kc < 4; kc++) {
#pragma unroll
            for (int nf = 0; nf < 16; nf++) {
                const unsigned b0 = K32[(nf * 8 + g) * (KH/2) + kc * 8 + tg    ];
                const unsigned b1 = K32[(nf * 8 + g) * (KH/2) + kc * 8 + tg + 4];
                mma16(s[nf], qa[kc][0], qa[kc][1], qa[kc][2], qa[kc][3], b0, b1);
            }
        }

        const bool diag = (kt == qt);
#pragma unroll
        for (int nf = 0; nf < 16; nf++) {
            const int col = kbase + nf * 8 + 2 * tg;
            float w0 = __expf(s[nf][0] * 0.125f - m0) * il0;
            float w1 = __expf(s[nf][1] * 0.125f - m0) * il0;
            float w2 = __expf(s[nf][2] * 0.125f - m1) * il1;
            float w3 = __expf(s[nf][3] * 0.125f - m1) * il1;
            if (diag) {
                if (col     > row0) w0 = 0.f;
                if (col + 1 > row0) w1 = 0.f;
                if (col     > row1) w2 = 0.f;
                if (col + 1 > row1) w3 = 0.f;
            }
            float2 t0, t1;
            t0.x = w0; t0.y = w1;
            t1.x = w2; t1.y = w3;
            *(float2*)&w0p[col] = t0;
            *(float2*)&w1p[col] = t1;
        }
    }

    // zero-fill strictly-upper region
    const int kl = nkt * 128;
    if (kl < SS) {
        const float4 z = make_float4(0.f, 0.f, 0.f, 0.f);
        const int w4 = (SS - kl) >> 2;
        for (int row = 0; row < 128; row++) {
            float4* dst = (float4*)&attn[(abase + row) * SS + kl];
            for (int c = tid; c < w4; c += 256) dst[c] = z;
        }
    }
}

// ---------------------------------------------------------------------------
extern "C" void kernel_launch(void* const* d_in, const int* in_sizes, int n_in,
                              void* d_out, int out_size)
{
    const float* x      = (const float*)d_in[0];
    const float* W_attn = (const float*)d_in[1];
    const float* b_attn = (const float*)d_in[2];
    const float* W_proj = (const float*)d_in[3];
    const float* b_proj = (const float*)d_in[4];
    float* out = (float*)d_out;

    cudaFuncSetAttribute(qkv_gemm,
                         cudaFuncAttributeMaxDynamicSharedMemorySize, GEMM_SMEM_BYTES);
    cudaFuncSetAttribute(proj_gemm,
                         cudaFuncAttributeMaxDynamicSharedMemorySize, GEMM_SMEM_BYTES);
    cudaFuncSetAttribute(attn_kernel,
                         cudaFuncAttributeMaxDynamicSharedMemorySize, ATT_SMEM_BYTES);

    cvt_x<<<1024, 256>>>(x);
    transpose_wa<<<dim3(96, 32), 256>>>(W_attn);
    transpose_wp<<<dim3(32, 32), 256>>>(W_proj);
    qkv_gemm<<<dim3(24, 32), 256, GEMM_SMEM_BYTES>>>(b_attn);
    attn_kernel<<<dim3(SS / 128, HH, BB), 256, ATT_SMEM_BYTES>>>(out);
    proj_gemm<<<dim3(8, 32), 256, GEMM_SMEM_BYTES>>>(b_proj, out);
}

// round 9
// speedup vs baseline: 8.8849x; 1.2179x over previous
#include <cuda_runtime.h>
#include <cuda_fp16.h>
#include <math.h>

#define BB 2
#define HH 16
#define SS 2048
#define DD 1024
#define HD 64
#define MM (BB*SS)          // 4096 rows

// Scratch (device globals)
__device__ __half g_q[BB*HH*SS*HD];   // [B,H,S,hd] fp16
__device__ __half g_k[BB*HH*SS*HD];   // [B,H,S,hd] fp16
__device__ __half g_v[BB*HH*HD*SS];   // [B,H,hd,S] fp16 (TRANSPOSED)
__device__ __half g_ao[MM*DD];        // attention output fp16
__device__ __half g_x[MM*DD];         // fp16 X
__device__ __half g_wa[3*DD*DD];      // W_attn^T  [n=3072][k=1024] fp16
__device__ __half g_wp[DD*DD];        // W_proj^T  [n=1024][k=1024] fp16

// ---------------------------------------------------------------------------
// helpers
// ---------------------------------------------------------------------------
__device__ __forceinline__ void mma16(float* c,
                                      unsigned a0, unsigned a1, unsigned a2, unsigned a3,
                                      unsigned b0, unsigned b1) {
    asm volatile(
        "mma.sync.aligned.m16n8k16.row.col.f32.f16.f16.f32 "
        "{%0,%1,%2,%3},{%4,%5,%6,%7},{%8,%9},{%0,%1,%2,%3};"
        : "+f"(c[0]), "+f"(c[1]), "+f"(c[2]), "+f"(c[3])
        : "r"(a0), "r"(a1), "r"(a2), "r"(a3), "r"(b0), "r"(b1));
}
__device__ __forceinline__ void cpa16(const void* smem_dst, const void* gsrc) {
    unsigned s = (unsigned)__cvta_generic_to_shared(smem_dst);
    asm volatile("cp.async.cg.shared.global [%0], [%1], 16;" :: "r"(s), "l"(gsrc));
}
__device__ __forceinline__ void cpa_commit() {
    asm volatile("cp.async.commit_group;");
}
__device__ __forceinline__ void cpa_wait0() {
    asm volatile("cp.async.wait_group 0;");
}
__device__ __forceinline__ void cpa_wait1() {
    asm volatile("cp.async.wait_group 1;");
}

// ---------------------------------------------------------------------------
// Converters
// ---------------------------------------------------------------------------
__global__ __launch_bounds__(256) void cvt_x(const float* __restrict__ X)
{
    const int stride = gridDim.x * blockDim.x;
    for (int k = blockIdx.x * blockDim.x + threadIdx.x; k < MM * DD / 4; k += stride) {
        float4 v = ((const float4*)X)[k];
        ((__half2*)g_x)[k * 2    ] = __floats2half2_rn(v.x, v.y);
        ((__half2*)g_x)[k * 2 + 1] = __floats2half2_rn(v.z, v.w);
    }
}

// W [1024][N] float -> Wt [N][1024] half (tiled transpose)
__global__ __launch_bounds__(256) void transpose_wa(const float* __restrict__ W)
{
    __shared__ float ts[32][33];
    const int tx = threadIdx.x & 31, ty = threadIdx.x >> 5;
    const int nb = blockIdx.x * 32, kb = blockIdx.y * 32;
#pragma unroll
    for (int i = 0; i < 4; i++)
        ts[ty + i * 8][tx] = W[(size_t)(kb + ty + i * 8) * 3072 + nb + tx];
    __syncthreads();
#pragma unroll
    for (int i = 0; i < 4; i++)
        g_wa[(size_t)(nb + ty + i * 8) * 1024 + kb + tx] = __float2half_rn(ts[tx][ty + i * 8]);
}
__global__ __launch_bounds__(256) void transpose_wp(const float* __restrict__ W)
{
    __shared__ float ts[32][33];
    const int tx = threadIdx.x & 31, ty = threadIdx.x >> 5;
    const int nb = blockIdx.x * 32, kb = blockIdx.y * 32;
#pragma unroll
    for (int i = 0; i < 4; i++)
        ts[ty + i * 8][tx] = W[(size_t)(kb + ty + i * 8) * 1024 + nb + tx];
    __syncthreads();
#pragma unroll
    for (int i = 0; i < 4; i++)
        g_wp[(size_t)(nb + ty + i * 8) * 1024 + kb + tx] = __float2half_rn(ts[tx][ty + i * 8]);
}

// ---------------------------------------------------------------------------
// fp16 GEMM core: C[128x128] tile, A [m][k] half, B [n][k] half, 3-stage cp.async
// ---------------------------------------------------------------------------
#define TH 40                 // halves per tile row
#define TH32 20
#define TSZ (128*TH)
#define GEMM_SMEM_BYTES (3 * 2 * TSZ * 2)

__device__ __forceinline__ void gemm128(const __half* __restrict__ Asrc, size_t a_stride,
                                        const __half* __restrict__ Bsrc, size_t b_stride,
                                        int bm, int bn, __half* sh, float acc[4][4][4])
{
    __half* Ah = sh;
    __half* Bh = sh + 3 * TSZ;

    const int tid  = threadIdx.x;
    const int NK = 32;

    auto stage = [&](int t) {
        const int k0 = t * 32;
        __half* An = Ah + (t % 3) * TSZ;
        __half* Bn = Bh + (t % 3) * TSZ;
#pragma unroll
        for (int i = 0; i < 2; i++) {
            int c = tid + i * 256;
            int row = c >> 2, cc = c & 3;
            cpa16(&An[row * TH + cc * 8], &Asrc[(size_t)(bm + row) * a_stride + k0 + cc * 8]);
            cpa16(&Bn[row * TH + cc * 8], &Bsrc[(size_t)(bn + row) * b_stride + k0 + cc * 8]);
        }
    };

    stage(0); cpa_commit();
    stage(1); cpa_commit();

    const int lane = tid & 31;
    const int wid  = tid >> 5;
    const int g    = lane >> 2;
    const int tg   = lane & 3;
    const int wm   = (wid >> 2) * 64;
    const int wn   = (wid & 3) * 32;

    for (int kt = 0; kt < NK; kt++) {
        cpa_wait1();
        __syncthreads();
        if (kt + 2 < NK) stage(kt + 2);
        cpa_commit();

        const unsigned* A32 = (const unsigned*)(Ah + (kt % 3) * TSZ);
        const unsigned* B32 = (const unsigned*)(Bh + (kt % 3) * TSZ);
#pragma unroll
        for (int kc = 0; kc < 2; kc++) {
            const int kb = kc * 8;
            unsigned af[4][4], bf[4][2];
#pragma unroll
            for (int mi = 0; mi < 4; mi++) {
                const int rb = wm + mi * 16;
                af[mi][0] = A32[(rb + g    ) * TH32 + kb + tg    ];
                af[mi][1] = A32[(rb + g + 8) * TH32 + kb + tg    ];
                af[mi][2] = A32[(rb + g    ) * TH32 + kb + tg + 4];
                af[mi][3] = A32[(rb + g + 8) * TH32 + kb + tg + 4];
            }
#pragma unroll
            for (int nj = 0; nj < 4; nj++) {
                const int cb = wn + nj * 8;
                bf[nj][0] = B32[(cb + g) * TH32 + kb + tg    ];
                bf[nj][1] = B32[(cb + g) * TH32 + kb + tg + 4];
            }
#pragma unroll
            for (int mi = 0; mi < 4; mi++)
#pragma unroll
                for (int nj = 0; nj < 4; nj++)
                    mma16(acc[mi][nj], af[mi][0], af[mi][1], af[mi][2], af[mi][3],
                          bf[nj][0], bf[nj][1]);
        }
    }
}

// ---------------------------------------------------------------------------
// QKV GEMM: X[4096,1024]h @ Wa^T -> q/k (half, [s][d]); v (half, TRANSPOSED [d][s])
// ---------------------------------------------------------------------------
__global__ __launch_bounds__(256, 2) void qkv_gemm(const float* __restrict__ bias)
{
    extern __shared__ __half shq[];
    float acc[4][4][4];
#pragma unroll
    for (int mi = 0; mi < 4; mi++)
#pragma unroll
        for (int nj = 0; nj < 4; nj++)
#pragma unroll
            for (int t = 0; t < 4; t++) acc[mi][nj][t] = 0.f;

    const int bm = blockIdx.y * 128;
    const int bn = blockIdx.x * 128;
    gemm128(g_x, 1024, g_wa, 1024, bm, bn, shq, acc);

    const int lane = threadIdx.x & 31;
    const int wid  = threadIdx.x >> 5;
    const int g    = lane >> 2;
    const int tg   = lane & 3;
    const int wm   = (wid >> 2) * 64;
    const int wn   = (wid & 3) * 32;

#pragma unroll
    for (int mi = 0; mi < 4; mi++) {
#pragma unroll
        for (int nj = 0; nj < 4; nj++) {
#pragma unroll
            for (int t = 0; t < 4; t++) {
                const int m = bm + wm + mi * 16 + g + ((t >= 2) ? 8 : 0);
                const int n = bn + wn + nj * 8 + 2 * tg + (t & 1);
                const float v = acc[mi][nj][t] + bias[n];
                const int bidx = m >> 11;
                const int s = m & 2047;
                const int which = n >> 10;
                const int jj = n & 1023;
                const int h = jj >> 6;
                const int d = jj & 63;
                if (which == 0)
                    g_q[(size_t)((bidx * HH + h) * SS + s) * HD + d] = __float2half_rn(v);
                else if (which == 1)
                    g_k[(size_t)((bidx * HH + h) * SS + s) * HD + d] = __float2half_rn(v);
                else
                    g_v[(size_t)((bidx * HH + h) * HD + d) * SS + s] = __float2half_rn(v);
            }
        }
    }
}

// ---------------------------------------------------------------------------
// Projection GEMM
// ---------------------------------------------------------------------------
__global__ __launch_bounds__(256, 2) void proj_gemm(const float* __restrict__ bias,
                                                    float* __restrict__ out)
{
    extern __shared__ __half shq[];
    float acc[4][4][4];
#pragma unroll
    for (int mi = 0; mi < 4; mi++)
#pragma unroll
        for (int nj = 0; nj < 4; nj++)
#pragma unroll
            for (int t = 0; t < 4; t++) acc[mi][nj][t] = 0.f;

    const int bm = blockIdx.y * 128;
    const int bn = blockIdx.x * 128;
    gemm128(g_ao, 1024, g_wp, 1024, bm, bn, shq, acc);

    const int lane = threadIdx.x & 31;
    const int wid  = threadIdx.x >> 5;
    const int g    = lane >> 2;
    const int tg   = lane & 3;
    const int wm   = (wid >> 2) * 64;
    const int wn   = (wid & 3) * 32;

#pragma unroll
    for (int mi = 0; mi < 4; mi++) {
#pragma unroll
        for (int nj = 0; nj < 4; nj++) {
#pragma unroll
            for (int t = 0; t < 4; t++) {
                const int m = bm + wm + mi * 16 + g + ((t >= 2) ? 8 : 0);
                const int n = bn + wn + nj * 8 + 2 * tg + (t & 1);
                out[(size_t)m * DD + n] = acc[mi][nj][t] + bias[n];
            }
        }
    }
}

// ---------------------------------------------------------------------------
// Flash-style attention, all-fp16 mma: QK^T and PV both m16n8k16.
// P staged as half in Ps; V^T tiles [64][136]h staged from transposed g_v.
// smem = 34816 (Ps) + 36864 (K x2) + 34816 (VT x2) = 106496 B -> 2 CTAs/SM
// ---------------------------------------------------------------------------
#define PS_H 136               // Ps row stride (halves); 68 u32, conflict-free
#define PSSZ (128*PS_H)
#define KH 72                  // K tile row stride (halves)
#define KSZH (128*KH)
#define VT_H 136               // V^T tile row stride (halves)
#define VTSZ (64*VT_H)
#define ATT_SMEM_BYTES ((PSSZ + 2*KSZH + 2*VTSZ) * 2)

__global__ __launch_bounds__(256, 2) void attn_kernel(float* __restrict__ out_base)
{
    extern __shared__ __half smh[];
    __half* Ps = smh;                     // [128][PS_H]
    __half* Kh = smh + PSSZ;              // [2][128][KH]
    __half* VT = Kh + 2 * KSZH;           // [2][64][VT_H]

    const int tid  = threadIdx.x;
    const int lane = tid & 31;
    const int wid  = tid >> 5;
    const int g    = lane >> 2;
    const int tg   = lane & 3;
    const int qw   = wid * 16;

    const int b  = blockIdx.z;
    const int h  = blockIdx.y;
    const int qt = blockIdx.x;
    const int q0 = qt * 128;

    const __half* Qbh = g_q + (size_t)((b * HH + h) * SS) * HD;
    const __half* Kbh = g_k + (size_t)((b * HH + h) * SS) * HD;
    const __half* Vbt = g_v + (size_t)((b * HH + h) * HD) * SS;   // [d][s]

    // prologue: async-load K0 + VT0
#pragma unroll
    for (int i = 0; i < 4; i++) {
        int c = tid + i * 256;                    // 1024 chunks (K)
        int row = c >> 3, cc = c & 7;
        cpa16(&Kh[row * KH + cc * 8], &Kbh[(size_t)row * HD + cc * 8]);
    }
#pragma unroll
    for (int i = 0; i < 4; i++) {
        int c = tid + i * 256;                    // 1024 chunks (VT: 64 rows x 16)
        int row = c >> 4, cc = c & 15;
        cpa16(&VT[row * VT_H + cc * 8], &Vbt[(size_t)row * SS + cc * 8]);
    }
    cpa_commit();

    // Q fragments (fp16, 4 kc steps of k16)
    unsigned qa[4][4];
    {
        const unsigned* q0p = (const unsigned*)(Qbh + (size_t)(q0 + qw + g) * HD);
        const unsigned* q1p = (const unsigned*)(Qbh + (size_t)(q0 + qw + g + 8) * HD);
#pragma unroll
        for (int kc = 0; kc < 4; kc++) {
            qa[kc][0] = q0p[kc * 8 + tg    ];
            qa[kc][1] = q1p[kc * 8 + tg    ];
            qa[kc][2] = q0p[kc * 8 + 4 + tg];
            qa[kc][3] = q1p[kc * 8 + 4 + tg];
        }
    }

    float m0 = -1e30f, m1 = -1e30f, l0 = 0.f, l1 = 0.f;
    float o[8][4];
#pragma unroll
    for (int nf = 0; nf < 8; nf++)
#pragma unroll
        for (int t = 0; t < 4; t++) o[nf][t] = 0.f;

    const int nkt  = qt + 1;
    const int row0 = q0 + qw + g;
    const int row1 = row0 + 8;

    // ======================= Pass 1 ===================
    for (int kt = 0; kt < nkt; kt++) {
        cpa_wait0();
        __syncthreads();

        if (kt + 1 < nkt) {
            const int nb = (kt + 1) * 128;
            __half* Kn = Kh + ((kt + 1) & 1) * KSZH;
            __half* Vn = VT + ((kt + 1) & 1) * VTSZ;
#pragma unroll
            for (int i = 0; i < 4; i++) {
                int c = tid + i * 256;
                int row = c >> 3, cc = c & 7;
                cpa16(&Kn[row * KH + cc * 8], &Kbh[(size_t)(nb + row) * HD + cc * 8]);
            }
#pragma unroll
            for (int i = 0; i < 4; i++) {
                int c = tid + i * 256;
                int row = c >> 4, cc = c & 15;
                cpa16(&Vn[row * VT_H + cc * 8], &Vbt[(size_t)row * SS + nb + cc * 8]);
            }
            cpa_commit();
        }

        const unsigned* K32 = (const unsigned*)(Kh + (kt & 1) * KSZH);
        const int kbase = kt * 128;

        // S = Q K^T (fp16 mma)
        float s[16][4];
#pragma unroll
        for (int nf = 0; nf < 16; nf++)
#pragma unroll
            for (int t = 0; t < 4; t++) s[nf][t] = 0.f;
#pragma unroll
        for (int kc = 0; kc < 4; kc++) {
#pragma unroll
            for (int nf = 0; nf < 16; nf++) {
                const unsigned b0 = K32[(nf * 8 + g) * (KH/2) + kc * 8 + tg    ];
                const unsigned b1 = K32[(nf * 8 + g) * (KH/2) + kc * 8 + tg + 4];
                mma16(s[nf], qa[kc][0], qa[kc][1], qa[kc][2], qa[kc][3], b0, b1);
            }
        }

        // scale + causal mask + tile row max
        const bool diag = (kt == qt);
        float mx0 = -1e30f, mx1 = -1e30f;
#pragma unroll
        for (int nf = 0; nf < 16; nf++) {
            const int col = kbase + nf * 8 + 2 * tg;
            float v0 = s[nf][0] * 0.125f;
            float v1 = s[nf][1] * 0.125f;
            float v2 = s[nf][2] * 0.125f;
            float v3 = s[nf][3] * 0.125f;
            if (diag) {
                if (col     > row0) v0 = -1e30f;
                if (col + 1 > row0) v1 = -1e30f;
                if (col     > row1) v2 = -1e30f;
                if (col + 1 > row1) v3 = -1e30f;
            }
            s[nf][0] = v0; s[nf][1] = v1; s[nf][2] = v2; s[nf][3] = v3;
            mx0 = fmaxf(mx0, fmaxf(v0, v1));
            mx1 = fmaxf(mx1, fmaxf(v2, v3));
        }
        mx0 = fmaxf(mx0, __shfl_xor_sync(0xffffffffu, mx0, 1));
        mx0 = fmaxf(mx0, __shfl_xor_sync(0xffffffffu, mx0, 2));
        mx1 = fmaxf(mx1, __shfl_xor_sync(0xffffffffu, mx1, 1));
        mx1 = fmaxf(mx1, __shfl_xor_sync(0xffffffffu, mx1, 2));

        const float mn0 = fmaxf(m0, mx0);
        const float mn1 = fmaxf(m1, mx1);
        const float al0 = __expf(m0 - mn0);
        const float al1 = __expf(m1 - mn1);

        float rs0 = 0.f, rs1 = 0.f;
        __half2* Pp = (__half2*)Ps;
#pragma unroll
        for (int nf = 0; nf < 16; nf++) {
            const float p0 = __expf(s[nf][0] - mn0);
            const float p1 = __expf(s[nf][1] - mn0);
            const float p2 = __expf(s[nf][2] - mn1);
            const float p3 = __expf(s[nf][3] - mn1);
            rs0 += p0 + p1;
            rs1 += p2 + p3;
            Pp[(qw + g    ) * (PS_H/2) + nf * 4 + tg] = __floats2half2_rn(p0, p1);
            Pp[(qw + g + 8) * (PS_H/2) + nf * 4 + tg] = __floats2half2_rn(p2, p3);
        }
        rs0 += __shfl_xor_sync(0xffffffffu, rs0, 1);
        rs0 += __shfl_xor_sync(0xffffffffu, rs0, 2);
        rs1 += __shfl_xor_sync(0xffffffffu, rs1, 1);
        rs1 += __shfl_xor_sync(0xffffffffu, rs1, 2);

        m0 = mn0; m1 = mn1;
        l0 = l0 * al0 + rs0;
        l1 = l1 * al1 + rs1;
#pragma unroll
        for (int nf = 0; nf < 8; nf++) {
            o[nf][0] *= al0; o[nf][1] *= al0;
            o[nf][2] *= al1; o[nf][3] *= al1;
        }

        // O += P V (fp16 mma; Ps rows warp-private, VT from smem)
        const unsigned* P32  = (const unsigned*)Ps;
        const unsigned* VT32 = (const unsigned*)(VT + (kt & 1) * VTSZ);
#pragma unroll
        for (int kc = 0; kc < 8; kc++) {
            const unsigned a0 = P32[(qw + g    ) * (PS_H/2) + kc * 8 + tg    ];
            const unsigned a1 = P32[(qw + g + 8) * (PS_H/2) + kc * 8 + tg    ];
            const unsigned a2 = P32[(qw + g    ) * (PS_H/2) + kc * 8 + tg + 4];
            const unsigned a3 = P32[(qw + g + 8) * (PS_H/2) + kc * 8 + tg + 4];
#pragma unroll
            for (int nf = 0; nf < 8; nf++) {
                const unsigned b0 = VT32[(nf * 8 + g) * (VT_H/2) + kc * 8 + tg    ];
                const unsigned b1 = VT32[(nf * 8 + g) * (VT_H/2) + kc * 8 + tg + 4];
                mma16(o[nf], a0, a1, a2, a3, b0, b1);
            }
        }
    }

    // Write O / l (fp16 for proj)
    const float il0 = 1.0f / l0;
    const float il1 = 1.0f / l1;
    {
        const int orow = b * SS + q0 + qw + g;
#pragma unroll
        for (int nf = 0; nf < 8; nf++) {
            const int col = h * HD + nf * 8 + 2 * tg;
            __half2* d0 = (__half2*)&g_ao[(size_t)orow * DD + col];
            __half2* d1 = (__half2*)&g_ao[(size_t)(orow + 8) * DD + col];
            *d0 = __floats2half2_rn(o[nf][0] * il0, o[nf][1] * il0);
            *d1 = __floats2half2_rn(o[nf][2] * il1, o[nf][3] * il1);
        }
    }
    __syncthreads();   // all reads of Kh/VT done before pass-2 overwrites

    // =============== Pass 2: recompute scores, write weights direct ========
    float* attn = out_base + (size_t)MM * DD;
    const size_t abase = (size_t)(b * HH + h) * SS + q0;
    float* w0p = attn + (abase + qw + g) * SS;
    float* w1p = attn + (abase + qw + g + 8) * SS;

#pragma unroll
    for (int i = 0; i < 4; i++) {
        int c = tid + i * 256;
        int row = c >> 3, cc = c & 7;
        cpa16(&Kh[row * KH + cc * 8], &Kbh[(size_t)row * HD + cc * 8]);
    }
    cpa_commit();

    for (int kt = 0; kt < nkt; kt++) {
        cpa_wait0();
        __syncthreads();

        if (kt + 1 < nkt) {
            const int nb = (kt + 1) * 128;
            __half* Kn = Kh + ((kt + 1) & 1) * KSZH;
#pragma unroll
            for (int i = 0; i < 4; i++) {
                int c = tid + i * 256;
                int row = c >> 3, cc = c & 7;
                cpa16(&Kn[row * KH + cc * 8], &Kbh[(size_t)(nb + row) * HD + cc * 8]);
            }
            cpa_commit();
        }

        const unsigned* K32 = (const unsigned*)(Kh + (kt & 1) * KSZH);
        const int kbase = kt * 128;

        float s[16][4];
#pragma unroll
        for (int nf = 0; nf < 16; nf++)
#pragma unroll
            for (int t = 0; t < 4; t++) s[nf][t] = 0.f;
#pragma unroll
        for (int kc = 0; kc < 4; kc++) {
#pragma unroll
            for (int nf = 0; nf < 16; nf++) {
                const unsigned b0 = K32[(nf * 8 + g) * (KH/2) + kc * 8 + tg    ];
                const unsigned b1 = K32[(nf * 8 + g) * (KH/2) + kc * 8 + tg + 4];
                mma16(s[nf], qa[kc][0], qa[kc][1], qa[kc][2], qa[kc][3], b0, b1);
            }
        }

        const bool diag = (kt == qt);
#pragma unroll
        for (int nf = 0; nf < 16; nf++) {
            const int col = kbase + nf * 8 + 2 * tg;
            float w0 = __expf(s[nf][0] * 0.125f - m0) * il0;
            float w1 = __expf(s[nf][1] * 0.125f - m0) * il0;
            float w2 = __expf(s[nf][2] * 0.125f - m1) * il1;
            float w3 = __expf(s[nf][3] * 0.125f - m1) * il1;
            if (diag) {
                if (col     > row0) w0 = 0.f;
                if (col + 1 > row0) w1 = 0.f;
                if (col     > row1) w2 = 0.f;
                if (col + 1 > row1) w3 = 0.f;
            }
            float2 t0, t1;
            t0.x = w0; t0.y = w1;
            t1.x = w2; t1.y = w3;
            *(float2*)&w0p[col] = t0;
            *(float2*)&w1p[col] = t1;
        }
    }

    // zero-fill strictly-upper region
    const int kl = nkt * 128;
    if (kl < SS) {
        const float4 z = make_float4(0.f, 0.f, 0.f, 0.f);
        const int w4 = (SS - kl) >> 2;
        for (int row = 0; row < 128; row++) {
            float4* dst = (float4*)&attn[(abase + row) * SS + kl];
            for (int c = tid; c < w4; c += 256) dst[c] = z;
        }
    }
}

// ---------------------------------------------------------------------------
extern "C" void kernel_launch(void* const* d_in, const int* in_sizes, int n_in,
                              void* d_out, int out_size)
{
    const float* x      = (const float*)d_in[0];
    const float* W_attn = (const float*)d_in[1];
    const float* b_attn = (const float*)d_in[2];
    const float* W_proj = (const float*)d_in[3];
    const float* b_proj = (const float*)d_in[4];
    float* out = (float*)d_out;

    cudaFuncSetAttribute(qkv_gemm,
                         cudaFuncAttributeMaxDynamicSharedMemorySize, GEMM_SMEM_BYTES);
    cudaFuncSetAttribute(proj_gemm,
                         cudaFuncAttributeMaxDynamicSharedMemorySize, GEMM_SMEM_BYTES);
    cudaFuncSetAttribute(attn_kernel,
                         cudaFuncAttributeMaxDynamicSharedMemorySize, ATT_SMEM_BYTES);

    cvt_x<<<1024, 256>>>(x);
    transpose_wa<<<dim3(96, 32), 256>>>(W_attn);
    transpose_wp<<<dim3(32, 32), 256>>>(W_proj);
    qkv_gemm<<<dim3(24, 32), 256, GEMM_SMEM_BYTES>>>(b_attn);
    attn_kernel<<<dim3(SS / 128, HH, BB), 256, ATT_SMEM_BYTES>>>(out);
    proj_gemm<<<dim3(8, 32), 256, GEMM_SMEM_BYTES>>>(b_proj, out);
}

// round 10
// speedup vs baseline: 9.4808x; 1.0671x over previous
#include <cuda_runtime.h>
#include <cuda_fp16.h>
#include <math.h>

#define BB 2
#define HH 16
#define SS 2048
#define DD 1024
#define HD 64
#define MM (BB*SS)          // 4096 rows

// Scratch (device globals)
__device__ __half g_q[BB*HH*SS*HD];   // [B,H,S,hd] fp16
__device__ __half g_k[BB*HH*SS*HD];   // [B,H,S,hd] fp16
__device__ __half g_v[BB*HH*HD*SS];   // [B,H,hd,S] fp16 (TRANSPOSED)
__device__ __half g_ao[MM*DD];        // attention output fp16
__device__ __half g_x[MM*DD];         // fp16 X
__device__ __half g_wa[3*DD*DD];      // W_attn^T  [n=3072][k=1024] fp16
__device__ __half g_wp[DD*DD];        // W_proj^T  [n=1024][k=1024] fp16

// ---------------------------------------------------------------------------
// helpers
// ---------------------------------------------------------------------------
__device__ __forceinline__ void mma16(float* c,
                                      unsigned a0, unsigned a1, unsigned a2, unsigned a3,
                                      unsigned b0, unsigned b1) {
    asm volatile(
        "mma.sync.aligned.m16n8k16.row.col.f32.f16.f16.f32 "
        "{%0,%1,%2,%3},{%4,%5,%6,%7},{%8,%9},{%0,%1,%2,%3};"
        : "+f"(c[0]), "+f"(c[1]), "+f"(c[2]), "+f"(c[3])
        : "r"(a0), "r"(a1), "r"(a2), "r"(a3), "r"(b0), "r"(b1));
}
__device__ __forceinline__ void ldsm4(unsigned& r0, unsigned& r1, unsigned& r2, unsigned& r3,
                                      const void* p) {
    unsigned a = (unsigned)__cvta_generic_to_shared(p);
    asm volatile("ldmatrix.sync.aligned.m8n8.x4.shared.b16 {%0,%1,%2,%3}, [%4];"
                 : "=r"(r0), "=r"(r1), "=r"(r2), "=r"(r3) : "r"(a));
}
__device__ __forceinline__ void cpa16(const void* smem_dst, const void* gsrc) {
    unsigned s = (unsigned)__cvta_generic_to_shared(smem_dst);
    asm volatile("cp.async.cg.shared.global [%0], [%1], 16;" :: "r"(s), "l"(gsrc));
}
__device__ __forceinline__ void cpa_commit() {
    asm volatile("cp.async.commit_group;");
}
__device__ __forceinline__ void cpa_wait0() {
    asm volatile("cp.async.wait_group 0;");
}
__device__ __forceinline__ void cpa_wait1() {
    asm volatile("cp.async.wait_group 1;");
}

// ---------------------------------------------------------------------------
// Converters
// ---------------------------------------------------------------------------
__global__ __launch_bounds__(256) void cvt_x(const float* __restrict__ X)
{
    const int stride = gridDim.x * blockDim.x;
    for (int k = blockIdx.x * blockDim.x + threadIdx.x; k < MM * DD / 4; k += stride) {
        float4 v = ((const float4*)X)[k];
        ((__half2*)g_x)[k * 2    ] = __floats2half2_rn(v.x, v.y);
        ((__half2*)g_x)[k * 2 + 1] = __floats2half2_rn(v.z, v.w);
    }
}

// W [1024][N] float -> Wt [N][1024] half (tiled transpose)
__global__ __launch_bounds__(256) void transpose_wa(const float* __restrict__ W)
{
    __shared__ float ts[32][33];
    const int tx = threadIdx.x & 31, ty = threadIdx.x >> 5;
    const int nb = blockIdx.x * 32, kb = blockIdx.y * 32;
#pragma unroll
    for (int i = 0; i < 4; i++)
        ts[ty + i * 8][tx] = W[(size_t)(kb + ty + i * 8) * 3072 + nb + tx];
    __syncthreads();
#pragma unroll
    for (int i = 0; i < 4; i++)
        g_wa[(size_t)(nb + ty + i * 8) * 1024 + kb + tx] = __float2half_rn(ts[tx][ty + i * 8]);
}
__global__ __launch_bounds__(256) void transpose_wp(const float* __restrict__ W)
{
    __shared__ float ts[32][33];
    const int tx = threadIdx.x & 31, ty = threadIdx.x >> 5;
    const int nb = blockIdx.x * 32, kb = blockIdx.y * 32;
#pragma unroll
    for (int i = 0; i < 4; i++)
        ts[ty + i * 8][tx] = W[(size_t)(kb + ty + i * 8) * 1024 + nb + tx];
    __syncthreads();
#pragma unroll
    for (int i = 0; i < 4; i++)
        g_wp[(size_t)(nb + ty + i * 8) * 1024 + kb + tx] = __float2half_rn(ts[tx][ty + i * 8]);
}

// ---------------------------------------------------------------------------
// fp16 GEMM core: C[128x128] tile, A [m][k] half, B [n][k] half, 3-stage cp.async
// Fragment loads via ldmatrix.x4.
// ---------------------------------------------------------------------------
#define TH 40                 // halves per tile row
#define TH32 20
#define TSZ (128*TH)
#define GEMM_SMEM_BYTES (3 * 2 * TSZ * 2)

__device__ __forceinline__ void gemm128(const __half* __restrict__ Asrc, size_t a_stride,
                                        const __half* __restrict__ Bsrc, size_t b_stride,
                                        int bm, int bn, __half* sh, float acc[4][4][4])
{
    __half* Ah = sh;
    __half* Bh = sh + 3 * TSZ;

    const int tid  = threadIdx.x;
    const int NK = 32;

    auto stage = [&](int t) {
        const int k0 = t * 32;
        __half* An = Ah + (t % 3) * TSZ;
        __half* Bn = Bh + (t % 3) * TSZ;
#pragma unroll
        for (int i = 0; i < 2; i++) {
            int c = tid + i * 256;
            int row = c >> 2, cc = c & 3;
            cpa16(&An[row * TH + cc * 8], &Asrc[(size_t)(bm + row) * a_stride + k0 + cc * 8]);
            cpa16(&Bn[row * TH + cc * 8], &Bsrc[(size_t)(bn + row) * b_stride + k0 + cc * 8]);
        }
    };

    stage(0); cpa_commit();
    stage(1); cpa_commit();

    const int lane = tid & 31;
    const int wid  = tid >> 5;
    const int wm   = (wid >> 2) * 64;
    const int wn   = (wid & 3) * 32;
    const int q8   = lane >> 3;       // matrix index within x4
    const int r8   = lane & 7;        // row within matrix

    for (int kt = 0; kt < NK; kt++) {
        cpa_wait1();
        __syncthreads();
        if (kt + 2 < NK) stage(kt + 2);
        cpa_commit();

        const unsigned* A32 = (const unsigned*)(Ah + (kt % 3) * TSZ);
        const unsigned* B32 = (const unsigned*)(Bh + (kt % 3) * TSZ);
#pragma unroll
        for (int kc = 0; kc < 2; kc++) {
            const int kb = kc * 8;
            unsigned af[4][4], bf[4][2];
#pragma unroll
            for (int mi = 0; mi < 4; mi++) {
                // x4: m0=(mg0,k0) m1=(mg1,k0) m2=(mg0,k1) m3=(mg1,k1)
                const int row = wm + mi * 16 + (q8 & 1) * 8 + r8;
                const int col = kb + (q8 >> 1) * 4;
                ldsm4(af[mi][0], af[mi][1], af[mi][2], af[mi][3], A32 + row * TH32 + col);
            }
#pragma unroll
            for (int njp = 0; njp < 4; njp += 2) {
                // x4: m0=(ng0,k0) m1=(ng0,k1) m2=(ng1,k0) m3=(ng1,k1)
                const int row = wn + njp * 8 + (q8 >> 1) * 8 + r8;
                const int col = kb + (q8 & 1) * 4;
                ldsm4(bf[njp][0], bf[njp][1], bf[njp + 1][0], bf[njp + 1][1],
                      B32 + row * TH32 + col);
            }
#pragma unroll
            for (int mi = 0; mi < 4; mi++)
#pragma unroll
                for (int nj = 0; nj < 4; nj++)
                    mma16(acc[mi][nj], af[mi][0], af[mi][1], af[mi][2], af[mi][3],
                          bf[nj][0], bf[nj][1]);
        }
    }
}

// ---------------------------------------------------------------------------
// QKV GEMM: X[4096,1024]h @ Wa^T -> q/k (half, [s][d]); v (half, TRANSPOSED [d][s])
// ---------------------------------------------------------------------------
__global__ __launch_bounds__(256, 2) void qkv_gemm(const float* __restrict__ bias)
{
    extern __shared__ __half shq[];
    float acc[4][4][4];
#pragma unroll
    for (int mi = 0; mi < 4; mi++)
#pragma unroll
        for (int nj = 0; nj < 4; nj++)
#pragma unroll
            for (int t = 0; t < 4; t++) acc[mi][nj][t] = 0.f;

    const int bm = blockIdx.y * 128;
    const int bn = blockIdx.x * 128;
    gemm128(g_x, 1024, g_wa, 1024, bm, bn, shq, acc);

    const int lane = threadIdx.x & 31;
    const int wid  = threadIdx.x >> 5;
    const int g    = lane >> 2;
    const int tg   = lane & 3;
    const int wm   = (wid >> 2) * 64;
    const int wn   = (wid & 3) * 32;

#pragma unroll
    for (int mi = 0; mi < 4; mi++) {
#pragma unroll
        for (int nj = 0; nj < 4; nj++) {
#pragma unroll
            for (int t = 0; t < 4; t++) {
                const int m = bm + wm + mi * 16 + g + ((t >= 2) ? 8 : 0);
                const int n = bn + wn + nj * 8 + 2 * tg + (t & 1);
                const float v = acc[mi][nj][t] + bias[n];
                const int bidx = m >> 11;
                const int s = m & 2047;
                const int which = n >> 10;
                const int jj = n & 1023;
                const int h = jj >> 6;
                const int d = jj & 63;
                if (which == 0)
                    g_q[(size_t)((bidx * HH + h) * SS + s) * HD + d] = __float2half_rn(v);
                else if (which == 1)
                    g_k[(size_t)((bidx * HH + h) * SS + s) * HD + d] = __float2half_rn(v);
                else
                    g_v[(size_t)((bidx * HH + h) * HD + d) * SS + s] = __float2half_rn(v);
            }
        }
    }
}

// ---------------------------------------------------------------------------
// Projection GEMM
// ---------------------------------------------------------------------------
__global__ __launch_bounds__(256, 2) void proj_gemm(const float* __restrict__ bias,
                                                    float* __restrict__ out)
{
    extern __shared__ __half shq[];
    float acc[4][4][4];
#pragma unroll
    for (int mi = 0; mi < 4; mi++)
#pragma unroll
        for (int nj = 0; nj < 4; nj++)
#pragma unroll
            for (int t = 0; t < 4; t++) acc[mi][nj][t] = 0.f;

    const int bm = blockIdx.y * 128;
    const int bn = blockIdx.x * 128;
    gemm128(g_ao, 1024, g_wp, 1024, bm, bn, shq, acc);

    const int lane = threadIdx.x & 31;
    const int wid  = threadIdx.x >> 5;
    const int g    = lane >> 2;
    const int tg   = lane & 3;
    const int wm   = (wid >> 2) * 64;
    const int wn   = (wid & 3) * 32;

#pragma unroll
    for (int mi = 0; mi < 4; mi++) {
#pragma unroll
        for (int nj = 0; nj < 4; nj++) {
#pragma unroll
            for (int t = 0; t < 4; t++) {
                const int m = bm + wm + mi * 16 + g + ((t >= 2) ? 8 : 0);
                const int n = bn + wn + nj * 8 + 2 * tg + (t & 1);
                out[(size_t)m * DD + n] = acc[mi][nj][t] + bias[n];
            }
        }
    }
}

// ---------------------------------------------------------------------------
// Flash-style attention, all-fp16 mma + ldmatrix fragment loads.
// ---------------------------------------------------------------------------
#define PS_H 136               // Ps row stride (halves); 68 u32
#define PS_H32 68
#define PSSZ (128*PS_H)
#define KH 72                  // K tile row stride (halves)
#define KH32 36
#define KSZH (128*KH)
#define VT_H 136               // V^T tile row stride (halves)
#define VT_H32 68
#define VTSZ (64*VT_H)
#define ATT_SMEM_BYTES ((PSSZ + 2*KSZH + 2*VTSZ) * 2)

__global__ __launch_bounds__(256, 2) void attn_kernel(float* __restrict__ out_base)
{
    extern __shared__ __half smh[];
    __half* Ps = smh;                     // [128][PS_H]
    __half* Kh = smh + PSSZ;              // [2][128][KH]
    __half* VT = Kh + 2 * KSZH;           // [2][64][VT_H]

    const int tid  = threadIdx.x;
    const int lane = tid & 31;
    const int wid  = tid >> 5;
    const int g    = lane >> 2;
    const int tg   = lane & 3;
    const int qw   = wid * 16;
    const int q8   = lane >> 3;
    const int r8   = lane & 7;

    const int b  = blockIdx.z;
    const int h  = blockIdx.y;
    const int qt = blockIdx.x;
    const int q0 = qt * 128;

    const __half* Qbh = g_q + (size_t)((b * HH + h) * SS) * HD;
    const __half* Kbh = g_k + (size_t)((b * HH + h) * SS) * HD;
    const __half* Vbt = g_v + (size_t)((b * HH + h) * HD) * SS;   // [d][s]

    // prologue: async-load K0 + VT0
#pragma unroll
    for (int i = 0; i < 4; i++) {
        int c = tid + i * 256;
        int row = c >> 3, cc = c & 7;
        cpa16(&Kh[row * KH + cc * 8], &Kbh[(size_t)row * HD + cc * 8]);
    }
#pragma unroll
    for (int i = 0; i < 4; i++) {
        int c = tid + i * 256;
        int row = c >> 4, cc = c & 15;
        cpa16(&VT[row * VT_H + cc * 8], &Vbt[(size_t)row * SS + cc * 8]);
    }
    cpa_commit();

    // Q fragments (fp16, 4 kc steps of k16), direct from gmem
    unsigned qa[4][4];
    {
        const unsigned* q0p = (const unsigned*)(Qbh + (size_t)(q0 + qw + g) * HD);
        const unsigned* q1p = (const unsigned*)(Qbh + (size_t)(q0 + qw + g + 8) * HD);
#pragma unroll
        for (int kc = 0; kc < 4; kc++) {
            qa[kc][0] = q0p[kc * 8 + tg    ];
            qa[kc][1] = q1p[kc * 8 + tg    ];
            qa[kc][2] = q0p[kc * 8 + 4 + tg];
            qa[kc][3] = q1p[kc * 8 + 4 + tg];
        }
    }

    float m0 = -1e30f, m1 = -1e30f, l0 = 0.f, l1 = 0.f;
    float o[8][4];
#pragma unroll
    for (int nf = 0; nf < 8; nf++)
#pragma unroll
        for (int t = 0; t < 4; t++) o[nf][t] = 0.f;

    const int nkt  = qt + 1;
    const int row0 = q0 + qw + g;
    const int row1 = row0 + 8;

    // ======================= Pass 1 ===================
    for (int kt = 0; kt < nkt; kt++) {
        cpa_wait0();
        __syncthreads();

        if (kt + 1 < nkt) {
            const int nb = (kt + 1) * 128;
            __half* Kn = Kh + ((kt + 1) & 1) * KSZH;
            __half* Vn = VT + ((kt + 1) & 1) * VTSZ;
#pragma unroll
            for (int i = 0; i < 4; i++) {
                int c = tid + i * 256;
                int row = c >> 3, cc = c & 7;
                cpa16(&Kn[row * KH + cc * 8], &Kbh[(size_t)(nb + row) * HD + cc * 8]);
            }
#pragma unroll
            for (int i = 0; i < 4; i++) {
                int c = tid + i * 256;
                int row = c >> 4, cc = c & 15;
                cpa16(&Vn[row * VT_H + cc * 8], &Vbt[(size_t)row * SS + nb + cc * 8]);
            }
            cpa_commit();
        }

        const unsigned* K32 = (const unsigned*)(Kh + (kt & 1) * KSZH);
        const int kbase = kt * 128;

        // S = Q K^T (fp16 mma, ldmatrix B)
        float s[16][4];
#pragma unroll
        for (int nf = 0; nf < 16; nf++)
#pragma unroll
            for (int t = 0; t < 4; t++) s[nf][t] = 0.f;
#pragma unroll
        for (int kc = 0; kc < 4; kc++) {
#pragma unroll
            for (int nfp = 0; nfp < 16; nfp += 2) {
                unsigned b00, b01, b10, b11;
                const int row = nfp * 8 + (q8 >> 1) * 8 + r8;
                const int col = kc * 8 + (q8 & 1) * 4;
                ldsm4(b00, b01, b10, b11, K32 + row * KH32 + col);
                mma16(s[nfp    ], qa[kc][0], qa[kc][1], qa[kc][2], qa[kc][3], b00, b01);
                mma16(s[nfp + 1], qa[kc][0], qa[kc][1], qa[kc][2], qa[kc][3], b10, b11);
            }
        }

        // scale + causal mask + tile row max
        const bool diag = (kt == qt);
        float mx0 = -1e30f, mx1 = -1e30f;
#pragma unroll
        for (int nf = 0; nf < 16; nf++) {
            const int col = kbase + nf * 8 + 2 * tg;
            float v0 = s[nf][0] * 0.125f;
            float v1 = s[nf][1] * 0.125f;
            float v2 = s[nf][2] * 0.125f;
            float v3 = s[nf][3] * 0.125f;
            if (diag) {
                if (col     > row0) v0 = -1e30f;
                if (col + 1 > row0) v1 = -1e30f;
                if (col     > row1) v2 = -1e30f;
                if (col + 1 > row1) v3 = -1e30f;
            }
            s[nf][0] = v0; s[nf][1] = v1; s[nf][2] = v2; s[nf][3] = v3;
            mx0 = fmaxf(mx0, fmaxf(v0, v1));
            mx1 = fmaxf(mx1, fmaxf(v2, v3));
        }
        mx0 = fmaxf(mx0, __shfl_xor_sync(0xffffffffu, mx0, 1));
        mx0 = fmaxf(mx0, __shfl_xor_sync(0xffffffffu, mx0, 2));
        mx1 = fmaxf(mx1, __shfl_xor_sync(0xffffffffu, mx1, 1));
        mx1 = fmaxf(mx1, __shfl_xor_sync(0xffffffffu, mx1, 2));

        const float mn0 = fmaxf(m0, mx0);
        const float mn1 = fmaxf(m1, mx1);
        const float al0 = __expf(m0 - mn0);
        const float al1 = __expf(m1 - mn1);

        float rs0 = 0.f, rs1 = 0.f;
        __half2* Pp = (__half2*)Ps;
#pragma unroll
        for (int nf = 0; nf < 16; nf++) {
            const float p0 = __expf(s[nf][0] - mn0);
            const float p1 = __expf(s[nf][1] - mn0);
            const float p2 = __expf(s[nf][2] - mn1);
            const float p3 = __expf(s[nf][3] - mn1);
            rs0 += p0 + p1;
            rs1 += p2 + p3;
            Pp[(qw + g    ) * (PS_H/2) + nf * 4 + tg] = __floats2half2_rn(p0, p1);
            Pp[(qw + g + 8) * (PS_H/2) + nf * 4 + tg] = __floats2half2_rn(p2, p3);
        }
        rs0 += __shfl_xor_sync(0xffffffffu, rs0, 1);
        rs0 += __shfl_xor_sync(0xffffffffu, rs0, 2);
        rs1 += __shfl_xor_sync(0xffffffffu, rs1, 1);
        rs1 += __shfl_xor_sync(0xffffffffu, rs1, 2);

        m0 = mn0; m1 = mn1;
        l0 = l0 * al0 + rs0;
        l1 = l1 * al1 + rs1;
#pragma unroll
        for (int nf = 0; nf < 8; nf++) {
            o[nf][0] *= al0; o[nf][1] *= al0;
            o[nf][2] *= al1; o[nf][3] *= al1;
        }

        // O += P V (fp16 mma; P and VT via ldmatrix)
        const unsigned* P32  = (const unsigned*)Ps;
        const unsigned* VT32 = (const unsigned*)(VT + (kt & 1) * VTSZ);
#pragma unroll
        for (int kc = 0; kc < 8; kc++) {
            unsigned a0, a1, a2, a3;
            {
                const int row = qw + (q8 & 1) * 8 + r8;
                const int col = kc * 8 + (q8 >> 1) * 4;
                ldsm4(a0, a1, a2, a3, P32 + row * PS_H32 + col);
            }
#pragma unroll
            for (int nfp = 0; nfp < 8; nfp += 2) {
                unsigned b00, b01, b10, b11;
                const int row = nfp * 8 + (q8 >> 1) * 8 + r8;
                const int col = kc * 8 + (q8 & 1) * 4;
                ldsm4(b00, b01, b10, b11, VT32 + row * VT_H32 + col);
                mma16(o[nfp    ], a0, a1, a2, a3, b00, b01);
                mma16(o[nfp + 1], a0, a1, a2, a3, b10, b11);
            }
        }
    }

    // Write O / l (fp16 for proj)
    const float il0 = 1.0f / l0;
    const float il1 = 1.0f / l1;
    {
        const int orow = b * SS + q0 + qw + g;
#pragma unroll
        for (int nf = 0; nf < 8; nf++) {
            const int col = h * HD + nf * 8 + 2 * tg;
            __half2* d0 = (__half2*)&g_ao[(size_t)orow * DD + col];
            __half2* d1 = (__half2*)&g_ao[(size_t)(orow + 8) * DD + col];
            *d0 = __floats2half2_rn(o[nf][0] * il0, o[nf][1] * il0);
            *d1 = __floats2half2_rn(o[nf][2] * il1, o[nf][3] * il1);
        }
    }
    __syncthreads();   // all reads of Kh/VT done before pass-2 overwrites

    // =============== Pass 2: recompute scores, write weights direct ========
    float* attn = out_base + (size_t)MM * DD;
    const size_t abase = (size_t)(b * HH + h) * SS + q0;
    float* w0p = attn + (abase + qw + g) * SS;
    float* w1p = attn + (abase + qw + g + 8) * SS;

#pragma unroll
    for (int i = 0; i < 4; i++) {
        int c = tid + i * 256;
        int row = c >> 3, cc = c & 7;
        cpa16(&Kh[row * KH + cc * 8], &Kbh[(size_t)row * HD + cc * 8]);
    }
    cpa_commit();

    for (int kt = 0; kt < nkt; kt++) {
        cpa_wait0();
        __syncthreads();

        if (kt + 1 < nkt) {
            const int nb = (kt + 1) * 128;
            __half* Kn = Kh + ((kt + 1) & 1) * KSZH;
#pragma unroll
            for (int i = 0; i < 4; i++) {
                int c = tid + i * 256;
                int row = c >> 3, cc = c & 7;
                cpa16(&Kn[row * KH + cc * 8], &Kbh[(size_t)(nb + row) * HD + cc * 8]);
            }
            cpa_commit();
        }

        const unsigned* K32 = (const unsigned*)(Kh + (kt & 1) * KSZH);
        const int kbase = kt * 128;

        float s[16][4];
#pragma unroll
        for (int nf = 0; nf < 16; nf++)
#pragma unroll
            for (int t = 0; t < 4; t++) s[nf][t] = 0.f;
#pragma unroll
        for (int kc = 0; kc < 4; kc++) {
#pragma unroll
            for (int nfp = 0; nfp < 16; nfp += 2) {
                unsigned b00, b01, b10, b11;
                const int row = nfp * 8 + (q8 >> 1) * 8 + r8;
                const int col = kc * 8 + (q8 & 1) * 4;
                ldsm4(b00, b01, b10, b11, K32 + row * KH32 + col);
                mma16(s[nfp    ], qa[kc][0], qa[kc][1], qa[kc][2], qa[kc][3], b00, b01);
                mma16(s[nfp + 1], qa[kc][0], qa[kc][1], qa[kc][2], qa[kc][3], b10, b11);
            }
        }

        const bool diag = (kt == qt);
#pragma unroll
        for (int nf = 0; nf < 16; nf++) {
            const int col = kbase + nf * 8 + 2 * tg;
            float w0 = __expf(s[nf][0] * 0.125f - m0) * il0;
            float w1 = __expf(s[nf][1] * 0.125f - m0) * il0;
            float w2 = __expf(s[nf][2] * 0.125f - m1) * il1;
            float w3 = __expf(s[nf][3] * 0.125f - m1) * il1;
            if (diag) {
                if (col     > row0) w0 = 0.f;
                if (col + 1 > row0) w1 = 0.f;
                if (col     > row1) w2 = 0.f;
                if (col + 1 > row1) w3 = 0.f;
            }
            float2 t0, t1;
            t0.x = w0; t0.y = w1;
            t1.x = w2; t1.y = w3;
            *(float2*)&w0p[col] = t0;
            *(float2*)&w1p[col] = t1;
        }
    }

    // zero-fill strictly-upper region
    const int kl = nkt * 128;
    if (kl < SS) {
        const float4 z = make_float4(0.f, 0.f, 0.f, 0.f);
        const int w4 = (SS - kl) >> 2;
        for (int row = 0; row < 128; row++) {
            float4* dst = (float4*)&attn[(abase + row) * SS + kl];
            for (int c = tid; c < w4; c += 256) dst[c] = z;
        }
    }
}

// ---------------------------------------------------------------------------
extern "C" void kernel_launch(void* const* d_in, const int* in_sizes, int n_in,
                              void* d_out, int out_size)
{
    const float* x      = (const float*)d_in[0];
    const float* W_attn = (const float*)d_in[1];
    const float* b_attn = (const float*)d_in[2];
    const float* W_proj = (const float*)d_in[3];
    const float* b_proj = (const float*)d_in[4];
    float* out = (float*)d_out;

    cudaFuncSetAttribute(qkv_gemm,
                         cudaFuncAttributeMaxDynamicSharedMemorySize, GEMM_SMEM_BYTES);
    cudaFuncSetAttribute(proj_gemm,
                         cudaFuncAttributeMaxDynamicSharedMemorySize, GEMM_SMEM_BYTES);
    cudaFuncSetAttribute(attn_kernel,
                         cudaFuncAttributeMaxDynamicSharedMemorySize, ATT_SMEM_BYTES);

    cvt_x<<<1024, 256>>>(x);
    transpose_wa<<<dim3(96, 32), 256>>>(W_attn);
    transpose_wp<<<dim3(32, 32), 256>>>(W_proj);
    qkv_gemm<<<dim3(24, 32), 256, GEMM_SMEM_BYTES>>>(b_attn);
    attn_kernel<<<dim3(SS / 128, HH, BB), 256, ATT_SMEM_BYTES>>>(out);
    proj_gemm<<<dim3(8, 32), 256, GEMM_SMEM_BYTES>>>(b_proj, out);
}

// round 11
// speedup vs baseline: 9.8972x; 1.0439x over previous
#include <cuda_runtime.h>
#include <cuda_fp16.h>
#include <math.h>

#define BB 2
#define HH 16
#define SS 2048
#define DD 1024
#define HD 64
#define MM (BB*SS)          // 4096 rows

// Scratch (device globals)
__device__ __half g_q[BB*HH*SS*HD];   // [B,H,S,hd] fp16
__device__ __half g_k[BB*HH*SS*HD];   // [B,H,S,hd] fp16
__device__ __half g_v[BB*HH*HD*SS];   // [B,H,hd,S] fp16 (TRANSPOSED)
__device__ __half g_ao[MM*DD];        // attention output fp16
__device__ __half g_x[MM*DD];         // fp16 X
__device__ __half g_wa[3*DD*DD];      // W_attn^T  [n=3072][k=1024] fp16
__device__ __half g_wp[DD*DD];        // W_proj^T  [n=1024][k=1024] fp16

// ---------------------------------------------------------------------------
// helpers
// ---------------------------------------------------------------------------
__device__ __forceinline__ void mma16(float* c,
                                      unsigned a0, unsigned a1, unsigned a2, unsigned a3,
                                      unsigned b0, unsigned b1) {
    asm volatile(
        "mma.sync.aligned.m16n8k16.row.col.f32.f16.f16.f32 "
        "{%0,%1,%2,%3},{%4,%5,%6,%7},{%8,%9},{%0,%1,%2,%3};"
        : "+f"(c[0]), "+f"(c[1]), "+f"(c[2]), "+f"(c[3])
        : "r"(a0), "r"(a1), "r"(a2), "r"(a3), "r"(b0), "r"(b1));
}
__device__ __forceinline__ void ldsm4(unsigned& r0, unsigned& r1, unsigned& r2, unsigned& r3,
                                      const void* p) {
    unsigned a = (unsigned)__cvta_generic_to_shared(p);
    asm volatile("ldmatrix.sync.aligned.m8n8.x4.shared.b16 {%0,%1,%2,%3}, [%4];"
                 : "=r"(r0), "=r"(r1), "=r"(r2), "=r"(r3) : "r"(a));
}
__device__ __forceinline__ void cpa16(const void* smem_dst, const void* gsrc) {
    unsigned s = (unsigned)__cvta_generic_to_shared(smem_dst);
    asm volatile("cp.async.cg.shared.global [%0], [%1], 16;" :: "r"(s), "l"(gsrc));
}
__device__ __forceinline__ void cpa_commit() {
    asm volatile("cp.async.commit_group;");
}
__device__ __forceinline__ void cpa_wait0() {
    asm volatile("cp.async.wait_group 0;");
}

// ---------------------------------------------------------------------------
// Converters
// ---------------------------------------------------------------------------
__global__ __launch_bounds__(256) void cvt_x(const float* __restrict__ X)
{
    const int stride = gridDim.x * blockDim.x;
    for (int k = blockIdx.x * blockDim.x + threadIdx.x; k < MM * DD / 4; k += stride) {
        float4 v = ((const float4*)X)[k];
        ((__half2*)g_x)[k * 2    ] = __floats2half2_rn(v.x, v.y);
        ((__half2*)g_x)[k * 2 + 1] = __floats2half2_rn(v.z, v.w);
    }
}

// W [1024][N] float -> Wt [N][1024] half (tiled transpose)
__global__ __launch_bounds__(256) void transpose_wa(const float* __restrict__ W)
{
    __shared__ float ts[32][33];
    const int tx = threadIdx.x & 31, ty = threadIdx.x >> 5;
    const int nb = blockIdx.x * 32, kb = blockIdx.y * 32;
#pragma unroll
    for (int i = 0; i < 4; i++)
        ts[ty + i * 8][tx] = W[(size_t)(kb + ty + i * 8) * 3072 + nb + tx];
    __syncthreads();
#pragma unroll
    for (int i = 0; i < 4; i++)
        g_wa[(size_t)(nb + ty + i * 8) * 1024 + kb + tx] = __float2half_rn(ts[tx][ty + i * 8]);
}
__global__ __launch_bounds__(256) void transpose_wp(const float* __restrict__ W)
{
    __shared__ float ts[32][33];
    const int tx = threadIdx.x & 31, ty = threadIdx.x >> 5;
    const int nb = blockIdx.x * 32, kb = blockIdx.y * 32;
#pragma unroll
    for (int i = 0; i < 4; i++)
        ts[ty + i * 8][tx] = W[(size_t)(kb + ty + i * 8) * 1024 + nb + tx];
    __syncthreads();
#pragma unroll
    for (int i = 0; i < 4; i++)
        g_wp[(size_t)(nb + ty + i * 8) * 1024 + kb + tx] = __float2half_rn(ts[tx][ty + i * 8]);
}

// ---------------------------------------------------------------------------
// fp16 GEMM core: C[128x128] tile, K-tile 64, 2-stage cp.async, ldmatrix.x4
// Tile: 128 rows x 64 halves, row stride 72 halves (36 u32, conflict-free)
// ---------------------------------------------------------------------------
#define TH 72                 // halves per tile row
#define TH32 36
#define TSZ (128*TH)
#define GEMM_SMEM_BYTES (2 * 2 * TSZ * 2)   // 2 stages x 2 matrices

__device__ __forceinline__ void gemm128(const __half* __restrict__ Asrc, size_t a_stride,
                                        const __half* __restrict__ Bsrc, size_t b_stride,
                                        int bm, int bn, __half* sh, float acc[4][4][4])
{
    __half* Ah = sh;                 // [2][TSZ]
    __half* Bh = sh + 2 * TSZ;       // [2][TSZ]

    const int tid  = threadIdx.x;
    const int NK = 16;               // 1024 / 64

    auto stage = [&](int t) {
        const int k0 = t * 64;
        __half* An = Ah + (t & 1) * TSZ;
        __half* Bn = Bh + (t & 1) * TSZ;
#pragma unroll
        for (int i = 0; i < 4; i++) {
            int c = tid + i * 256;               // 1024 chunks (128 rows x 8)
            int row = c >> 3, cc = c & 7;
            cpa16(&An[row * TH + cc * 8], &Asrc[(size_t)(bm + row) * a_stride + k0 + cc * 8]);
            cpa16(&Bn[row * TH + cc * 8], &Bsrc[(size_t)(bn + row) * b_stride + k0 + cc * 8]);
        }
    };

    stage(0); cpa_commit();

    const int lane = tid & 31;
    const int wid  = tid >> 5;
    const int wm   = (wid >> 2) * 64;
    const int wn   = (wid & 3) * 32;
    const int q8   = lane >> 3;
    const int r8   = lane & 7;

    for (int kt = 0; kt < NK; kt++) {
        cpa_wait0();
        __syncthreads();
        if (kt + 1 < NK) {
            stage(kt + 1);
            cpa_commit();
        }

        const unsigned* A32 = (const unsigned*)(Ah + (kt & 1) * TSZ);
        const unsigned* B32 = (const unsigned*)(Bh + (kt & 1) * TSZ);
#pragma unroll
        for (int kc = 0; kc < 4; kc++) {
            const int kb = kc * 8;
            unsigned af[4][4], bf[4][2];
#pragma unroll
            for (int mi = 0; mi < 4; mi++) {
                const int row = wm + mi * 16 + (q8 & 1) * 8 + r8;
                const int col = kb + (q8 >> 1) * 4;
                ldsm4(af[mi][0], af[mi][1], af[mi][2], af[mi][3], A32 + row * TH32 + col);
            }
#pragma unroll
            for (int njp = 0; njp < 4; njp += 2) {
                const int row = wn + njp * 8 + (q8 >> 1) * 8 + r8;
                const int col = kb + (q8 & 1) * 4;
                ldsm4(bf[njp][0], bf[njp][1], bf[njp + 1][0], bf[njp + 1][1],
                      B32 + row * TH32 + col);
            }
#pragma unroll
            for (int mi = 0; mi < 4; mi++)
#pragma unroll
                for (int nj = 0; nj < 4; nj++)
                    mma16(acc[mi][nj], af[mi][0], af[mi][1], af[mi][2], af[mi][3],
                          bf[nj][0], bf[nj][1]);
        }
    }
}

// ---------------------------------------------------------------------------
// QKV GEMM: X[4096,1024]h @ Wa^T -> q/k (half, [s][d]); v (half, TRANSPOSED [d][s])
// ---------------------------------------------------------------------------
__global__ __launch_bounds__(256, 2) void qkv_gemm(const float* __restrict__ bias)
{
    extern __shared__ __half shq[];
    float acc[4][4][4];
#pragma unroll
    for (int mi = 0; mi < 4; mi++)
#pragma unroll
        for (int nj = 0; nj < 4; nj++)
#pragma unroll
            for (int t = 0; t < 4; t++) acc[mi][nj][t] = 0.f;

    const int bm = blockIdx.y * 128;
    const int bn = blockIdx.x * 128;
    gemm128(g_x, 1024, g_wa, 1024, bm, bn, shq, acc);

    const int lane = threadIdx.x & 31;
    const int wid  = threadIdx.x >> 5;
    const int g    = lane >> 2;
    const int tg   = lane & 3;
    const int wm   = (wid >> 2) * 64;
    const int wn   = (wid & 3) * 32;

#pragma unroll
    for (int mi = 0; mi < 4; mi++) {
#pragma unroll
        for (int nj = 0; nj < 4; nj++) {
#pragma unroll
            for (int t = 0; t < 4; t++) {
                const int m = bm + wm + mi * 16 + g + ((t >= 2) ? 8 : 0);
                const int n = bn + wn + nj * 8 + 2 * tg + (t & 1);
                const float v = acc[mi][nj][t] + bias[n];
                const int bidx = m >> 11;
                const int s = m & 2047;
                const int which = n >> 10;
                const int jj = n & 1023;
                const int h = jj >> 6;
                const int d = jj & 63;
                if (which == 0)
                    g_q[(size_t)((bidx * HH + h) * SS + s) * HD + d] = __float2half_rn(v);
                else if (which == 1)
                    g_k[(size_t)((bidx * HH + h) * SS + s) * HD + d] = __float2half_rn(v);
                else
                    g_v[(size_t)((bidx * HH + h) * HD + d) * SS + s] = __float2half_rn(v);
            }
        }
    }
}

// ---------------------------------------------------------------------------
// Projection GEMM
// ---------------------------------------------------------------------------
__global__ __launch_bounds__(256, 2) void proj_gemm(const float* __restrict__ bias,
                                                    float* __restrict__ out)
{
    extern __shared__ __half shq[];
    float acc[4][4][4];
#pragma unroll
    for (int mi = 0; mi < 4; mi++)
#pragma unroll
        for (int nj = 0; nj < 4; nj++)
#pragma unroll
            for (int t = 0; t < 4; t++) acc[mi][nj][t] = 0.f;

    const int bm = blockIdx.y * 128;
    const int bn = blockIdx.x * 128;
    gemm128(g_ao, 1024, g_wp, 1024, bm, bn, shq, acc);

    const int lane = threadIdx.x & 31;
    const int wid  = threadIdx.x >> 5;
    const int g    = lane >> 2;
    const int tg   = lane & 3;
    const int wm   = (wid >> 2) * 64;
    const int wn   = (wid & 3) * 32;

#pragma unroll
    for (int mi = 0; mi < 4; mi++) {
#pragma unroll
        for (int nj = 0; nj < 4; nj++) {
#pragma unroll
            for (int t = 0; t < 4; t++) {
                const int m = bm + wm + mi * 16 + g + ((t >= 2) ? 8 : 0);
                const int n = bn + wn + nj * 8 + 2 * tg + (t & 1);
                out[(size_t)m * DD + n] = acc[mi][nj][t] + bias[n];
            }
        }
    }
}

// ---------------------------------------------------------------------------
// Flash-style attention, all-fp16 mma + ldmatrix; LPT scheduling (big qt first)
// ---------------------------------------------------------------------------
#define PS_H 136               // Ps row stride (halves); 68 u32
#define PS_H32 68
#define PSSZ (128*PS_H)
#define KH 72                  // K tile row stride (halves)
#define KH32 36
#define KSZH (128*KH)
#define VT_H 136               // V^T tile row stride (halves)
#define VT_H32 68
#define VTSZ (64*VT_H)
#define ATT_SMEM_BYTES ((PSSZ + 2*KSZH + 2*VTSZ) * 2)

__global__ __launch_bounds__(256, 2) void attn_kernel(float* __restrict__ out_base)
{
    extern __shared__ __half smh[];
    __half* Ps = smh;                     // [128][PS_H]
    __half* Kh = smh + PSSZ;              // [2][128][KH]
    __half* VT = Kh + 2 * KSZH;           // [2][64][VT_H]

    const int tid  = threadIdx.x;
    const int lane = tid & 31;
    const int wid  = tid >> 5;
    const int g    = lane >> 2;
    const int tg   = lane & 3;
    const int qw   = wid * 16;
    const int q8   = lane >> 3;
    const int r8   = lane & 7;

    const int b  = blockIdx.z;
    const int h  = blockIdx.y;
    const int qt = (gridDim.x - 1) - blockIdx.x;   // LPT: expensive tiles first
    const int q0 = qt * 128;

    const __half* Qbh = g_q + (size_t)((b * HH + h) * SS) * HD;
    const __half* Kbh = g_k + (size_t)((b * HH + h) * SS) * HD;
    const __half* Vbt = g_v + (size_t)((b * HH + h) * HD) * SS;   // [d][s]

    // prologue: async-load K0 + VT0
#pragma unroll
    for (int i = 0; i < 4; i++) {
        int c = tid + i * 256;
        int row = c >> 3, cc = c & 7;
        cpa16(&Kh[row * KH + cc * 8], &Kbh[(size_t)row * HD + cc * 8]);
    }
#pragma unroll
    for (int i = 0; i < 4; i++) {
        int c = tid + i * 256;
        int row = c >> 4, cc = c & 15;
        cpa16(&VT[row * VT_H + cc * 8], &Vbt[(size_t)row * SS + cc * 8]);
    }
    cpa_commit();

    // Q fragments (fp16, 4 kc steps of k16), direct from gmem
    unsigned qa[4][4];
    {
        const unsigned* q0p = (const unsigned*)(Qbh + (size_t)(q0 + qw + g) * HD);
        const unsigned* q1p = (const unsigned*)(Qbh + (size_t)(q0 + qw + g + 8) * HD);
#pragma unroll
        for (int kc = 0; kc < 4; kc++) {
            qa[kc][0] = q0p[kc * 8 + tg    ];
            qa[kc][1] = q1p[kc * 8 + tg    ];
            qa[kc][2] = q0p[kc * 8 + 4 + tg];
            qa[kc][3] = q1p[kc * 8 + 4 + tg];
        }
    }

    float m0 = -1e30f, m1 = -1e30f, l0 = 0.f, l1 = 0.f;
    float o[8][4];
#pragma unroll
    for (int nf = 0; nf < 8; nf++)
#pragma unroll
        for (int t = 0; t < 4; t++) o[nf][t] = 0.f;

    const int nkt  = qt + 1;
    const int row0 = q0 + qw + g;
    const int row1 = row0 + 8;

    // ======================= Pass 1 ===================
    for (int kt = 0; kt < nkt; kt++) {
        cpa_wait0();
        __syncthreads();

        if (kt + 1 < nkt) {
            const int nb = (kt + 1) * 128;
            __half* Kn = Kh + ((kt + 1) & 1) * KSZH;
            __half* Vn = VT + ((kt + 1) & 1) * VTSZ;
#pragma unroll
            for (int i = 0; i < 4; i++) {
                int c = tid + i * 256;
                int row = c >> 3, cc = c & 7;
                cpa16(&Kn[row * KH + cc * 8], &Kbh[(size_t)(nb + row) * HD + cc * 8]);
            }
#pragma unroll
            for (int i = 0; i < 4; i++) {
                int c = tid + i * 256;
                int row = c >> 4, cc = c & 15;
                cpa16(&Vn[row * VT_H + cc * 8], &Vbt[(size_t)row * SS + nb + cc * 8]);
            }
            cpa_commit();
        }

        const unsigned* K32 = (const unsigned*)(Kh + (kt & 1) * KSZH);
        const int kbase = kt * 128;

        // S = Q K^T (fp16 mma, ldmatrix B)
        float s[16][4];
#pragma unroll
        for (int nf = 0; nf < 16; nf++)
#pragma unroll
            for (int t = 0; t < 4; t++) s[nf][t] = 0.f;
#pragma unroll
        for (int kc = 0; kc < 4; kc++) {
#pragma unroll
            for (int nfp = 0; nfp < 16; nfp += 2) {
                unsigned b00, b01, b10, b11;
                const int row = nfp * 8 + (q8 >> 1) * 8 + r8;
                const int col = kc * 8 + (q8 & 1) * 4;
                ldsm4(b00, b01, b10, b11, K32 + row * KH32 + col);
                mma16(s[nfp    ], qa[kc][0], qa[kc][1], qa[kc][2], qa[kc][3], b00, b01);
                mma16(s[nfp + 1], qa[kc][0], qa[kc][1], qa[kc][2], qa[kc][3], b10, b11);
            }
        }

        // scale + causal mask + tile row max
        const bool diag = (kt == qt);
        float mx0 = -1e30f, mx1 = -1e30f;
#pragma unroll
        for (int nf = 0; nf < 16; nf++) {
            const int col = kbase + nf * 8 + 2 * tg;
            float v0 = s[nf][0] * 0.125f;
            float v1 = s[nf][1] * 0.125f;
            float v2 = s[nf][2] * 0.125f;
            float v3 = s[nf][3] * 0.125f;
            if (diag) {
                if (col     > row0) v0 = -1e30f;
                if (col + 1 > row0) v1 = -1e30f;
                if (col     > row1) v2 = -1e30f;
                if (col + 1 > row1) v3 = -1e30f;
            }
            s[nf][0] = v0; s[nf][1] = v1; s[nf][2] = v2; s[nf][3] = v3;
            mx0 = fmaxf(mx0, fmaxf(v0, v1));
            mx1 = fmaxf(mx1, fmaxf(v2, v3));
        }
        mx0 = fmaxf(mx0, __shfl_xor_sync(0xffffffffu, mx0, 1));
        mx0 = fmaxf(mx0, __shfl_xor_sync(0xffffffffu, mx0, 2));
        mx1 = fmaxf(mx1, __shfl_xor_sync(0xffffffffu, mx1, 1));
        mx1 = fmaxf(mx1, __shfl_xor_sync(0xffffffffu, mx1, 2));

        const float mn0 = fmaxf(m0, mx0);
        const float mn1 = fmaxf(m1, mx1);
        const float al0 = __expf(m0 - mn0);
        const float al1 = __expf(m1 - mn1);

        float rs0 = 0.f, rs1 = 0.f;
        __half2* Pp = (__half2*)Ps;
#pragma unroll
        for (int nf = 0; nf < 16; nf++) {
            const float p0 = __expf(s[nf][0] - mn0);
            const float p1 = __expf(s[nf][1] - mn0);
            const float p2 = __expf(s[nf][2] - mn1);
            const float p3 = __expf(s[nf][3] - mn1);
            rs0 += p0 + p1;
            rs1 += p2 + p3;
            Pp[(qw + g    ) * (PS_H/2) + nf * 4 + tg] = __floats2half2_rn(p0, p1);
            Pp[(qw + g + 8) * (PS_H/2) + nf * 4 + tg] = __floats2half2_rn(p2, p3);
        }
        rs0 += __shfl_xor_sync(0xffffffffu, rs0, 1);
        rs0 += __shfl_xor_sync(0xffffffffu, rs0, 2);
        rs1 += __shfl_xor_sync(0xffffffffu, rs1, 1);
        rs1 += __shfl_xor_sync(0xffffffffu, rs1, 2);

        m0 = mn0; m1 = mn1;
        l0 = l0 * al0 + rs0;
        l1 = l1 * al1 + rs1;
#pragma unroll
        for (int nf = 0; nf < 8; nf++) {
            o[nf][0] *= al0; o[nf][1] *= al0;
            o[nf][2] *= al1; o[nf][3] *= al1;
        }

        // O += P V (fp16 mma; P and VT via ldmatrix)
        const unsigned* P32  = (const unsigned*)Ps;
        const unsigned* VT32 = (const unsigned*)(VT + (kt & 1) * VTSZ);
#pragma unroll
        for (int kc = 0; kc < 8; kc++) {
            unsigned a0, a1, a2, a3;
            {
                const int row = qw + (q8 & 1) * 8 + r8;
                const int col = kc * 8 + (q8 >> 1) * 4;
                ldsm4(a0, a1, a2, a3, P32 + row * PS_H32 + col);
            }
#pragma unroll
            for (int nfp = 0; nfp < 8; nfp += 2) {
                unsigned b00, b01, b10, b11;
                const int row = nfp * 8 + (q8 >> 1) * 8 + r8;
                const int col = kc * 8 + (q8 & 1) * 4;
                ldsm4(b00, b01, b10, b11, VT32 + row * VT_H32 + col);
                mma16(o[nfp    ], a0, a1, a2, a3, b00, b01);
                mma16(o[nfp + 1], a0, a1, a2, a3, b10, b11);
            }
        }
    }

    // Write O / l (fp16 for proj)
    const float il0 = 1.0f / l0;
    const float il1 = 1.0f / l1;
    {
        const int orow = b * SS + q0 + qw + g;
#pragma unroll
        for (int nf = 0; nf < 8; nf++) {
            const int col = h * HD + nf * 8 + 2 * tg;
            __half2* d0 = (__half2*)&g_ao[(size_t)orow * DD + col];
            __half2* d1 = (__half2*)&g_ao[(size_t)(orow + 8) * DD + col];
            *d0 = __floats2half2_rn(o[nf][0] * il0, o[nf][1] * il0);
            *d1 = __floats2half2_rn(o[nf][2] * il1, o[nf][3] * il1);
        }
    }
    __syncthreads();   // all reads of Kh/VT done before pass-2 overwrites

    // =============== Pass 2: recompute scores, write weights direct ========
    float* attn = out_base + (size_t)MM * DD;
    const size_t abase = (size_t)(b * HH + h) * SS + q0;
    float* w0p = attn + (abase + qw + g) * SS;
    float* w1p = attn + (abase + qw + g + 8) * SS;

#pragma unroll
    for (int i = 0; i < 4; i++) {
        int c = tid + i * 256;
        int row = c >> 3, cc = c & 7;
        cpa16(&Kh[row * KH + cc * 8], &Kbh[(size_t)row * HD + cc * 8]);
    }
    cpa_commit();

    for (int kt = 0; kt < nkt; kt++) {
        cpa_wait0();
        __syncthreads();

        if (kt + 1 < nkt) {
            const int nb = (kt + 1) * 128;
            __half* Kn = Kh + ((kt + 1) & 1) * KSZH;
#pragma unroll
            for (int i = 0; i < 4; i++) {
                int c = tid + i * 256;
                int row = c >> 3, cc = c & 7;
                cpa16(&Kn[row * KH + cc * 8], &Kbh[(size_t)(nb + row) * HD + cc * 8]);
            }
            cpa_commit();
        }

        const unsigned* K32 = (const unsigned*)(Kh + (kt & 1) * KSZH);
        const int kbase = kt * 128;

        float s[16][4];
#pragma unroll
        for (int nf = 0; nf < 16; nf++)
#pragma unroll
            for (int t = 0; t < 4; t++) s[nf][t] = 0.f;
#pragma unroll
        for (int kc = 0; kc < 4; kc++) {
#pragma unroll
            for (int nfp = 0; nfp < 16; nfp += 2) {
                unsigned b00, b01, b10, b11;
                const int row = nfp * 8 + (q8 >> 1) * 8 + r8;
                const int col = kc * 8 + (q8 & 1) * 4;
                ldsm4(b00, b01, b10, b11, K32 + row * KH32 + col);
                mma16(s[nfp    ], qa[kc][0], qa[kc][1], qa[kc][2], qa[kc][3], b00, b01);
                mma16(s[nfp + 1], qa[kc][0], qa[kc][1], qa[kc][2], qa[kc][3], b10, b11);
            }
        }

        const bool diag = (kt == qt);
#pragma unroll
        for (int nf = 0; nf < 16; nf++) {
            const int col = kbase + nf * 8 + 2 * tg;
            float w0 = __expf(s[nf][0] * 0.125f - m0) * il0;
            float w1 = __expf(s[nf][1] * 0.125f - m0) * il0;
            float w2 = __expf(s[nf][2] * 0.125f - m1) * il1;
            float w3 = __expf(s[nf][3] * 0.125f - m1) * il1;
            if (diag) {
                if (col     > row0) w0 = 0.f;
                if (col + 1 > row0) w1 = 0.f;
                if (col     > row1) w2 = 0.f;
                if (col + 1 > row1) w3 = 0.f;
            }
            float2 t0, t1;
            t0.x = w0; t0.y = w1;
            t1.x = w2; t1.y = w3;
            *(float2*)&w0p[col] = t0;
            *(float2*)&w1p[col] = t1;
        }
    }

    // zero-fill strictly-upper region
    const int kl = nkt * 128;
    if (kl < SS) {
        const float4 z = make_float4(0.f, 0.f, 0.f, 0.f);
        const int w4 = (SS - kl) >> 2;
        for (int row = 0; row < 128; row++) {
            float4* dst = (float4*)&attn[(abase + row) * SS + kl];
            for (int c = tid; c < w4; c += 256) dst[c] = z;
        }
    }
}

// ---------------------------------------------------------------------------
extern "C" void kernel_launch(void* const* d_in, const int* in_sizes, int n_in,
                              void* d_out, int out_size)
{
    const float* x      = (const float*)d_in[0];
    const float* W_attn = (const float*)d_in[1];
    const float* b_attn = (const float*)d_in[2];
    const float* W_proj = (const float*)d_in[3];
    const float* b_proj = (const float*)d_in[4];
    float* out = (float*)d_out;

    cudaFuncSetAttribute(qkv_gemm,
                         cudaFuncAttributeMaxDynamicSharedMemorySize, GEMM_SMEM_BYTES);
    cudaFuncSetAttribute(proj_gemm,
                         cudaFuncAttributeMaxDynamicSharedMemorySize, GEMM_SMEM_BYTES);
    cudaFuncSetAttribute(attn_kernel,
                         cudaFuncAttributeMaxDynamicSharedMemorySize, ATT_SMEM_BYTES);

    cvt_x<<<1024, 256>>>(x);
    transpose_wa<<<dim3(96, 32), 256>>>(W_attn);
    transpose_wp<<<dim3(32, 32), 256>>>(W_proj);
    qkv_gemm<<<dim3(24, 32), 256, GEMM_SMEM_BYTES>>>(b_attn);
    attn_kernel<<<dim3(SS / 128, HH, BB), 256, ATT_SMEM_BYTES>>>(out);
    proj_gemm<<<dim3(8, 32), 256, GEMM_SMEM_BYTES>>>(b_proj, out);
}

// round 12
// speedup vs baseline: 10.5064x; 1.0616x over previous
#include <cuda_runtime.h>
#include <cuda_fp16.h>
#include <math.h>

#define BB 2
#define HH 16
#define SS 2048
#define DD 1024
#define HD 64
#define MM (BB*SS)          // 4096 rows

// Scratch (device globals)
__device__ __half g_q[BB*HH*SS*HD];   // [B,H,S,hd] fp16
__device__ __half g_k[BB*HH*SS*HD];   // [B,H,S,hd] fp16
__device__ __half g_v[BB*HH*HD*SS];   // [B,H,hd,S] fp16 (TRANSPOSED)
__device__ __half g_ao[MM*DD];        // attention output fp16
__device__ __half g_x[MM*DD];         // fp16 X
__device__ __half g_wa[3*DD*DD];      // W_attn^T  [n=3072][k=1024] fp16
__device__ __half g_wp[DD*DD];        // W_proj^T  [n=1024][k=1024] fp16
__device__ float2 g_ml[BB*HH*SS];     // per-row (m, 1/l)

// ---------------------------------------------------------------------------
// helpers
// ---------------------------------------------------------------------------
__device__ __forceinline__ void mma16(float* c,
                                      unsigned a0, unsigned a1, unsigned a2, unsigned a3,
                                      unsigned b0, unsigned b1) {
    asm volatile(
        "mma.sync.aligned.m16n8k16.row.col.f32.f16.f16.f32 "
        "{%0,%1,%2,%3},{%4,%5,%6,%7},{%8,%9},{%0,%1,%2,%3};"
        : "+f"(c[0]), "+f"(c[1]), "+f"(c[2]), "+f"(c[3])
        : "r"(a0), "r"(a1), "r"(a2), "r"(a3), "r"(b0), "r"(b1));
}
__device__ __forceinline__ void ldsm4(unsigned& r0, unsigned& r1, unsigned& r2, unsigned& r3,
                                      const void* p) {
    unsigned a = (unsigned)__cvta_generic_to_shared(p);
    asm volatile("ldmatrix.sync.aligned.m8n8.x4.shared.b16 {%0,%1,%2,%3}, [%4];"
                 : "=r"(r0), "=r"(r1), "=r"(r2), "=r"(r3) : "r"(a));
}
__device__ __forceinline__ void cpa16(const void* smem_dst, const void* gsrc) {
    unsigned s = (unsigned)__cvta_generic_to_shared(smem_dst);
    asm volatile("cp.async.cg.shared.global [%0], [%1], 16;" :: "r"(s), "l"(gsrc));
}
__device__ __forceinline__ void cpa_commit() {
    asm volatile("cp.async.commit_group;");
}
__device__ __forceinline__ void cpa_wait0() {
    asm volatile("cp.async.wait_group 0;");
}

// ---------------------------------------------------------------------------
// Converters
// ---------------------------------------------------------------------------
__global__ __launch_bounds__(256) void cvt_x(const float* __restrict__ X)
{
    const int stride = gridDim.x * blockDim.x;
    for (int k = blockIdx.x * blockDim.x + threadIdx.x; k < MM * DD / 4; k += stride) {
        float4 v = ((const float4*)X)[k];
        ((__half2*)g_x)[k * 2    ] = __floats2half2_rn(v.x, v.y);
        ((__half2*)g_x)[k * 2 + 1] = __floats2half2_rn(v.z, v.w);
    }
}

__global__ __launch_bounds__(256) void transpose_wa(const float* __restrict__ W)
{
    __shared__ float ts[32][33];
    const int tx = threadIdx.x & 31, ty = threadIdx.x >> 5;
    const int nb = blockIdx.x * 32, kb = blockIdx.y * 32;
#pragma unroll
    for (int i = 0; i < 4; i++)
        ts[ty + i * 8][tx] = W[(size_t)(kb + ty + i * 8) * 3072 + nb + tx];
    __syncthreads();
#pragma unroll
    for (int i = 0; i < 4; i++)
        g_wa[(size_t)(nb + ty + i * 8) * 1024 + kb + tx] = __float2half_rn(ts[tx][ty + i * 8]);
}
__global__ __launch_bounds__(256) void transpose_wp(const float* __restrict__ W)
{
    __shared__ float ts[32][33];
    const int tx = threadIdx.x & 31, ty = threadIdx.x >> 5;
    const int nb = blockIdx.x * 32, kb = blockIdx.y * 32;
#pragma unroll
    for (int i = 0; i < 4; i++)
        ts[ty + i * 8][tx] = W[(size_t)(kb + ty + i * 8) * 1024 + nb + tx];
    __syncthreads();
#pragma unroll
    for (int i = 0; i < 4; i++)
        g_wp[(size_t)(nb + ty + i * 8) * 1024 + kb + tx] = __float2half_rn(ts[tx][ty + i * 8]);
}

// ---------------------------------------------------------------------------
// fp16 GEMM core: C[128x128] tile, K-tile 64, 2-stage cp.async, ldmatrix.x4
// ---------------------------------------------------------------------------
#define TH 72                 // halves per tile row
#define TH32 36
#define TSZ (128*TH)
#define GEMM_SMEM_BYTES (2 * 2 * TSZ * 2)

__device__ __forceinline__ void gemm128(const __half* __restrict__ Asrc, size_t a_stride,
                                        const __half* __restrict__ Bsrc, size_t b_stride,
                                        int bm, int bn, __half* sh, float acc[4][4][4])
{
    __half* Ah = sh;
    __half* Bh = sh + 2 * TSZ;

    const int tid  = threadIdx.x;
    const int NK = 16;

    auto stage = [&](int t) {
        const int k0 = t * 64;
        __half* An = Ah + (t & 1) * TSZ;
        __half* Bn = Bh + (t & 1) * TSZ;
#pragma unroll
        for (int i = 0; i < 4; i++) {
            int c = tid + i * 256;
            int row = c >> 3, cc = c & 7;
            cpa16(&An[row * TH + cc * 8], &Asrc[(size_t)(bm + row) * a_stride + k0 + cc * 8]);
            cpa16(&Bn[row * TH + cc * 8], &Bsrc[(size_t)(bn + row) * b_stride + k0 + cc * 8]);
        }
    };

    stage(0); cpa_commit();

    const int lane = tid & 31;
    const int wid  = tid >> 5;
    const int wm   = (wid >> 2) * 64;
    const int wn   = (wid & 3) * 32;
    const int q8   = lane >> 3;
    const int r8   = lane & 7;

    for (int kt = 0; kt < NK; kt++) {
        cpa_wait0();
        __syncthreads();
        if (kt + 1 < NK) {
            stage(kt + 1);
            cpa_commit();
        }

        const unsigned* A32 = (const unsigned*)(Ah + (kt & 1) * TSZ);
        const unsigned* B32 = (const unsigned*)(Bh + (kt & 1) * TSZ);
#pragma unroll
        for (int kc = 0; kc < 4; kc++) {
            const int kb = kc * 8;
            unsigned af[4][4], bf[4][2];
#pragma unroll
            for (int mi = 0; mi < 4; mi++) {
                const int row = wm + mi * 16 + (q8 & 1) * 8 + r8;
                const int col = kb + (q8 >> 1) * 4;
                ldsm4(af[mi][0], af[mi][1], af[mi][2], af[mi][3], A32 + row * TH32 + col);
            }
#pragma unroll
            for (int njp = 0; njp < 4; njp += 2) {
                const int row = wn + njp * 8 + (q8 >> 1) * 8 + r8;
                const int col = kb + (q8 & 1) * 4;
                ldsm4(bf[njp][0], bf[njp][1], bf[njp + 1][0], bf[njp + 1][1],
                      B32 + row * TH32 + col);
            }
#pragma unroll
            for (int mi = 0; mi < 4; mi++)
#pragma unroll
                for (int nj = 0; nj < 4; nj++)
                    mma16(acc[mi][nj], af[mi][0], af[mi][1], af[mi][2], af[mi][3],
                          bf[nj][0], bf[nj][1]);
        }
    }
}

// ---------------------------------------------------------------------------
// QKV GEMM
// ---------------------------------------------------------------------------
__global__ __launch_bounds__(256, 2) void qkv_gemm(const float* __restrict__ bias)
{
    extern __shared__ __half shq[];
    float acc[4][4][4];
#pragma unroll
    for (int mi = 0; mi < 4; mi++)
#pragma unroll
        for (int nj = 0; nj < 4; nj++)
#pragma unroll
            for (int t = 0; t < 4; t++) acc[mi][nj][t] = 0.f;

    const int bm = blockIdx.y * 128;
    const int bn = blockIdx.x * 128;
    gemm128(g_x, 1024, g_wa, 1024, bm, bn, shq, acc);

    const int lane = threadIdx.x & 31;
    const int wid  = threadIdx.x >> 5;
    const int g    = lane >> 2;
    const int tg   = lane & 3;
    const int wm   = (wid >> 2) * 64;
    const int wn   = (wid & 3) * 32;

#pragma unroll
    for (int mi = 0; mi < 4; mi++) {
#pragma unroll
        for (int nj = 0; nj < 4; nj++) {
#pragma unroll
            for (int t = 0; t < 4; t++) {
                const int m = bm + wm + mi * 16 + g + ((t >= 2) ? 8 : 0);
                const int n = bn + wn + nj * 8 + 2 * tg + (t & 1);
                const float v = acc[mi][nj][t] + bias[n];
                const int bidx = m >> 11;
                const int s = m & 2047;
                const int which = n >> 10;
                const int jj = n & 1023;
                const int h = jj >> 6;
                const int d = jj & 63;
                if (which == 0)
                    g_q[(size_t)((bidx * HH + h) * SS + s) * HD + d] = __float2half_rn(v);
                else if (which == 1)
                    g_k[(size_t)((bidx * HH + h) * SS + s) * HD + d] = __float2half_rn(v);
                else
                    g_v[(size_t)((bidx * HH + h) * HD + d) * SS + s] = __float2half_rn(v);
            }
        }
    }
}

// ---------------------------------------------------------------------------
// Flash attention pass 1 only: O, m, 1/l. LPT scheduling.
// ---------------------------------------------------------------------------
#define PS_H 136
#define PS_H32 68
#define PSSZ (128*PS_H)
#define KH 72
#define KH32 36
#define KSZH (128*KH)
#define VT_H 136
#define VT_H32 68
#define VTSZ (64*VT_H)
#define ATT_SMEM_BYTES ((PSSZ + 2*KSZH + 2*VTSZ) * 2)

__global__ __launch_bounds__(256, 2) void attn_kernel()
{
    extern __shared__ __half smh[];
    __half* Ps = smh;                     // [128][PS_H]
    __half* Kh = smh + PSSZ;              // [2][128][KH]
    __half* VT = Kh + 2 * KSZH;           // [2][64][VT_H]

    const int tid  = threadIdx.x;
    const int lane = tid & 31;
    const int wid  = tid >> 5;
    const int g    = lane >> 2;
    const int tg   = lane & 3;
    const int qw   = wid * 16;
    const int q8   = lane >> 3;
    const int r8   = lane & 7;

    const int b  = blockIdx.z;
    const int h  = blockIdx.y;
    const int qt = (gridDim.x - 1) - blockIdx.x;   // LPT
    const int q0 = qt * 128;

    const __half* Qbh = g_q + (size_t)((b * HH + h) * SS) * HD;
    const __half* Kbh = g_k + (size_t)((b * HH + h) * SS) * HD;
    const __half* Vbt = g_v + (size_t)((b * HH + h) * HD) * SS;

#pragma unroll
    for (int i = 0; i < 4; i++) {
        int c = tid + i * 256;
        int row = c >> 3, cc = c & 7;
        cpa16(&Kh[row * KH + cc * 8], &Kbh[(size_t)row * HD + cc * 8]);
    }
#pragma unroll
    for (int i = 0; i < 4; i++) {
        int c = tid + i * 256;
        int row = c >> 4, cc = c & 15;
        cpa16(&VT[row * VT_H + cc * 8], &Vbt[(size_t)row * SS + cc * 8]);
    }
    cpa_commit();

    unsigned qa[4][4];
    {
        const unsigned* q0p = (const unsigned*)(Qbh + (size_t)(q0 + qw + g) * HD);
        const unsigned* q1p = (const unsigned*)(Qbh + (size_t)(q0 + qw + g + 8) * HD);
#pragma unroll
        for (int kc = 0; kc < 4; kc++) {
            qa[kc][0] = q0p[kc * 8 + tg    ];
            qa[kc][1] = q1p[kc * 8 + tg    ];
            qa[kc][2] = q0p[kc * 8 + 4 + tg];
            qa[kc][3] = q1p[kc * 8 + 4 + tg];
        }
    }

    float m0 = -1e30f, m1 = -1e30f, l0 = 0.f, l1 = 0.f;
    float o[8][4];
#pragma unroll
    for (int nf = 0; nf < 8; nf++)
#pragma unroll
        for (int t = 0; t < 4; t++) o[nf][t] = 0.f;

    const int nkt  = qt + 1;
    const int row0 = q0 + qw + g;
    const int row1 = row0 + 8;

    for (int kt = 0; kt < nkt; kt++) {
        cpa_wait0();
        __syncthreads();

        if (kt + 1 < nkt) {
            const int nb = (kt + 1) * 128;
            __half* Kn = Kh + ((kt + 1) & 1) * KSZH;
            __half* Vn = VT + ((kt + 1) & 1) * VTSZ;
#pragma unroll
            for (int i = 0; i < 4; i++) {
                int c = tid + i * 256;
                int row = c >> 3, cc = c & 7;
                cpa16(&Kn[row * KH + cc * 8], &Kbh[(size_t)(nb + row) * HD + cc * 8]);
            }
#pragma unroll
            for (int i = 0; i < 4; i++) {
                int c = tid + i * 256;
                int row = c >> 4, cc = c & 15;
                cpa16(&Vn[row * VT_H + cc * 8], &Vbt[(size_t)row * SS + nb + cc * 8]);
            }
            cpa_commit();
        }

        const unsigned* K32 = (const unsigned*)(Kh + (kt & 1) * KSZH);
        const int kbase = kt * 128;

        float s[16][4];
#pragma unroll
        for (int nf = 0; nf < 16; nf++)
#pragma unroll
            for (int t = 0; t < 4; t++) s[nf][t] = 0.f;
#pragma unroll
        for (int kc = 0; kc < 4; kc++) {
#pragma unroll
            for (int nfp = 0; nfp < 16; nfp += 2) {
                unsigned b00, b01, b10, b11;
                const int row = nfp * 8 + (q8 >> 1) * 8 + r8;
                const int col = kc * 8 + (q8 & 1) * 4;
                ldsm4(b00, b01, b10, b11, K32 + row * KH32 + col);
                mma16(s[nfp    ], qa[kc][0], qa[kc][1], qa[kc][2], qa[kc][3], b00, b01);
                mma16(s[nfp + 1], qa[kc][0], qa[kc][1], qa[kc][2], qa[kc][3], b10, b11);
            }
        }

        const bool diag = (kt == qt);
        float mx0 = -1e30f, mx1 = -1e30f;
#pragma unroll
        for (int nf = 0; nf < 16; nf++) {
            const int col = kbase + nf * 8 + 2 * tg;
            float v0 = s[nf][0] * 0.125f;
            float v1 = s[nf][1] * 0.125f;
            float v2 = s[nf][2] * 0.125f;
            float v3 = s[nf][3] * 0.125f;
            if (diag) {
                if (col     > row0) v0 = -1e30f;
                if (col + 1 > row0) v1 = -1e30f;
                if (col     > row1) v2 = -1e30f;
                if (col + 1 > row1) v3 = -1e30f;
            }
            s[nf][0] = v0; s[nf][1] = v1; s[nf][2] = v2; s[nf][3] = v3;
            mx0 = fmaxf(mx0, fmaxf(v0, v1));
            mx1 = fmaxf(mx1, fmaxf(v2, v3));
        }
        mx0 = fmaxf(mx0, __shfl_xor_sync(0xffffffffu, mx0, 1));
        mx0 = fmaxf(mx0, __shfl_xor_sync(0xffffffffu, mx0, 2));
        mx1 = fmaxf(mx1, __shfl_xor_sync(0xffffffffu, mx1, 1));
        mx1 = fmaxf(mx1, __shfl_xor_sync(0xffffffffu, mx1, 2));

        const float mn0 = fmaxf(m0, mx0);
        const float mn1 = fmaxf(m1, mx1);
        const float al0 = __expf(m0 - mn0);
        const float al1 = __expf(m1 - mn1);

        float rs0 = 0.f, rs1 = 0.f;
        __half2* Pp = (__half2*)Ps;
#pragma unroll
        for (int nf = 0; nf < 16; nf++) {
            const float p0 = __expf(s[nf][0] - mn0);
            const float p1 = __expf(s[nf][1] - mn0);
            const float p2 = __expf(s[nf][2] - mn1);
            const float p3 = __expf(s[nf][3] - mn1);
            rs0 += p0 + p1;
            rs1 += p2 + p3;
            Pp[(qw + g    ) * (PS_H/2) + nf * 4 + tg] = __floats2half2_rn(p0, p1);
            Pp[(qw + g + 8) * (PS_H/2) + nf * 4 + tg] = __floats2half2_rn(p2, p3);
        }
        rs0 += __shfl_xor_sync(0xffffffffu, rs0, 1);
        rs0 += __shfl_xor_sync(0xffffffffu, rs0, 2);
        rs1 += __shfl_xor_sync(0xffffffffu, rs1, 1);
        rs1 += __shfl_xor_sync(0xffffffffu, rs1, 2);

        m0 = mn0; m1 = mn1;
        l0 = l0 * al0 + rs0;
        l1 = l1 * al1 + rs1;
#pragma unroll
        for (int nf = 0; nf < 8; nf++) {
            o[nf][0] *= al0; o[nf][1] *= al0;
            o[nf][2] *= al1; o[nf][3] *= al1;
        }

        const unsigned* P32  = (const unsigned*)Ps;
        const unsigned* VT32 = (const unsigned*)(VT + (kt & 1) * VTSZ);
#pragma unroll
        for (int kc = 0; kc < 8; kc++) {
            unsigned a0, a1, a2, a3;
            {
                const int row = qw + (q8 & 1) * 8 + r8;
                const int col = kc * 8 + (q8 >> 1) * 4;
                ldsm4(a0, a1, a2, a3, P32 + row * PS_H32 + col);
            }
#pragma unroll
            for (int nfp = 0; nfp < 8; nfp += 2) {
                unsigned b00, b01, b10, b11;
                const int row = nfp * 8 + (q8 >> 1) * 8 + r8;
                const int col = kc * 8 + (q8 & 1) * 4;
                ldsm4(b00, b01, b10, b11, VT32 + row * VT_H32 + col);
                mma16(o[nfp    ], a0, a1, a2, a3, b00, b01);
                mma16(o[nfp + 1], a0, a1, a2, a3, b10, b11);
            }
        }
    }

    // Write O (fp16) + (m, 1/l) per row
    const float il0 = 1.0f / l0;
    const float il1 = 1.0f / l1;
    {
        const int orow = b * SS + q0 + qw + g;
#pragma unroll
        for (int nf = 0; nf < 8; nf++) {
            const int col = h * HD + nf * 8 + 2 * tg;
            __half2* d0 = (__half2*)&g_ao[(size_t)orow * DD + col];
            __half2* d1 = (__half2*)&g_ao[(size_t)(orow + 8) * DD + col];
            *d0 = __floats2half2_rn(o[nf][0] * il0, o[nf][1] * il0);
            *d1 = __floats2half2_rn(o[nf][2] * il1, o[nf][3] * il1);
        }
        if (tg == 0) {
            const size_t mlbase = (size_t)(b * HH + h) * SS;
            g_ml[mlbase + q0 + qw + g    ] = make_float2(m0, il0);
            g_ml[mlbase + q0 + qw + g + 8] = make_float2(m1, il1);
        }
    }
}

// ---------------------------------------------------------------------------
// Epilogue: CTA 0..255 = proj tiles; 256..8447 = attn-weight tiles
// (lower/diag: recompute QK^T, exp, scale; upper: zero-fill)
// ---------------------------------------------------------------------------
__global__ __launch_bounds__(256, 2) void epilogue(const float* __restrict__ bias,
                                                   float* __restrict__ out)
{
    extern __shared__ __half shq[];
    const int tid  = threadIdx.x;
    const int lane = tid & 31;
    const int wid  = tid >> 5;
    const int g    = lane >> 2;
    const int tg   = lane & 3;
    const int idx  = blockIdx.x;

    if (idx < 256) {
        // ----- projection tile -----
        float acc[4][4][4];
#pragma unroll
        for (int mi = 0; mi < 4; mi++)
#pragma unroll
            for (int nj = 0; nj < 4; nj++)
#pragma unroll
                for (int t = 0; t < 4; t++) acc[mi][nj][t] = 0.f;

        const int bm = (idx >> 3) * 128;
        const int bn = (idx & 7) * 128;
        gemm128(g_ao, 1024, g_wp, 1024, bm, bn, shq, acc);

        const int wm = (wid >> 2) * 64;
        const int wn = (wid & 3) * 32;
#pragma unroll
        for (int mi = 0; mi < 4; mi++) {
#pragma unroll
            for (int nj = 0; nj < 4; nj++) {
#pragma unroll
                for (int t = 0; t < 4; t++) {
                    const int m = bm + wm + mi * 16 + g + ((t >= 2) ? 8 : 0);
                    const int n = bn + wn + nj * 8 + 2 * tg + (t & 1);
                    out[(size_t)m * DD + n] = acc[mi][nj][t] + bias[n];
                }
            }
        }
        return;
    }

    // ----- attention weight tile -----
    const int w  = idx - 256;
    const int bh = w >> 8;            // 0..31
    const int t8 = w & 255;
    const int qt = t8 >> 4;
    const int kt = t8 & 15;
    const int b  = bh >> 4;
    const int h  = bh & 15;
    const int q0 = qt * 128;
    const int kbase = kt * 128;

    float* attn = out + (size_t)MM * DD;
    float* dst = attn + ((size_t)((b * HH + h) * SS) + q0) * SS + kbase;

    if (kt > qt) {
        // zero tile: 128 rows x 32 float4
        const float4 z = make_float4(0.f, 0.f, 0.f, 0.f);
#pragma unroll
        for (int i = 0; i < 16; i++) {
            int c = tid + i * 256;
            int row = c >> 5, c4 = c & 31;
            *(float4*)&dst[(size_t)row * SS + c4 * 4] = z;
        }
        return;
    }

    // stage K tile (single stage)
    const __half* Kbh = g_k + (size_t)((b * HH + h) * SS) * HD;
    __half* Kh = shq;
#pragma unroll
    for (int i = 0; i < 4; i++) {
        int c = tid + i * 256;
        int row = c >> 3, cc = c & 7;
        cpa16(&Kh[row * KH + cc * 8], &Kbh[(size_t)(kbase + row) * HD + cc * 8]);
    }
    cpa_commit();

    // Q fragments
    const __half* Qbh = g_q + (size_t)((b * HH + h) * SS) * HD;
    const int qw = wid * 16;
    unsigned qa[4][4];
    {
        const unsigned* q0p = (const unsigned*)(Qbh + (size_t)(q0 + qw + g) * HD);
        const unsigned* q1p = (const unsigned*)(Qbh + (size_t)(q0 + qw + g + 8) * HD);
#pragma unroll
        for (int kc = 0; kc < 4; kc++) {
            qa[kc][0] = q0p[kc * 8 + tg    ];
            qa[kc][1] = q1p[kc * 8 + tg    ];
            qa[kc][2] = q0p[kc * 8 + 4 + tg];
            qa[kc][3] = q1p[kc * 8 + 4 + tg];
        }
    }

    // per-row (m, 1/l)
    const size_t mlbase = (size_t)(b * HH + h) * SS;
    const float2 ml0 = g_ml[mlbase + q0 + qw + g    ];
    const float2 ml1 = g_ml[mlbase + q0 + qw + g + 8];

    cpa_wait0();
    __syncthreads();

    const int q8 = lane >> 3;
    const int r8 = lane & 7;
    const unsigned* K32 = (const unsigned*)Kh;

    float s[16][4];
#pragma unroll
    for (int nf = 0; nf < 16; nf++)
#pragma unroll
        for (int t = 0; t < 4; t++) s[nf][t] = 0.f;
#pragma unroll
    for (int kc = 0; kc < 4; kc++) {
#pragma unroll
        for (int nfp = 0; nfp < 16; nfp += 2) {
            unsigned b00, b01, b10, b11;
            const int row = nfp * 8 + (q8 >> 1) * 8 + r8;
            const int col = kc * 8 + (q8 & 1) * 4;
            ldsm4(b00, b01, b10, b11, K32 + row * KH32 + col);
            mma16(s[nfp    ], qa[kc][0], qa[kc][1], qa[kc][2], qa[kc][3], b00, b01);
            mma16(s[nfp + 1], qa[kc][0], qa[kc][1], qa[kc][2], qa[kc][3], b10, b11);
        }
    }

    const bool diag = (kt == qt);
    const int row0 = q0 + qw + g;
    const int row1 = row0 + 8;
    float* w0p = dst + (size_t)(qw + g) * SS;
    float* w1p = dst + (size_t)(qw + g + 8) * SS;
#pragma unroll
    for (int nf = 0; nf < 16; nf++) {
        const int coll = nf * 8 + 2 * tg;          // col within tile
        const int col  = kbase + coll;             // global col
        float w0 = __expf(s[nf][0] * 0.125f - ml0.x) * ml0.y;
        float w1 = __expf(s[nf][1] * 0.125f - ml0.x) * ml0.y;
        float w2 = __expf(s[nf][2] * 0.125f - ml1.x) * ml1.y;
        float w3 = __expf(s[nf][3] * 0.125f - ml1.x) * ml1.y;
        if (diag) {
            if (col     > row0) w0 = 0.f;
            if (col + 1 > row0) w1 = 0.f;
            if (col     > row1) w2 = 0.f;
            if (col + 1 > row1) w3 = 0.f;
        }
        float2 t0, t1;
        t0.x = w0; t0.y = w1;
        t1.x = w2; t1.y = w3;
        *(float2*)&w0p[coll] = t0;
        *(float2*)&w1p[coll] = t1;
    }
}

// ---------------------------------------------------------------------------
extern "C" void kernel_launch(void* const* d_in, const int* in_sizes, int n_in,
                              void* d_out, int out_size)
{
    const float* x      = (const float*)d_in[0];
    const float* W_attn = (const float*)d_in[1];
    const float* b_attn = (const float*)d_in[2];
    const float* W_proj = (const float*)d_in[3];
    const float* b_proj = (const float*)d_in[4];
    float* out = (float*)d_out;

    cudaFuncSetAttribute(qkv_gemm,
                         cudaFuncAttributeMaxDynamicSharedMemorySize, GEMM_SMEM_BYTES);
    cudaFuncSetAttribute(epilogue,
                         cudaFuncAttributeMaxDynamicSharedMemorySize, GEMM_SMEM_BYTES);
    cudaFuncSetAttribute(attn_kernel,
                         cudaFuncAttributeMaxDynamicSharedMemorySize, ATT_SMEM_BYTES);

    cvt_x<<<1024, 256>>>(x);
    transpose_wa<<<dim3(96, 32), 256>>>(W_attn);
    transpose_wp<<<dim3(32, 32), 256>>>(W_proj);
    qkv_gemm<<<dim3(24, 32), 256, GEMM_SMEM_BYTES>>>(b_attn);
    attn_kernel<<<dim3(SS / 128, HH, BB), 256, ATT_SMEM_BYTES>>>();
    epilogue<<<8448, 256, GEMM_SMEM_BYTES>>>(b_proj, out);
}